// round 1
// baseline (speedup 1.0000x reference)
#include <cuda_runtime.h>

#define BATCH 4
#define S_LEN 2048
#define NH    16
#define DK    64
#define DM    1024

// Scratch (no allocations allowed): Q/K/V in head-major [B,H,S,Dk], ctx in [B,S,H*Dk]
__device__ float g_q[BATCH * NH * S_LEN * DK];
__device__ float g_k[BATCH * NH * S_LEN * DK];
__device__ float g_v[BATCH * NH * S_LEN * DK];
__device__ float g_ctx[BATCH * S_LEN * DM];

// ---------------------------------------------------------------------------
// SGEMM: C[M,N] = A[M,K] * W[K,N], M=8192, N=1024, K=1024. fp32.
// 128x128 block tile, BK=8, 256 threads, 8x8 per-thread register tile.
// headMajor=1: write to [B,H,S,Dk] layout (for Q/K/V). 0: plain row-major.
// ---------------------------------------------------------------------------
__global__ __launch_bounds__(256) void sgemm_kernel(
    const float* __restrict__ A, const float* __restrict__ W,
    float* __restrict__ out, int headMajor)
{
    __shared__ float As[8][132];   // transposed A tile: As[k][m], padded
    __shared__ float Bs[8][128];   // Bs[k][n]

    const int m0  = blockIdx.y * 128;
    const int n0  = blockIdx.x * 128;
    const int tid = threadIdx.x;
    const int tx  = tid & 15;      // col group 0..15
    const int ty  = tid >> 4;      // row group 0..15

    const int arow = tid >> 1;         // 0..127
    const int akg  = (tid & 1) * 4;    // 0 or 4
    const int bk   = tid >> 5;         // 0..7
    const int bn   = (tid & 31) * 4;   // 0..124

    float acc[8][8];
#pragma unroll
    for (int i = 0; i < 8; ++i)
#pragma unroll
        for (int j = 0; j < 8; ++j) acc[i][j] = 0.f;

    const float* Aptr = A + (size_t)(m0 + arow) * DM + akg;
    const float* Wptr = W + (size_t)bk * DM + n0 + bn;

    for (int k0 = 0; k0 < DM; k0 += 8) {
        float4 a = *(const float4*)(Aptr + k0);
        float4 b = *(const float4*)(Wptr + (size_t)k0 * DM);
        As[akg + 0][arow] = a.x;
        As[akg + 1][arow] = a.y;
        As[akg + 2][arow] = a.z;
        As[akg + 3][arow] = a.w;
        *(float4*)(&Bs[bk][bn]) = b;
        __syncthreads();

#pragma unroll
        for (int kk = 0; kk < 8; ++kk) {
            float4 a0 = *(const float4*)(&As[kk][ty * 8]);
            float4 a1 = *(const float4*)(&As[kk][ty * 8 + 4]);
            float4 b0 = *(const float4*)(&Bs[kk][tx * 8]);
            float4 b1 = *(const float4*)(&Bs[kk][tx * 8 + 4]);
            float av[8] = {a0.x, a0.y, a0.z, a0.w, a1.x, a1.y, a1.z, a1.w};
            float bv[8] = {b0.x, b0.y, b0.z, b0.w, b1.x, b1.y, b1.z, b1.w};
#pragma unroll
            for (int i = 0; i < 8; ++i)
#pragma unroll
                for (int j = 0; j < 8; ++j)
                    acc[i][j] = fmaf(av[i], bv[j], acc[i][j]);
        }
        __syncthreads();
    }

    if (headMajor) {
        // out[(b*NH + h)*S + s][d] where m = b*S+s, n = h*64+d
#pragma unroll
        for (int i = 0; i < 8; ++i) {
            int m = m0 + ty * 8 + i;
            int bb = m >> 11;          // /2048
            int ss = m & (S_LEN - 1);
#pragma unroll
            for (int j = 0; j < 8; j += 4) {
                int n  = n0 + tx * 8 + j;
                int hh = n >> 6;
                int dd = n & 63;
                float4 v = make_float4(acc[i][j], acc[i][j + 1], acc[i][j + 2], acc[i][j + 3]);
                *(float4*)(out + ((size_t)((bb * NH + hh) * S_LEN + ss)) * DK + dd) = v;
            }
        }
    } else {
#pragma unroll
        for (int i = 0; i < 8; ++i) {
            int m = m0 + ty * 8 + i;
#pragma unroll
            for (int j = 0; j < 8; j += 4) {
                float4 v = make_float4(acc[i][j], acc[i][j + 1], acc[i][j + 2], acc[i][j + 3]);
                *(float4*)(out + (size_t)m * DM + n0 + tx * 8 + j) = v;
            }
        }
    }
}

// ---------------------------------------------------------------------------
// Flash attention (fp32): one block per (b,h, 128 q-rows). Bc = 64 k-cols.
// Exact integer reconstruction of the T5 relative-position bucket.
// ---------------------------------------------------------------------------
__device__ __forceinline__ int t5_bucket(int delta)
{
    int base = (delta > 0) ? 16 : 0;
    int a = delta < 0 ? -delta : delta;
    int bucket;
    if (a < 8) {
        bucket = a;
    } else if (a >= 128) {
        bucket = 15;
    } else {
        // bucket = 8 + floor( 2*log2(a/8) ) = 2 + 2*floor(log2 a) + frac bit
        int t = 31 - __clz(a);
        int f = (a * a >= (1 << (2 * t + 1))) ? 1 : 0;
        bucket = 2 + 2 * t + f;
        if (bucket > 15) bucket = 15;
    }
    return base + bucket;
}

#define ATTN_SMEM_FLOATS (64*132 + 64*68 + 64*68 + 64*132 + 32)
#define ATTN_SMEM_BYTES  (ATTN_SMEM_FLOATS * 4)

__global__ __launch_bounds__(256, 1) void attn_kernel(
    const float* __restrict__ Q, const float* __restrict__ K,
    const float* __restrict__ V, const float* __restrict__ rel_bias,
    float* __restrict__ ctx)
{
    extern __shared__ float sm[];
    float* Qs    = sm;                    // [64][132]  d-major: Qs[d][q]
    float* Ks    = Qs + 64 * 132;         // [64][68]   d-major: Ks[d][k]
    float* Vs    = Ks + 64 * 68;          // [64][68]   k-major: Vs[k][d]
    float* Ps    = Vs + 64 * 68;          // [64][132]  k-major: Ps[k][q]
    float* sbias = Ps + 64 * 132;         // [32]

    const int bh = blockIdx.y;            // b*NH + h
    const int h  = bh & (NH - 1);
    const int b  = bh >> 4;
    const int q0 = blockIdx.x * 128;
    const int tid = threadIdx.x;
    const int tx  = tid & 15;             // k/d col group
    const int ty  = tid >> 4;             // q row group

    const float* Qbase = Q + (size_t)bh * S_LEN * DK;
    const float* Kbase = K + (size_t)bh * S_LEN * DK;
    const float* Vbase = V + (size_t)bh * S_LEN * DK;

    if (tid < 32) sbias[tid] = rel_bias[tid * NH + h];

    // Load Q tile transposed: 128 rows x 64 d
#pragma unroll
    for (int it = 0; it < 8; ++it) {
        int i  = tid + it * 256;          // 0..2047 (float4 units)
        int qr = i >> 4;
        int dg = (i & 15) * 4;
        float4 t = *(const float4*)(Qbase + (size_t)(q0 + qr) * DK + dg);
        Qs[(dg + 0) * 132 + qr] = t.x;
        Qs[(dg + 1) * 132 + qr] = t.y;
        Qs[(dg + 2) * 132 + qr] = t.z;
        Qs[(dg + 3) * 132 + qr] = t.w;
    }

    float acc[8][4];
    float mrow[8], lrow[8];
#pragma unroll
    for (int r = 0; r < 8; ++r) {
        mrow[r] = -1e30f;
        lrow[r] = 0.f;
#pragma unroll
        for (int c = 0; c < 4; ++c) acc[r][c] = 0.f;
    }
    __syncthreads();

    for (int k0 = 0; k0 < S_LEN; k0 += 64) {
        // Load K (transposed) and V (natural) tiles: 64 x 64 each
#pragma unroll
        for (int it = 0; it < 4; ++it) {
            int i  = tid + it * 256;      // 0..1023
            int kr = i >> 4;
            int dg = (i & 15) * 4;
            float4 t = *(const float4*)(Kbase + (size_t)(k0 + kr) * DK + dg);
            Ks[(dg + 0) * 68 + kr] = t.x;
            Ks[(dg + 1) * 68 + kr] = t.y;
            Ks[(dg + 2) * 68 + kr] = t.z;
            Ks[(dg + 3) * 68 + kr] = t.w;
            float4 u = *(const float4*)(Vbase + (size_t)(k0 + kr) * DK + dg);
            *(float4*)(Vs + kr * 68 + dg) = u;
        }
        __syncthreads();

        // S = Q * K^T  (8 q-rows x 4 k-cols per thread)
        float sf[8][4];
#pragma unroll
        for (int r = 0; r < 8; ++r)
#pragma unroll
            for (int c = 0; c < 4; ++c) sf[r][c] = 0.f;

#pragma unroll 4
        for (int d = 0; d < 64; ++d) {
            float4 a0 = *(const float4*)(Qs + d * 132 + ty * 8);
            float4 a1 = *(const float4*)(Qs + d * 132 + ty * 8 + 4);
            float4 bb = *(const float4*)(Ks + d * 68 + tx * 4);
            float av[8] = {a0.x, a0.y, a0.z, a0.w, a1.x, a1.y, a1.z, a1.w};
            float bv[4] = {bb.x, bb.y, bb.z, bb.w};
#pragma unroll
            for (int r = 0; r < 8; ++r)
#pragma unroll
                for (int c = 0; c < 4; ++c)
                    sf[r][c] = fmaf(av[r], bv[c], sf[r][c]);
        }

        // Bias + online softmax (row reductions across the 16 tx lanes = half warp)
#pragma unroll
        for (int r = 0; r < 8; ++r) {
            int qg = q0 + ty * 8 + r;
            float rmax = -1e30f;
#pragma unroll
            for (int c = 0; c < 4; ++c) {
                int kg = k0 + tx * 4 + c;
                float v = sf[r][c] + sbias[t5_bucket(kg - qg)];
                sf[r][c] = v;
                rmax = fmaxf(rmax, v);
            }
            rmax = fmaxf(rmax, __shfl_xor_sync(0xffffffffu, rmax, 1));
            rmax = fmaxf(rmax, __shfl_xor_sync(0xffffffffu, rmax, 2));
            rmax = fmaxf(rmax, __shfl_xor_sync(0xffffffffu, rmax, 4));
            rmax = fmaxf(rmax, __shfl_xor_sync(0xffffffffu, rmax, 8));

            float mnew = fmaxf(mrow[r], rmax);
            float corr = __expf(mrow[r] - mnew);
            mrow[r] = mnew;

            float psum = 0.f;
#pragma unroll
            for (int c = 0; c < 4; ++c) {
                float p = __expf(sf[r][c] - mnew);
                sf[r][c] = p;
                psum += p;
            }
            psum += __shfl_xor_sync(0xffffffffu, psum, 1);
            psum += __shfl_xor_sync(0xffffffffu, psum, 2);
            psum += __shfl_xor_sync(0xffffffffu, psum, 4);
            psum += __shfl_xor_sync(0xffffffffu, psum, 8);

            lrow[r] = lrow[r] * corr + psum;
#pragma unroll
            for (int c = 0; c < 4; ++c) acc[r][c] *= corr;
            // Store P transposed: Ps[k][q]
#pragma unroll
            for (int c = 0; c < 4; ++c)
                Ps[(tx * 4 + c) * 132 + ty * 8 + r] = sf[r][c];
        }
        __syncthreads();

        // O += P * V  (8 q-rows x 4 d-cols per thread)
#pragma unroll 4
        for (int kk = 0; kk < 64; ++kk) {
            float4 a0 = *(const float4*)(Ps + kk * 132 + ty * 8);
            float4 a1 = *(const float4*)(Ps + kk * 132 + ty * 8 + 4);
            float4 bb = *(const float4*)(Vs + kk * 68 + tx * 4);
            float av[8] = {a0.x, a0.y, a0.z, a0.w, a1.x, a1.y, a1.z, a1.w};
            float bv[4] = {bb.x, bb.y, bb.z, bb.w};
#pragma unroll
            for (int r = 0; r < 8; ++r)
#pragma unroll
                for (int c = 0; c < 4; ++c)
                    acc[r][c] = fmaf(av[r], bv[c], acc[r][c]);
        }
        __syncthreads();
    }

    // Epilogue: normalize and write ctx in [B,S,H*Dk] layout
#pragma unroll
    for (int r = 0; r < 8; ++r) {
        float inv = 1.f / lrow[r];
        int qg = q0 + ty * 8 + r;
        float4 o = make_float4(acc[r][0] * inv, acc[r][1] * inv,
                               acc[r][2] * inv, acc[r][3] * inv);
        *(float4*)(ctx + ((size_t)b * S_LEN + qg) * DM + h * DK + tx * 4) = o;
    }
}

// ---------------------------------------------------------------------------
extern "C" void kernel_launch(void* const* d_in, const int* in_sizes, int n_in,
                              void* d_out, int out_size)
{
    const float* hidden  = (const float*)d_in[0];
    const float* wq      = (const float*)d_in[1];
    const float* wk      = (const float*)d_in[2];
    const float* wv      = (const float*)d_in[3];
    const float* wo      = (const float*)d_in[4];
    const float* relbias = (const float*)d_in[5];
    float* out = (float*)d_out;

    float *q, *k, *v, *ctx;
    cudaGetSymbolAddress((void**)&q,   g_q);
    cudaGetSymbolAddress((void**)&k,   g_k);
    cudaGetSymbolAddress((void**)&v,   g_v);
    cudaGetSymbolAddress((void**)&ctx, g_ctx);

    cudaFuncSetAttribute(attn_kernel,
                         cudaFuncAttributeMaxDynamicSharedMemorySize,
                         ATTN_SMEM_BYTES);

    dim3 gGemm(DM / 128, (BATCH * S_LEN) / 128);   // (8, 64)
    dim3 blk(256);

    sgemm_kernel<<<gGemm, blk>>>(hidden, wq, q, 1);
    sgemm_kernel<<<gGemm, blk>>>(hidden, wk, k, 1);
    sgemm_kernel<<<gGemm, blk>>>(hidden, wv, v, 1);

    dim3 gAttn(S_LEN / 128, BATCH * NH);           // (16, 64)
    attn_kernel<<<gAttn, blk, ATTN_SMEM_BYTES>>>(q, k, v, relbias, ctx);

    sgemm_kernel<<<gGemm, blk>>>(ctx, wo, out, 0);
}

// round 2
// speedup vs baseline: 1.0005x; 1.0005x over previous
#include <cuda_runtime.h>

#define BATCH 4
#define S_LEN 2048
#define NH    16
#define DK    64
#define DM    1024

// Scratch (no allocations allowed): Q/K/V in head-major [B,H,S,Dk], ctx in [B,S,H*Dk]
__device__ float g_q[BATCH * NH * S_LEN * DK];
__device__ float g_k[BATCH * NH * S_LEN * DK];
__device__ float g_v[BATCH * NH * S_LEN * DK];
__device__ float g_ctx[BATCH * S_LEN * DM];

// ---------------------------------------------------------------------------
// SGEMM: C[M,N] = A[M,K] * W[K,N], M=8192, N=1024, K=1024. fp32.
// 128x128 block tile, BK=8, 256 threads, 8x8 per-thread register tile.
// headMajor=1: write to [B,H,S,Dk] layout (for Q/K/V). 0: plain row-major.
// ---------------------------------------------------------------------------
__global__ __launch_bounds__(256) void sgemm_kernel(
    const float* __restrict__ A, const float* __restrict__ W,
    float* __restrict__ out, int headMajor)
{
    __shared__ float As[8][132];   // transposed A tile: As[k][m], padded
    __shared__ float Bs[8][128];   // Bs[k][n]

    const int m0  = blockIdx.y * 128;
    const int n0  = blockIdx.x * 128;
    const int tid = threadIdx.x;
    const int tx  = tid & 15;      // col group 0..15
    const int ty  = tid >> 4;      // row group 0..15

    const int arow = tid >> 1;         // 0..127
    const int akg  = (tid & 1) * 4;    // 0 or 4
    const int bk   = tid >> 5;         // 0..7
    const int bn   = (tid & 31) * 4;   // 0..124

    float acc[8][8];
#pragma unroll
    for (int i = 0; i < 8; ++i)
#pragma unroll
        for (int j = 0; j < 8; ++j) acc[i][j] = 0.f;

    const float* Aptr = A + (size_t)(m0 + arow) * DM + akg;
    const float* Wptr = W + (size_t)bk * DM + n0 + bn;

    for (int k0 = 0; k0 < DM; k0 += 8) {
        float4 a = *(const float4*)(Aptr + k0);
        float4 b = *(const float4*)(Wptr + (size_t)k0 * DM);
        As[akg + 0][arow] = a.x;
        As[akg + 1][arow] = a.y;
        As[akg + 2][arow] = a.z;
        As[akg + 3][arow] = a.w;
        *(float4*)(&Bs[bk][bn]) = b;
        __syncthreads();

#pragma unroll
        for (int kk = 0; kk < 8; ++kk) {
            float4 a0 = *(const float4*)(&As[kk][ty * 8]);
            float4 a1 = *(const float4*)(&As[kk][ty * 8 + 4]);
            float4 b0 = *(const float4*)(&Bs[kk][tx * 8]);
            float4 b1 = *(const float4*)(&Bs[kk][tx * 8 + 4]);
            float av[8] = {a0.x, a0.y, a0.z, a0.w, a1.x, a1.y, a1.z, a1.w};
            float bv[8] = {b0.x, b0.y, b0.z, b0.w, b1.x, b1.y, b1.z, b1.w};
#pragma unroll
            for (int i = 0; i < 8; ++i)
#pragma unroll
                for (int j = 0; j < 8; ++j)
                    acc[i][j] = fmaf(av[i], bv[j], acc[i][j]);
        }
        __syncthreads();
    }

    if (headMajor) {
        // out[(b*NH + h)*S + s][d] where m = b*S+s, n = h*64+d
#pragma unroll
        for (int i = 0; i < 8; ++i) {
            int m = m0 + ty * 8 + i;
            int bb = m >> 11;          // /2048
            int ss = m & (S_LEN - 1);
#pragma unroll
            for (int j = 0; j < 8; j += 4) {
                int n  = n0 + tx * 8 + j;
                int hh = n >> 6;
                int dd = n & 63;
                float4 v = make_float4(acc[i][j], acc[i][j + 1], acc[i][j + 2], acc[i][j + 3]);
                *(float4*)(out + ((size_t)((bb * NH + hh) * S_LEN + ss)) * DK + dd) = v;
            }
        }
    } else {
#pragma unroll
        for (int i = 0; i < 8; ++i) {
            int m = m0 + ty * 8 + i;
#pragma unroll
            for (int j = 0; j < 8; j += 4) {
                float4 v = make_float4(acc[i][j], acc[i][j + 1], acc[i][j + 2], acc[i][j + 3]);
                *(float4*)(out + (size_t)m * DM + n0 + tx * 8 + j) = v;
            }
        }
    }
}

// ---------------------------------------------------------------------------
// Flash attention (fp32): one block per (b,h, 128 q-rows). Bc = 64 k-cols.
// Exact integer reconstruction of the T5 relative-position bucket.
// ---------------------------------------------------------------------------
__device__ __forceinline__ int t5_bucket(int delta)
{
    int base = (delta > 0) ? 16 : 0;
    int a = delta < 0 ? -delta : delta;
    int bucket;
    if (a < 8) {
        bucket = a;
    } else if (a >= 128) {
        bucket = 15;
    } else {
        // bucket = 8 + floor( 2*log2(a/8) ) = 2 + 2*floor(log2 a) + frac bit
        int t = 31 - __clz(a);
        int f = (a * a >= (1 << (2 * t + 1))) ? 1 : 0;
        bucket = 2 + 2 * t + f;
        if (bucket > 15) bucket = 15;
    }
    return base + bucket;
}

#define ATTN_SMEM_FLOATS (64*132 + 64*68 + 64*68 + 64*132 + 32)
#define ATTN_SMEM_BYTES  (ATTN_SMEM_FLOATS * 4)

__global__ __launch_bounds__(256, 1) void attn_kernel(
    const float* __restrict__ Q, const float* __restrict__ K,
    const float* __restrict__ V, const float* __restrict__ rel_bias,
    float* __restrict__ ctx)
{
    extern __shared__ float sm[];
    float* Qs    = sm;                    // [64][132]  d-major: Qs[d][q]
    float* Ks    = Qs + 64 * 132;         // [64][68]   d-major: Ks[d][k]
    float* Vs    = Ks + 64 * 68;          // [64][68]   k-major: Vs[k][d]
    float* Ps    = Vs + 64 * 68;          // [64][132]  k-major: Ps[k][q]
    float* sbias = Ps + 64 * 132;         // [32]

    const int bh = blockIdx.y;            // b*NH + h
    const int h  = bh & (NH - 1);
    const int b  = bh >> 4;
    const int q0 = blockIdx.x * 128;
    const int tid = threadIdx.x;
    const int tx  = tid & 15;             // k/d col group
    const int ty  = tid >> 4;             // q row group

    const float* Qbase = Q + (size_t)bh * S_LEN * DK;
    const float* Kbase = K + (size_t)bh * S_LEN * DK;
    const float* Vbase = V + (size_t)bh * S_LEN * DK;

    if (tid < 32) sbias[tid] = rel_bias[tid * NH + h];

    // Load Q tile transposed: 128 rows x 64 d
#pragma unroll
    for (int it = 0; it < 8; ++it) {
        int i  = tid + it * 256;          // 0..2047 (float4 units)
        int qr = i >> 4;
        int dg = (i & 15) * 4;
        float4 t = *(const float4*)(Qbase + (size_t)(q0 + qr) * DK + dg);
        Qs[(dg + 0) * 132 + qr] = t.x;
        Qs[(dg + 1) * 132 + qr] = t.y;
        Qs[(dg + 2) * 132 + qr] = t.z;
        Qs[(dg + 3) * 132 + qr] = t.w;
    }

    float acc[8][4];
    float mrow[8], lrow[8];
#pragma unroll
    for (int r = 0; r < 8; ++r) {
        mrow[r] = -1e30f;
        lrow[r] = 0.f;
#pragma unroll
        for (int c = 0; c < 4; ++c) acc[r][c] = 0.f;
    }
    __syncthreads();

    for (int k0 = 0; k0 < S_LEN; k0 += 64) {
        // Load K (transposed) and V (natural) tiles: 64 x 64 each
#pragma unroll
        for (int it = 0; it < 4; ++it) {
            int i  = tid + it * 256;      // 0..1023
            int kr = i >> 4;
            int dg = (i & 15) * 4;
            float4 t = *(const float4*)(Kbase + (size_t)(k0 + kr) * DK + dg);
            Ks[(dg + 0) * 68 + kr] = t.x;
            Ks[(dg + 1) * 68 + kr] = t.y;
            Ks[(dg + 2) * 68 + kr] = t.z;
            Ks[(dg + 3) * 68 + kr] = t.w;
            float4 u = *(const float4*)(Vbase + (size_t)(k0 + kr) * DK + dg);
            *(float4*)(Vs + kr * 68 + dg) = u;
        }
        __syncthreads();

        // S = Q * K^T  (8 q-rows x 4 k-cols per thread)
        float sf[8][4];
#pragma unroll
        for (int r = 0; r < 8; ++r)
#pragma unroll
            for (int c = 0; c < 4; ++c) sf[r][c] = 0.f;

#pragma unroll 4
        for (int d = 0; d < 64; ++d) {
            float4 a0 = *(const float4*)(Qs + d * 132 + ty * 8);
            float4 a1 = *(const float4*)(Qs + d * 132 + ty * 8 + 4);
            float4 bb = *(const float4*)(Ks + d * 68 + tx * 4);
            float av[8] = {a0.x, a0.y, a0.z, a0.w, a1.x, a1.y, a1.z, a1.w};
            float bv[4] = {bb.x, bb.y, bb.z, bb.w};
#pragma unroll
            for (int r = 0; r < 8; ++r)
#pragma unroll
                for (int c = 0; c < 4; ++c)
                    sf[r][c] = fmaf(av[r], bv[c], sf[r][c]);
        }

        // Bias + online softmax (row reductions across the 16 tx lanes = half warp)
#pragma unroll
        for (int r = 0; r < 8; ++r) {
            int qg = q0 + ty * 8 + r;
            float rmax = -1e30f;
#pragma unroll
            for (int c = 0; c < 4; ++c) {
                int kg = k0 + tx * 4 + c;
                float v = sf[r][c] + sbias[t5_bucket(kg - qg)];
                sf[r][c] = v;
                rmax = fmaxf(rmax, v);
            }
            rmax = fmaxf(rmax, __shfl_xor_sync(0xffffffffu, rmax, 1));
            rmax = fmaxf(rmax, __shfl_xor_sync(0xffffffffu, rmax, 2));
            rmax = fmaxf(rmax, __shfl_xor_sync(0xffffffffu, rmax, 4));
            rmax = fmaxf(rmax, __shfl_xor_sync(0xffffffffu, rmax, 8));

            float mnew = fmaxf(mrow[r], rmax);
            float corr = __expf(mrow[r] - mnew);
            mrow[r] = mnew;

            float psum = 0.f;
#pragma unroll
            for (int c = 0; c < 4; ++c) {
                float p = __expf(sf[r][c] - mnew);
                sf[r][c] = p;
                psum += p;
            }
            psum += __shfl_xor_sync(0xffffffffu, psum, 1);
            psum += __shfl_xor_sync(0xffffffffu, psum, 2);
            psum += __shfl_xor_sync(0xffffffffu, psum, 4);
            psum += __shfl_xor_sync(0xffffffffu, psum, 8);

            lrow[r] = lrow[r] * corr + psum;
#pragma unroll
            for (int c = 0; c < 4; ++c) acc[r][c] *= corr;
            // Store P transposed: Ps[k][q]
#pragma unroll
            for (int c = 0; c < 4; ++c)
                Ps[(tx * 4 + c) * 132 + ty * 8 + r] = sf[r][c];
        }
        __syncthreads();

        // O += P * V  (8 q-rows x 4 d-cols per thread)
#pragma unroll 4
        for (int kk = 0; kk < 64; ++kk) {
            float4 a0 = *(const float4*)(Ps + kk * 132 + ty * 8);
            float4 a1 = *(const float4*)(Ps + kk * 132 + ty * 8 + 4);
            float4 bb = *(const float4*)(Vs + kk * 68 + tx * 4);
            float av[8] = {a0.x, a0.y, a0.z, a0.w, a1.x, a1.y, a1.z, a1.w};
            float bv[4] = {bb.x, bb.y, bb.z, bb.w};
#pragma unroll
            for (int r = 0; r < 8; ++r)
#pragma unroll
                for (int c = 0; c < 4; ++c)
                    acc[r][c] = fmaf(av[r], bv[c], acc[r][c]);
        }
        __syncthreads();
    }

    // Epilogue: normalize and write ctx in [B,S,H*Dk] layout
#pragma unroll
    for (int r = 0; r < 8; ++r) {
        float inv = 1.f / lrow[r];
        int qg = q0 + ty * 8 + r;
        float4 o = make_float4(acc[r][0] * inv, acc[r][1] * inv,
                               acc[r][2] * inv, acc[r][3] * inv);
        *(float4*)(ctx + ((size_t)b * S_LEN + qg) * DM + h * DK + tx * 4) = o;
    }
}

// ---------------------------------------------------------------------------
extern "C" void kernel_launch(void* const* d_in, const int* in_sizes, int n_in,
                              void* d_out, int out_size)
{
    const float* hidden  = (const float*)d_in[0];
    const float* wq      = (const float*)d_in[1];
    const float* wk      = (const float*)d_in[2];
    const float* wv      = (const float*)d_in[3];
    const float* wo      = (const float*)d_in[4];
    const float* relbias = (const float*)d_in[5];
    float* out = (float*)d_out;

    float *q, *k, *v, *ctx;
    cudaGetSymbolAddress((void**)&q,   g_q);
    cudaGetSymbolAddress((void**)&k,   g_k);
    cudaGetSymbolAddress((void**)&v,   g_v);
    cudaGetSymbolAddress((void**)&ctx, g_ctx);

    cudaFuncSetAttribute(attn_kernel,
                         cudaFuncAttributeMaxDynamicSharedMemorySize,
                         ATTN_SMEM_BYTES);

    dim3 gGemm(DM / 128, (BATCH * S_LEN) / 128);   // (8, 64)
    dim3 blk(256);

    sgemm_kernel<<<gGemm, blk>>>(hidden, wq, q, 1);
    sgemm_kernel<<<gGemm, blk>>>(hidden, wk, k, 1);
    sgemm_kernel<<<gGemm, blk>>>(hidden, wv, v, 1);

    dim3 gAttn(S_LEN / 128, BATCH * NH);           // (16, 64)
    attn_kernel<<<gAttn, blk, ATTN_SMEM_BYTES>>>(q, k, v, relbias, ctx);

    sgemm_kernel<<<gGemm, blk>>>(ctx, wo, out, 0);
}

// round 4
// speedup vs baseline: 1.4862x; 1.4854x over previous
#include <cuda_runtime.h>
#include <cuda_bf16.h>
#include <cstdint>

#define BATCH 4
#define S_LEN 2048
#define NH    16
#define DK    64
#define DM    1024
#define MT    (BATCH*S_LEN)

__device__ __nv_bfloat16 g_h_hi[MT * DM];
__device__ __nv_bfloat16 g_h_lo[MT * DM];
__device__ __nv_bfloat16 g_wt_hi[4 * DM * DM];
__device__ __nv_bfloat16 g_wt_lo[4 * DM * DM];
__device__ float g_q[BATCH * NH * S_LEN * DK];
__device__ float g_k[BATCH * NH * S_LEN * DK];
__device__ float g_v[BATCH * NH * S_LEN * DK];
__device__ __nv_bfloat16 g_ctx_hi[MT * DM];
__device__ __nv_bfloat16 g_ctx_lo[MT * DM];

// ---------------- helpers ----------------
__device__ __forceinline__ uint32_t smem_u32(const void* p) {
    uint32_t a;
    asm("{ .reg .u64 t; cvta.to.shared.u64 t, %1; cvt.u32.u64 %0, t; }" : "=r"(a) : "l"(p));
    return a;
}
__device__ __forceinline__ void cp16(uint32_t dst, const void* src) {
    asm volatile("cp.async.cg.shared.global [%0], [%1], 16;" :: "r"(dst), "l"(src));
}
__device__ __forceinline__ void cp_commit() { asm volatile("cp.async.commit_group;" ::: "memory"); }
template<int N> __device__ __forceinline__ void cp_wait() {
    asm volatile("cp.async.wait_group %0;" :: "n"(N) : "memory");
}
__device__ __forceinline__ void ldm_x4(uint32_t a, uint32_t& r0, uint32_t& r1,
                                       uint32_t& r2, uint32_t& r3) {
    asm volatile("ldmatrix.sync.aligned.m8n8.x4.shared.b16 {%0,%1,%2,%3}, [%4];"
                 : "=r"(r0), "=r"(r1), "=r"(r2), "=r"(r3) : "r"(a));
}
__device__ __forceinline__ void ldm_x2(uint32_t a, uint32_t& r0, uint32_t& r1) {
    asm volatile("ldmatrix.sync.aligned.m8n8.x2.shared.b16 {%0,%1}, [%2];"
                 : "=r"(r0), "=r"(r1) : "r"(a));
}
__device__ __forceinline__ void mma16816(float* c, const uint32_t* a, const uint32_t* b) {
    asm volatile("mma.sync.aligned.m16n8k16.row.col.f32.bf16.bf16.f32 "
                 "{%0,%1,%2,%3},{%4,%5,%6,%7},{%8,%9},{%0,%1,%2,%3};"
                 : "+f"(c[0]), "+f"(c[1]), "+f"(c[2]), "+f"(c[3])
                 : "r"(a[0]), "r"(a[1]), "r"(a[2]), "r"(a[3]), "r"(b[0]), "r"(b[1]));
}

// ---------------- prep ----------------
__global__ void split_hidden(const float4* __restrict__ in,
                             __nv_bfloat16* __restrict__ hi, __nv_bfloat16* __restrict__ lo)
{
    int i = blockIdx.x * 256 + threadIdx.x;
    float4 v = in[i];
    float f[4] = {v.x, v.y, v.z, v.w};
    __nv_bfloat16 h4[4], l4[4];
#pragma unroll
    for (int j = 0; j < 4; ++j) {
        h4[j] = __float2bfloat16(f[j]);
        l4[j] = __float2bfloat16(f[j] - __bfloat162float(h4[j]));
    }
    *(uint2*)(hi + (size_t)i * 4) = *(uint2*)h4;
    *(uint2*)(lo + (size_t)i * 4) = *(uint2*)l4;
}

__global__ void transpose_split(const float* __restrict__ w0, const float* __restrict__ w1,
                                const float* __restrict__ w2, const float* __restrict__ w3,
                                __nv_bfloat16* __restrict__ ohi, __nv_bfloat16* __restrict__ olo)
{
    __shared__ float t[32][33];
    const float* w = blockIdx.z == 0 ? w0 : blockIdx.z == 1 ? w1 : blockIdx.z == 2 ? w2 : w3;
    size_t zoff = (size_t)blockIdx.z * DM * DM;
    int x0 = blockIdx.x * 32, y0 = blockIdx.y * 32;
    for (int i = threadIdx.y; i < 32; i += 8)
        t[i][threadIdx.x] = w[(size_t)(y0 + i) * DM + x0 + threadIdx.x];
    __syncthreads();
    for (int i = threadIdx.y; i < 32; i += 8) {
        float v = t[threadIdx.x][i];
        __nv_bfloat16 hb = __float2bfloat16(v);
        __nv_bfloat16 lb = __float2bfloat16(v - __bfloat162float(hb));
        size_t o = zoff + (size_t)(x0 + i) * DM + y0 + threadIdx.x;
        ohi[o] = hb; olo[o] = lb;
    }
}

// ---------------- HMMA split-bf16 GEMM: C[8192,1024] = A[M,K] * Bt[N,K]^T ----------------
// CTA 128x128, 8 warps (2 M x 4 N), warp tile 64x32. K-chunk 32, 3 stages.
// smem rows padded to 40 bf16 (80 B): granule stride 5 (odd) => conflict-free ldmatrix.
#define KCH   32
#define NKT   (DM / KCH)        // 32
#define ROWB  80                // bytes per padded row
#define OFF_AL (128 * 40)       // element offsets inside a stage
#define OFF_BH (2 * 128 * 40)
#define OFF_BL (3 * 128 * 40)
#define STG_BYTES (4 * 128 * 40 * 2)   // 40960
#define GEMM_SMEM (3 * STG_BYTES)      // 122880

__global__ __launch_bounds__(256, 1) void gemm_hmma(
    const __nv_bfloat16* __restrict__ Ah, const __nv_bfloat16* __restrict__ Al,
    const __nv_bfloat16* __restrict__ Bh, const __nv_bfloat16* __restrict__ Bl,
    float* __restrict__ out, int headMajor)
{
    extern __shared__ __align__(16) char dsm[];
    const uint32_t base = smem_u32(dsm);
    const int tid = threadIdx.x, lane = tid & 31, wid = tid >> 5;
    const int warpM = wid & 1, warpN = wid >> 1;
    const int m0 = blockIdx.y * 128, n0 = blockIdx.x * 128;

    const __nv_bfloat16* Ahp = Ah + (size_t)m0 * DM;
    const __nv_bfloat16* Alp = Al + (size_t)m0 * DM;
    const __nv_bfloat16* Bhp = Bh + (size_t)n0 * DM;
    const __nv_bfloat16* Blp = Bl + (size_t)n0 * DM;

    const int lrow = tid >> 2;          // 0..63 base row for loads (2 iters -> 128)
    const int lu   = tid & 3;           // 16B unit within 64B row

    auto issue = [&](int kc, int st) {
        uint32_t sb = base + st * STG_BYTES;
#pragma unroll
        for (int t = 0; t < 2; ++t) {
            int row = lrow + t * 64;
            uint32_t d = sb + row * ROWB + lu * 16;
            size_t  go = (size_t)row * DM + kc + lu * 8;
            cp16(d,                Ahp + go);
            cp16(d + OFF_AL * 2,   Alp + go);
            cp16(d + OFF_BH * 2,   Bhp + go);
            cp16(d + OFF_BL * 2,   Blp + go);
        }
        cp_commit();
    };

    float acc[4][4][4];
#pragma unroll
    for (int i = 0; i < 4; ++i)
#pragma unroll
        for (int j = 0; j < 4; ++j)
#pragma unroll
            for (int r = 0; r < 4; ++r) acc[i][j][r] = 0.f;

    issue(0, 0);
    issue(KCH, 1);

    // ldmatrix base offsets (per-thread, within a stage)
    const uint32_t aRow = (uint32_t)(warpM * 64 + (lane & 15));
    const uint32_t aCol = (uint32_t)(((lane >> 4) & 1) * 16);
    const uint32_t bRow = (uint32_t)(warpN * 32 + (lane & 7));
    const uint32_t bCol = (uint32_t)(((lane >> 3) & 1) * 16);

    for (int kt = 0; kt < NKT; ++kt) {
        int st = kt % 3;
        if (kt + 2 < NKT) issue((kt + 2) * KCH, (kt + 2) % 3);
        else cp_commit();               // keep group count uniform
        cp_wait<2>();
        __syncthreads();

        uint32_t sb = base + st * STG_BYTES;
#pragma unroll
        for (int s = 0; s < 2; ++s) {   // two k16 steps
            uint32_t ah[4][4], al[4][4], bh[4][2], bl[4][2];
#pragma unroll
            for (int i = 0; i < 4; ++i) {
                uint32_t a = sb + (aRow + i * 16) * ROWB + s * 32 + aCol;
                ldm_x4(a,                ah[i][0], ah[i][1], ah[i][2], ah[i][3]);
                ldm_x4(a + OFF_AL * 2,   al[i][0], al[i][1], al[i][2], al[i][3]);
            }
#pragma unroll
            for (int j = 0; j < 4; ++j) {
                uint32_t b = sb + (bRow + j * 8) * ROWB + s * 32 + bCol;
                ldm_x2(b + OFF_BH * 2,   bh[j][0], bh[j][1]);
                ldm_x2(b + OFF_BL * 2,   bl[j][0], bl[j][1]);
            }
#pragma unroll
            for (int i = 0; i < 4; ++i)
#pragma unroll
                for (int j = 0; j < 4; ++j) {
                    mma16816(acc[i][j], ah[i], bh[j]);
                    mma16816(acc[i][j], ah[i], bl[j]);
                    mma16816(acc[i][j], al[i], bh[j]);
                }
        }
        __syncthreads();
    }

    // epilogue
#pragma unroll
    for (int i = 0; i < 4; ++i) {
        int mA = m0 + warpM * 64 + i * 16 + (lane >> 2);
        int mB = mA + 8;
#pragma unroll
        for (int j = 0; j < 4; ++j) {
            int n = n0 + warpN * 32 + j * 8 + ((lane & 3) << 1);
            float2 v0 = make_float2(acc[i][j][0], acc[i][j][1]);
            float2 v1 = make_float2(acc[i][j][2], acc[i][j][3]);
            if (headMajor) {
                int hh = n >> 6, dd = n & 63;
                int bA = mA >> 11, sA = mA & (S_LEN - 1);
                int bB = mB >> 11, sB = mB & (S_LEN - 1);
                *(float2*)(out + ((size_t)(bA * NH + hh) * S_LEN + sA) * DK + dd) = v0;
                *(float2*)(out + ((size_t)(bB * NH + hh) * S_LEN + sB) * DK + dd) = v1;
            } else {
                *(float2*)(out + (size_t)mA * DM + n) = v0;
                *(float2*)(out + (size_t)mB * DM + n) = v1;
            }
        }
    }
}

// ---------------- flash attention (fp32 SIMT, occ 2) ----------------
__device__ __forceinline__ int t5_bucket(int delta)
{
    int base = (delta > 0) ? 16 : 0;
    int a = delta < 0 ? -delta : delta;
    int bucket;
    if (a < 8) bucket = a;
    else if (a >= 128) bucket = 15;
    else {
        int t = 31 - __clz(a);
        int f = (a * a >= (1 << (2 * t + 1))) ? 1 : 0;
        bucket = 2 + 2 * t + f;
        if (bucket > 15) bucket = 15;
    }
    return base + bucket;
}

#define ATTN_SMEM_FLOATS (64*132 + 64*68 + 64*68 + 64*132 + 32)
#define ATTN_SMEM_BYTES  (ATTN_SMEM_FLOATS * 4)

__global__ __launch_bounds__(256, 2) void attn_kernel(
    const float* __restrict__ Q, const float* __restrict__ K,
    const float* __restrict__ V, const float* __restrict__ rel_bias,
    __nv_bfloat16* __restrict__ ctx_hi, __nv_bfloat16* __restrict__ ctx_lo)
{
    extern __shared__ float sm[];
    float* Qs    = sm;
    float* Ks    = Qs + 64 * 132;
    float* Vs    = Ks + 64 * 68;
    float* Ps    = Vs + 64 * 68;
    float* sbias = Ps + 64 * 132;

    const int bh = blockIdx.y;
    const int hd = bh & (NH - 1);
    const int b  = bh >> 4;
    const int q0 = blockIdx.x * 128;
    const int tid = threadIdx.x;
    const int tx  = tid & 15;
    const int ty  = tid >> 4;

    const float* Qbase = Q + (size_t)bh * S_LEN * DK;
    const float* Kbase = K + (size_t)bh * S_LEN * DK;
    const float* Vbase = V + (size_t)bh * S_LEN * DK;

    if (tid < 32) sbias[tid] = rel_bias[tid * NH + hd];

#pragma unroll
    for (int it = 0; it < 8; ++it) {
        int i  = tid + it * 256;
        int qr = i >> 4;
        int dg = (i & 15) * 4;
        float4 t = *(const float4*)(Qbase + (size_t)(q0 + qr) * DK + dg);
        Qs[(dg + 0) * 132 + qr] = t.x;
        Qs[(dg + 1) * 132 + qr] = t.y;
        Qs[(dg + 2) * 132 + qr] = t.z;
        Qs[(dg + 3) * 132 + qr] = t.w;
    }

    float acc[8][4], mrow[8], lrow[8];
#pragma unroll
    for (int r = 0; r < 8; ++r) {
        mrow[r] = -1e30f; lrow[r] = 0.f;
#pragma unroll
        for (int c = 0; c < 4; ++c) acc[r][c] = 0.f;
    }
    __syncthreads();

    for (int k0 = 0; k0 < S_LEN; k0 += 64) {
#pragma unroll
        for (int it = 0; it < 4; ++it) {
            int i  = tid + it * 256;
            int kr = i >> 4;
            int dg = (i & 15) * 4;
            float4 t = *(const float4*)(Kbase + (size_t)(k0 + kr) * DK + dg);
            Ks[(dg + 0) * 68 + kr] = t.x;
            Ks[(dg + 1) * 68 + kr] = t.y;
            Ks[(dg + 2) * 68 + kr] = t.z;
            Ks[(dg + 3) * 68 + kr] = t.w;
            float4 u = *(const float4*)(Vbase + (size_t)(k0 + kr) * DK + dg);
            *(float4*)(Vs + kr * 68 + dg) = u;
        }
        __syncthreads();

        float sf[8][4];
#pragma unroll
        for (int r = 0; r < 8; ++r)
#pragma unroll
            for (int c = 0; c < 4; ++c) sf[r][c] = 0.f;

#pragma unroll 4
        for (int d = 0; d < 64; ++d) {
            float4 a0 = *(const float4*)(Qs + d * 132 + ty * 8);
            float4 a1 = *(const float4*)(Qs + d * 132 + ty * 8 + 4);
            float4 bb = *(const float4*)(Ks + d * 68 + tx * 4);
            float av[8] = {a0.x, a0.y, a0.z, a0.w, a1.x, a1.y, a1.z, a1.w};
            float bv[4] = {bb.x, bb.y, bb.z, bb.w};
#pragma unroll
            for (int r = 0; r < 8; ++r)
#pragma unroll
                for (int c = 0; c < 4; ++c)
                    sf[r][c] = fmaf(av[r], bv[c], sf[r][c]);
        }

#pragma unroll
        for (int r = 0; r < 8; ++r) {
            int qg = q0 + ty * 8 + r;
            float rmax = -1e30f;
#pragma unroll
            for (int c = 0; c < 4; ++c) {
                int kg = k0 + tx * 4 + c;
                float v = sf[r][c] + sbias[t5_bucket(kg - qg)];
                sf[r][c] = v;
                rmax = fmaxf(rmax, v);
            }
            rmax = fmaxf(rmax, __shfl_xor_sync(0xffffffffu, rmax, 1));
            rmax = fmaxf(rmax, __shfl_xor_sync(0xffffffffu, rmax, 2));
            rmax = fmaxf(rmax, __shfl_xor_sync(0xffffffffu, rmax, 4));
            rmax = fmaxf(rmax, __shfl_xor_sync(0xffffffffu, rmax, 8));

            float mnew = fmaxf(mrow[r], rmax);
            float corr = __expf(mrow[r] - mnew);
            mrow[r] = mnew;

            float psum = 0.f;
#pragma unroll
            for (int c = 0; c < 4; ++c) {
                float p = __expf(sf[r][c] - mnew);
                sf[r][c] = p;
                psum += p;
            }
            psum += __shfl_xor_sync(0xffffffffu, psum, 1);
            psum += __shfl_xor_sync(0xffffffffu, psum, 2);
            psum += __shfl_xor_sync(0xffffffffu, psum, 4);
            psum += __shfl_xor_sync(0xffffffffu, psum, 8);

            lrow[r] = lrow[r] * corr + psum;
#pragma unroll
            for (int c = 0; c < 4; ++c) acc[r][c] *= corr;
#pragma unroll
            for (int c = 0; c < 4; ++c)
                Ps[(tx * 4 + c) * 132 + ty * 8 + r] = sf[r][c];
        }
        __syncthreads();

#pragma unroll 4
        for (int kk = 0; kk < 64; ++kk) {
            float4 a0 = *(const float4*)(Ps + kk * 132 + ty * 8);
            float4 a1 = *(const float4*)(Ps + kk * 132 + ty * 8 + 4);
            float4 bb = *(const float4*)(Vs + kk * 68 + tx * 4);
            float av[8] = {a0.x, a0.y, a0.z, a0.w, a1.x, a1.y, a1.z, a1.w};
            float bv[4] = {bb.x, bb.y, bb.z, bb.w};
#pragma unroll
            for (int r = 0; r < 8; ++r)
#pragma unroll
                for (int c = 0; c < 4; ++c)
                    acc[r][c] = fmaf(av[r], bv[c], acc[r][c]);
        }
        __syncthreads();
    }

#pragma unroll
    for (int r = 0; r < 8; ++r) {
        float inv = 1.f / lrow[r];
        int qg = q0 + ty * 8 + r;
        __nv_bfloat16 hv[4], lv[4];
#pragma unroll
        for (int c = 0; c < 4; ++c) {
            float val = acc[r][c] * inv;
            hv[c] = __float2bfloat16(val);
            lv[c] = __float2bfloat16(val - __bfloat162float(hv[c]));
        }
        size_t o = ((size_t)b * S_LEN + qg) * DM + hd * DK + tx * 4;
        *(uint2*)(ctx_hi + o) = *(uint2*)hv;
        *(uint2*)(ctx_lo + o) = *(uint2*)lv;
    }
}

// ---------------------------------------------------------------------------
extern "C" void kernel_launch(void* const* d_in, const int* in_sizes, int n_in,
                              void* d_out, int out_size)
{
    const float* hidden  = (const float*)d_in[0];
    const float* wq      = (const float*)d_in[1];
    const float* wk      = (const float*)d_in[2];
    const float* wv      = (const float*)d_in[3];
    const float* wo      = (const float*)d_in[4];
    const float* relbias = (const float*)d_in[5];
    float* out = (float*)d_out;

    __nv_bfloat16 *hhi, *hlo, *whi, *wlo, *chi, *clo;
    float *q, *k, *v;
    cudaGetSymbolAddress((void**)&hhi, g_h_hi);
    cudaGetSymbolAddress((void**)&hlo, g_h_lo);
    cudaGetSymbolAddress((void**)&whi, g_wt_hi);
    cudaGetSymbolAddress((void**)&wlo, g_wt_lo);
    cudaGetSymbolAddress((void**)&q,   g_q);
    cudaGetSymbolAddress((void**)&k,   g_k);
    cudaGetSymbolAddress((void**)&v,   g_v);
    cudaGetSymbolAddress((void**)&chi, g_ctx_hi);
    cudaGetSymbolAddress((void**)&clo, g_ctx_lo);

    cudaFuncSetAttribute(attn_kernel, cudaFuncAttributeMaxDynamicSharedMemorySize, ATTN_SMEM_BYTES);
    cudaFuncSetAttribute(gemm_hmma,   cudaFuncAttributeMaxDynamicSharedMemorySize, GEMM_SMEM);

    split_hidden<<<MT * DM / 1024, 256>>>((const float4*)hidden, hhi, hlo);
    transpose_split<<<dim3(32, 32, 4), dim3(32, 8)>>>(wq, wk, wv, wo, whi, wlo);

    dim3 gG(DM / 128, MT / 128);     // (8, 64)
    const size_t WSZ = (size_t)DM * DM;
    gemm_hmma<<<gG, 256, GEMM_SMEM>>>(hhi, hlo, whi + 0*WSZ, wlo + 0*WSZ, q, 1);
    gemm_hmma<<<gG, 256, GEMM_SMEM>>>(hhi, hlo, whi + 1*WSZ, wlo + 1*WSZ, k, 1);
    gemm_hmma<<<gG, 256, GEMM_SMEM>>>(hhi, hlo, whi + 2*WSZ, wlo + 2*WSZ, v, 1);

    dim3 gA(S_LEN / 128, BATCH * NH);
    attn_kernel<<<gA, 256, ATTN_SMEM_BYTES>>>(q, k, v, relbias, chi, clo);

    gemm_hmma<<<gG, 256, GEMM_SMEM>>>(chi, clo, whi + 3*WSZ, wlo + 3*WSZ, out, 0);
}

// round 5
// speedup vs baseline: 2.1451x; 1.4434x over previous
#include <cuda_runtime.h>
#include <cuda_bf16.h>
#include <cstdint>

#define BATCH 4
#define S_LEN 2048
#define NH    16
#define DK    64
#define DM    1024
#define MT    (BATCH*S_LEN)
#define BHSZ  ((size_t)BATCH * NH * S_LEN * DK)

__device__ __nv_bfloat16 g_h_hi[MT * DM];
__device__ __nv_bfloat16 g_h_lo[MT * DM];
__device__ __nv_bfloat16 g_wt_hi[4 * DM * DM];
__device__ __nv_bfloat16 g_wt_lo[4 * DM * DM];
__device__ __nv_bfloat16 g_qh[BHSZ], g_ql[BHSZ];
__device__ __nv_bfloat16 g_kh[BHSZ], g_kl[BHSZ];
__device__ __nv_bfloat16 g_vh[BHSZ], g_vl[BHSZ];
__device__ __nv_bfloat16 g_ctx_hi[MT * DM];
__device__ __nv_bfloat16 g_ctx_lo[MT * DM];

// ---------------- helpers ----------------
__device__ __forceinline__ uint32_t smem_u32(const void* p) {
    uint32_t a;
    asm("{ .reg .u64 t; cvta.to.shared.u64 t, %1; cvt.u32.u64 %0, t; }" : "=r"(a) : "l"(p));
    return a;
}
__device__ __forceinline__ void cp16(uint32_t dst, const void* src) {
    asm volatile("cp.async.cg.shared.global [%0], [%1], 16;" :: "r"(dst), "l"(src));
}
__device__ __forceinline__ void cp_commit() { asm volatile("cp.async.commit_group;" ::: "memory"); }
template<int N> __device__ __forceinline__ void cp_wait() {
    asm volatile("cp.async.wait_group %0;" :: "n"(N) : "memory");
}
__device__ __forceinline__ void ldm_x4(uint32_t a, uint32_t& r0, uint32_t& r1,
                                       uint32_t& r2, uint32_t& r3) {
    asm volatile("ldmatrix.sync.aligned.m8n8.x4.shared.b16 {%0,%1,%2,%3}, [%4];"
                 : "=r"(r0), "=r"(r1), "=r"(r2), "=r"(r3) : "r"(a));
}
__device__ __forceinline__ void ldm_x4t(uint32_t a, uint32_t& r0, uint32_t& r1,
                                        uint32_t& r2, uint32_t& r3) {
    asm volatile("ldmatrix.sync.aligned.m8n8.x4.trans.shared.b16 {%0,%1,%2,%3}, [%4];"
                 : "=r"(r0), "=r"(r1), "=r"(r2), "=r"(r3) : "r"(a));
}
__device__ __forceinline__ void ldm_x2(uint32_t a, uint32_t& r0, uint32_t& r1) {
    asm volatile("ldmatrix.sync.aligned.m8n8.x2.shared.b16 {%0,%1}, [%2];"
                 : "=r"(r0), "=r"(r1) : "r"(a));
}
__device__ __forceinline__ void mma16816(float* c, const uint32_t* a, const uint32_t* b) {
    asm volatile("mma.sync.aligned.m16n8k16.row.col.f32.bf16.bf16.f32 "
                 "{%0,%1,%2,%3},{%4,%5,%6,%7},{%8,%9},{%0,%1,%2,%3};"
                 : "+f"(c[0]), "+f"(c[1]), "+f"(c[2]), "+f"(c[3])
                 : "r"(a[0]), "r"(a[1]), "r"(a[2]), "r"(a[3]), "r"(b[0]), "r"(b[1]));
}
__device__ __forceinline__ void pksplit(float x, float y, uint32_t& hi, uint32_t& lo) {
    __nv_bfloat162 h = __floats2bfloat162_rn(x, y);
    __nv_bfloat162 l = __floats2bfloat162_rn(x - __bfloat162float(h.x),
                                             y - __bfloat162float(h.y));
    hi = *(uint32_t*)&h; lo = *(uint32_t*)&l;
}

// ---------------- prep ----------------
__global__ void split_hidden(const float4* __restrict__ in,
                             __nv_bfloat16* __restrict__ hi, __nv_bfloat16* __restrict__ lo)
{
    int i = blockIdx.x * 256 + threadIdx.x;
    float4 v = in[i];
    float f[4] = {v.x, v.y, v.z, v.w};
    __nv_bfloat16 h4[4], l4[4];
#pragma unroll
    for (int j = 0; j < 4; ++j) {
        h4[j] = __float2bfloat16(f[j]);
        l4[j] = __float2bfloat16(f[j] - __bfloat162float(h4[j]));
    }
    *(uint2*)(hi + (size_t)i * 4) = *(uint2*)h4;
    *(uint2*)(lo + (size_t)i * 4) = *(uint2*)l4;
}

__global__ void transpose_split(const float* __restrict__ w0, const float* __restrict__ w1,
                                const float* __restrict__ w2, const float* __restrict__ w3,
                                __nv_bfloat16* __restrict__ ohi, __nv_bfloat16* __restrict__ olo)
{
    __shared__ float t[32][33];
    const float* w = blockIdx.z == 0 ? w0 : blockIdx.z == 1 ? w1 : blockIdx.z == 2 ? w2 : w3;
    size_t zoff = (size_t)blockIdx.z * DM * DM;
    int x0 = blockIdx.x * 32, y0 = blockIdx.y * 32;
    for (int i = threadIdx.y; i < 32; i += 8)
        t[i][threadIdx.x] = w[(size_t)(y0 + i) * DM + x0 + threadIdx.x];
    __syncthreads();
    for (int i = threadIdx.y; i < 32; i += 8) {
        float v = t[threadIdx.x][i];
        __nv_bfloat16 hb = __float2bfloat16(v);
        __nv_bfloat16 lb = __float2bfloat16(v - __bfloat162float(hb));
        size_t o = zoff + (size_t)(x0 + i) * DM + y0 + threadIdx.x;
        ohi[o] = hb; olo[o] = lb;
    }
}

// ---------------- HMMA split-bf16 GEMM (2-stage, occ 2) ----------------
#define KCH   32
#define NKT   (DM / KCH)
#define ROWB  80
#define OFF_AL (128 * 40)
#define OFF_BH (2 * 128 * 40)
#define OFF_BL (3 * 128 * 40)
#define STG_BYTES (4 * 128 * 40 * 2)
#define GEMM_SMEM (2 * STG_BYTES)

__global__ __launch_bounds__(256, 2) void gemm_hmma(
    const __nv_bfloat16* __restrict__ Ah, const __nv_bfloat16* __restrict__ Al,
    const __nv_bfloat16* __restrict__ Bh, const __nv_bfloat16* __restrict__ Bl,
    float* __restrict__ outF, __nv_bfloat16* __restrict__ outH,
    __nv_bfloat16* __restrict__ outL, int headMajor)
{
    extern __shared__ __align__(16) char dsm[];
    const uint32_t base = smem_u32(dsm);
    const int tid = threadIdx.x, lane = tid & 31, wid = tid >> 5;
    const int warpM = wid & 1, warpN = wid >> 1;
    const int m0 = blockIdx.y * 128, n0 = blockIdx.x * 128;

    const __nv_bfloat16* Ahp = Ah + (size_t)m0 * DM;
    const __nv_bfloat16* Alp = Al + (size_t)m0 * DM;
    const __nv_bfloat16* Bhp = Bh + (size_t)n0 * DM;
    const __nv_bfloat16* Blp = Bl + (size_t)n0 * DM;

    const int lrow = tid >> 2;
    const int lu   = tid & 3;

    auto issue = [&](int kc, int st) {
        uint32_t sb = base + st * STG_BYTES;
#pragma unroll
        for (int t = 0; t < 2; ++t) {
            int row = lrow + t * 64;
            uint32_t d = sb + row * ROWB + lu * 16;
            size_t  go = (size_t)row * DM + kc + lu * 8;
            cp16(d,              Ahp + go);
            cp16(d + OFF_AL * 2, Alp + go);
            cp16(d + OFF_BH * 2, Bhp + go);
            cp16(d + OFF_BL * 2, Blp + go);
        }
        cp_commit();
    };

    float acc[4][4][4];
#pragma unroll
    for (int i = 0; i < 4; ++i)
#pragma unroll
        for (int j = 0; j < 4; ++j)
#pragma unroll
            for (int r = 0; r < 4; ++r) acc[i][j][r] = 0.f;

    issue(0, 0);
    issue(KCH, 1);

    const uint32_t aRow = (uint32_t)(warpM * 64 + (lane & 15));
    const uint32_t aCol = (uint32_t)(((lane >> 4) & 1) * 16);
    const uint32_t bRow = (uint32_t)(warpN * 32 + (lane & 7));
    const uint32_t bCol = (uint32_t)(((lane >> 3) & 1) * 16);

    for (int kt = 0; kt < NKT; ++kt) {
        if (kt + 2 < NKT) cp_wait<1>(); else cp_wait<0>();
        __syncthreads();

        uint32_t sb = base + (kt & 1) * STG_BYTES;
#pragma unroll
        for (int s = 0; s < 2; ++s) {
            uint32_t ah[4][4], al[4][4], bh[4][2], bl[4][2];
#pragma unroll
            for (int i = 0; i < 4; ++i) {
                uint32_t a = sb + (aRow + i * 16) * ROWB + s * 32 + aCol;
                ldm_x4(a,              ah[i][0], ah[i][1], ah[i][2], ah[i][3]);
                ldm_x4(a + OFF_AL * 2, al[i][0], al[i][1], al[i][2], al[i][3]);
            }
#pragma unroll
            for (int j = 0; j < 4; ++j) {
                uint32_t b = sb + (bRow + j * 8) * ROWB + s * 32 + bCol;
                ldm_x2(b + OFF_BH * 2, bh[j][0], bh[j][1]);
                ldm_x2(b + OFF_BL * 2, bl[j][0], bl[j][1]);
            }
#pragma unroll
            for (int i = 0; i < 4; ++i)
#pragma unroll
                for (int j = 0; j < 4; ++j) {
                    mma16816(acc[i][j], ah[i], bh[j]);
                    mma16816(acc[i][j], ah[i], bl[j]);
                    mma16816(acc[i][j], al[i], bh[j]);
                }
        }
        __syncthreads();
        if (kt + 2 < NKT) issue((kt + 2) * KCH, kt & 1);
    }

#pragma unroll
    for (int i = 0; i < 4; ++i) {
        int mA = m0 + warpM * 64 + i * 16 + (lane >> 2);
        int mB = mA + 8;
#pragma unroll
        for (int j = 0; j < 4; ++j) {
            int n = n0 + warpN * 32 + j * 8 + ((lane & 3) << 1);
            if (headMajor) {
                int hh = n >> 6, dd = n & 63;
                int bA = mA >> 11, sA = mA & (S_LEN - 1);
                int bB = mB >> 11, sB = mB & (S_LEN - 1);
                size_t oA = ((size_t)(bA * NH + hh) * S_LEN + sA) * DK + dd;
                size_t oB = ((size_t)(bB * NH + hh) * S_LEN + sB) * DK + dd;
                uint32_t h0, l0, h1, l1;
                pksplit(acc[i][j][0], acc[i][j][1], h0, l0);
                pksplit(acc[i][j][2], acc[i][j][3], h1, l1);
                *(uint32_t*)(outH + oA) = h0; *(uint32_t*)(outL + oA) = l0;
                *(uint32_t*)(outH + oB) = h1; *(uint32_t*)(outL + oB) = l1;
            } else {
                *(float2*)(outF + (size_t)mA * DM + n) = make_float2(acc[i][j][0], acc[i][j][1]);
                *(float2*)(outF + (size_t)mB * DM + n) = make_float2(acc[i][j][2], acc[i][j][3]);
            }
        }
    }
}

// ---------------- HMMA flash attention ----------------
__device__ __forceinline__ int t5_bucket(int delta)
{
    int base = (delta > 0) ? 16 : 0;
    int a = delta < 0 ? -delta : delta;
    int bucket;
    if (a < 8) bucket = a;
    else if (a >= 128) bucket = 15;
    else {
        int t = 31 - __clz(a);
        int f = (a * a >= (1 << (2 * t + 1))) ? 1 : 0;
        bucket = 2 + 2 * t + f;
        if (bucket > 15) bucket = 15;
    }
    return base + bucket;
}

#define PQ        144                    // smem row pitch bytes (72 bf16)
#define A_QH      0
#define A_QL      18432
#define A_BUF     36864
#define A_BUFSZ   36864                  // KH,KL,VH,VL tiles (64 rows each)
#define A_KH      0
#define A_KL      9216
#define A_VH      18432
#define A_VL      27648
#define A_BIAS    (A_BUF + 2*A_BUFSZ)    // 110592
#define ATT_SMEM  (A_BIAS + 1152)        // 111744

__global__ __launch_bounds__(256, 2) void attn_mma(
    const __nv_bfloat16* __restrict__ qh, const __nv_bfloat16* __restrict__ ql,
    const __nv_bfloat16* __restrict__ kh, const __nv_bfloat16* __restrict__ kl,
    const __nv_bfloat16* __restrict__ vh, const __nv_bfloat16* __restrict__ vl,
    const float* __restrict__ rel_bias,
    __nv_bfloat16* __restrict__ chi, __nv_bfloat16* __restrict__ clo)
{
    extern __shared__ __align__(16) char asmem[];
    const uint32_t base = smem_u32(asmem);
    float* bias = (float*)(asmem + A_BIAS);

    const int tid = threadIdx.x, lane = tid & 31, wid = tid >> 5;
    const int bh = blockIdx.y;
    const int hd = bh & (NH - 1);
    const int b  = bh >> 4;
    const int q0 = blockIdx.x * 128;
    const size_t bo = (size_t)bh * S_LEN * DK;

    for (int i = tid; i < 257; i += 256)
        bias[i] = rel_bias[t5_bucket(i - 128) * NH + hd];

    // Q tile (hi+lo) via cp.async — group 0 with K/V tile 0
#pragma unroll
    for (int it = 0; it < 8; ++it) {
        int idx = tid + it * 256;
        int sub = idx & 1023, row = sub >> 3, u = sub & 7;
        const __nv_bfloat16* src = (it < 4) ? qh : ql;
        cp16(base + (it < 4 ? A_QH : A_QL) + row * PQ + u * 16,
             src + bo + (size_t)(q0 + row) * DK + u * 8);
    }
    auto issue_kv = [&](int t, int buf) {
        uint32_t bb = base + A_BUF + buf * A_BUFSZ;
#pragma unroll
        for (int it = 0; it < 8; ++it) {
            int idx = tid + it * 256;
            int sub = idx & 511, row = sub >> 3, u = sub & 7;
            const __nv_bfloat16* src = (it < 2) ? kh : (it < 4) ? kl : (it < 6) ? vh : vl;
            uint32_t toff = (it < 2) ? A_KH : (it < 4) ? A_KL : (it < 6) ? A_VH : A_VL;
            cp16(bb + toff + row * PQ + u * 16,
                 src + bo + (size_t)(t * 64 + row) * DK + u * 8);
        }
        cp_commit();
    };
    issue_kv(0, 0);   // commits group 0 (Q + tile0)
    issue_kv(1, 1);   // group 1

    const int g  = lane >> 2;      // row within 8
    const int tc = lane & 3;       // col pair selector
    const int qg0 = q0 + wid * 16 + g;
    const int qg1 = qg0 + 8;

    float acc_o[8][4];
#pragma unroll
    for (int j = 0; j < 8; ++j)
#pragma unroll
        for (int r = 0; r < 4; ++r) acc_o[j][r] = 0.f;
    float m0 = -1e30f, m1 = -1e30f, l0 = 0.f, l1 = 0.f;

    const uint32_t aBase = base + (wid * 16 + (lane & 15)) * PQ + ((lane >> 4) & 1) * 16;
    const uint32_t bRowSel = ((lane >> 4) & 1) * 8 + (lane & 7);
    const uint32_t bColSel = ((lane >> 3) & 1) * 16;
    const uint32_t vRowSel = ((lane >> 3) & 1) * 8 + (lane & 7);
    const uint32_t vColSel = ((lane >> 4) & 1) * 16;

    for (int t = 0; t < 32; ++t) {
        if (t + 2 < 32) cp_wait<1>(); else cp_wait<0>();
        __syncthreads();
        uint32_t kb = base + A_BUF + (t & 1) * A_BUFSZ;

        // ---- S = Q K^T (split-bf16, 3 mma) ----
        float s[8][4];
#pragma unroll
        for (int j = 0; j < 8; ++j)
#pragma unroll
            for (int r = 0; r < 4; ++r) s[j][r] = 0.f;

#pragma unroll
        for (int ks = 0; ks < 4; ++ks) {
            uint32_t ah[4], al[4];
            ldm_x4(aBase + ks * 32,        ah[0], ah[1], ah[2], ah[3]);
            ldm_x4(aBase + A_QL + ks * 32, al[0], al[1], al[2], al[3]);
#pragma unroll
            for (int nb2 = 0; nb2 < 4; ++nb2) {
                uint32_t bAddr = kb + A_KH + (nb2 * 16 + bRowSel) * PQ + bColSel + ks * 32;
                uint32_t h0, h1, h2, h3, u0, u1, u2, u3;
                ldm_x4(bAddr,          h0, h1, h2, h3);
                ldm_x4(bAddr + A_KL,   u0, u1, u2, u3);
                uint32_t bh0[2] = {h0, h1}, bh1[2] = {h2, h3};
                uint32_t bl0[2] = {u0, u1}, bl1[2] = {u2, u3};
                mma16816(s[2*nb2],   ah, bh0); mma16816(s[2*nb2],   ah, bl0);
                mma16816(s[2*nb2],   al, bh0);
                mma16816(s[2*nb2+1], ah, bh1); mma16816(s[2*nb2+1], ah, bl1);
                mma16816(s[2*nb2+1], al, bh1);
            }
        }

        // ---- bias + online softmax ----
        int ktb = t * 64;
        float rm0 = -1e30f, rm1 = -1e30f;
#pragma unroll
        for (int nb = 0; nb < 8; ++nb) {
            int kg = ktb + nb * 8 + tc * 2;
            int d00 = kg - qg0, d10 = kg - qg1;
            int i00 = min(max(d00,     -128), 128) + 128;
            int i01 = min(max(d00 + 1, -128), 128) + 128;
            int i10 = min(max(d10,     -128), 128) + 128;
            int i11 = min(max(d10 + 1, -128), 128) + 128;
            s[nb][0] += bias[i00]; s[nb][1] += bias[i01];
            s[nb][2] += bias[i10]; s[nb][3] += bias[i11];
            rm0 = fmaxf(rm0, fmaxf(s[nb][0], s[nb][1]));
            rm1 = fmaxf(rm1, fmaxf(s[nb][2], s[nb][3]));
        }
        rm0 = fmaxf(rm0, __shfl_xor_sync(0xffffffffu, rm0, 1));
        rm0 = fmaxf(rm0, __shfl_xor_sync(0xffffffffu, rm0, 2));
        rm1 = fmaxf(rm1, __shfl_xor_sync(0xffffffffu, rm1, 1));
        rm1 = fmaxf(rm1, __shfl_xor_sync(0xffffffffu, rm1, 2));

        float mn0 = fmaxf(m0, rm0), mn1 = fmaxf(m1, rm1);
        float c0 = __expf(m0 - mn0), c1 = __expf(m1 - mn1);
        m0 = mn0; m1 = mn1;

        float ps0 = 0.f, ps1 = 0.f;
#pragma unroll
        for (int nb = 0; nb < 8; ++nb) {
            s[nb][0] = __expf(s[nb][0] - mn0); s[nb][1] = __expf(s[nb][1] - mn0);
            s[nb][2] = __expf(s[nb][2] - mn1); s[nb][3] = __expf(s[nb][3] - mn1);
            ps0 += s[nb][0] + s[nb][1];
            ps1 += s[nb][2] + s[nb][3];
        }
        ps0 += __shfl_xor_sync(0xffffffffu, ps0, 1);
        ps0 += __shfl_xor_sync(0xffffffffu, ps0, 2);
        ps1 += __shfl_xor_sync(0xffffffffu, ps1, 1);
        ps1 += __shfl_xor_sync(0xffffffffu, ps1, 2);
        l0 = l0 * c0 + ps0; l1 = l1 * c1 + ps1;

#pragma unroll
        for (int j = 0; j < 8; ++j) {
            acc_o[j][0] *= c0; acc_o[j][1] *= c0;
            acc_o[j][2] *= c1; acc_o[j][3] *= c1;
        }

        // ---- O += P V (split-bf16, 3 mma) ----
#pragma unroll
        for (int ks = 0; ks < 4; ++ks) {
            uint32_t aph[4], apl[4];
            pksplit(s[2*ks][0],   s[2*ks][1],   aph[0], apl[0]);
            pksplit(s[2*ks][2],   s[2*ks][3],   aph[1], apl[1]);
            pksplit(s[2*ks+1][0], s[2*ks+1][1], aph[2], apl[2]);
            pksplit(s[2*ks+1][2], s[2*ks+1][3], aph[3], apl[3]);
#pragma unroll
            for (int db2 = 0; db2 < 4; ++db2) {
                uint32_t vAddr = kb + A_VH + (ks * 16 + vRowSel) * PQ + db2 * 32 + vColSel;
                uint32_t h0, h1, h2, h3, u0, u1, u2, u3;
                ldm_x4t(vAddr,        h0, h1, h2, h3);
                ldm_x4t(vAddr + 9216, u0, u1, u2, u3);
                uint32_t vh0[2] = {h0, h1}, vh1[2] = {h2, h3};
                uint32_t vl0[2] = {u0, u1}, vl1[2] = {u2, u3};
                mma16816(acc_o[2*db2],   aph, vh0); mma16816(acc_o[2*db2],   apl, vh0);
                mma16816(acc_o[2*db2],   aph, vl0);
                mma16816(acc_o[2*db2+1], aph, vh1); mma16816(acc_o[2*db2+1], apl, vh1);
                mma16816(acc_o[2*db2+1], aph, vl1);
            }
        }
        __syncthreads();
        if (t + 2 < 32) issue_kv(t + 2, t & 1);
    }

    // ---- epilogue: ctx = O / l as bf16 hi/lo ----
    float inv0 = 1.f / l0, inv1 = 1.f / l1;
#pragma unroll
    for (int db = 0; db < 8; ++db) {
        int dcol = hd * DK + db * 8 + tc * 2;
        size_t o0 = ((size_t)b * S_LEN + qg0) * DM + dcol;
        size_t o1 = ((size_t)b * S_LEN + qg1) * DM + dcol;
        uint32_t h0, lo0, h1, lo1;
        pksplit(acc_o[db][0] * inv0, acc_o[db][1] * inv0, h0, lo0);
        pksplit(acc_o[db][2] * inv1, acc_o[db][3] * inv1, h1, lo1);
        *(uint32_t*)(chi + o0) = h0; *(uint32_t*)(clo + o0) = lo0;
        *(uint32_t*)(chi + o1) = h1; *(uint32_t*)(clo + o1) = lo1;
    }
}

// ---------------------------------------------------------------------------
extern "C" void kernel_launch(void* const* d_in, const int* in_sizes, int n_in,
                              void* d_out, int out_size)
{
    const float* hidden  = (const float*)d_in[0];
    const float* wq      = (const float*)d_in[1];
    const float* wk      = (const float*)d_in[2];
    const float* wv      = (const float*)d_in[3];
    const float* wo      = (const float*)d_in[4];
    const float* relbias = (const float*)d_in[5];
    float* out = (float*)d_out;

    __nv_bfloat16 *hhi, *hlo, *whi, *wlo, *chi, *clo;
    __nv_bfloat16 *qh, *ql, *kh, *kl, *vh, *vl;
    cudaGetSymbolAddress((void**)&hhi, g_h_hi);
    cudaGetSymbolAddress((void**)&hlo, g_h_lo);
    cudaGetSymbolAddress((void**)&whi, g_wt_hi);
    cudaGetSymbolAddress((void**)&wlo, g_wt_lo);
    cudaGetSymbolAddress((void**)&qh,  g_qh);
    cudaGetSymbolAddress((void**)&ql,  g_ql);
    cudaGetSymbolAddress((void**)&kh,  g_kh);
    cudaGetSymbolAddress((void**)&kl,  g_kl);
    cudaGetSymbolAddress((void**)&vh,  g_vh);
    cudaGetSymbolAddress((void**)&vl,  g_vl);
    cudaGetSymbolAddress((void**)&chi, g_ctx_hi);
    cudaGetSymbolAddress((void**)&clo, g_ctx_lo);

    cudaFuncSetAttribute(gemm_hmma, cudaFuncAttributeMaxDynamicSharedMemorySize, GEMM_SMEM);
    cudaFuncSetAttribute(attn_mma,  cudaFuncAttributeMaxDynamicSharedMemorySize, ATT_SMEM);

    split_hidden<<<MT * DM / 1024, 256>>>((const float4*)hidden, hhi, hlo);
    transpose_split<<<dim3(32, 32, 4), dim3(32, 8)>>>(wq, wk, wv, wo, whi, wlo);

    dim3 gG(DM / 128, MT / 128);
    const size_t WSZ = (size_t)DM * DM;
    gemm_hmma<<<gG, 256, GEMM_SMEM>>>(hhi, hlo, whi + 0*WSZ, wlo + 0*WSZ, nullptr, qh, ql, 1);
    gemm_hmma<<<gG, 256, GEMM_SMEM>>>(hhi, hlo, whi + 1*WSZ, wlo + 1*WSZ, nullptr, kh, kl, 1);
    gemm_hmma<<<gG, 256, GEMM_SMEM>>>(hhi, hlo, whi + 2*WSZ, wlo + 2*WSZ, nullptr, vh, vl, 1);

    dim3 gA(S_LEN / 128, BATCH * NH);
    attn_mma<<<gA, 256, ATT_SMEM>>>(qh, ql, kh, kl, vh, vl, relbias, chi, clo);

    gemm_hmma<<<gG, 256, GEMM_SMEM>>>(chi, clo, whi + 3*WSZ, wlo + 3*WSZ, out, nullptr, nullptr, 0);
}

// round 6
// speedup vs baseline: 3.3363x; 1.5553x over previous
#include <cuda_runtime.h>
#include <cuda_bf16.h>
#include <cuda_fp16.h>
#include <cstdint>

#define BATCH 4
#define S_LEN 2048
#define NH    16
#define DK    64
#define DM    1024
#define MT    (BATCH*S_LEN)
#define BHSZ  ((size_t)BATCH * NH * S_LEN * DK)

__device__ __nv_bfloat16 g_h_hi[MT * DM];
__device__ __nv_bfloat16 g_h_lo[MT * DM];
__device__ __nv_bfloat16 g_wt_hi[4 * DM * DM];
__device__ __nv_bfloat16 g_wt_lo[4 * DM * DM];
__device__ __nv_bfloat16 g_qh[BHSZ], g_ql[BHSZ];
__device__ __nv_bfloat16 g_kh[BHSZ], g_kl[BHSZ];
__device__ __half        g_vf[BHSZ];
__device__ __nv_bfloat16 g_ctx_hi[MT * DM];
__device__ __nv_bfloat16 g_ctx_lo[MT * DM];

// ---------------- helpers ----------------
__device__ __forceinline__ uint32_t smem_u32(const void* p) {
    uint32_t a;
    asm("{ .reg .u64 t; cvta.to.shared.u64 t, %1; cvt.u32.u64 %0, t; }" : "=r"(a) : "l"(p));
    return a;
}
__device__ __forceinline__ void cp16(uint32_t dst, const void* src) {
    asm volatile("cp.async.cg.shared.global [%0], [%1], 16;" :: "r"(dst), "l"(src));
}
__device__ __forceinline__ void cp_commit() { asm volatile("cp.async.commit_group;" ::: "memory"); }
template<int N> __device__ __forceinline__ void cp_wait() {
    asm volatile("cp.async.wait_group %0;" :: "n"(N) : "memory");
}
__device__ __forceinline__ void ldm_x4(uint32_t a, uint32_t& r0, uint32_t& r1,
                                       uint32_t& r2, uint32_t& r3) {
    asm volatile("ldmatrix.sync.aligned.m8n8.x4.shared.b16 {%0,%1,%2,%3}, [%4];"
                 : "=r"(r0), "=r"(r1), "=r"(r2), "=r"(r3) : "r"(a));
}
__device__ __forceinline__ void ldm_x4t(uint32_t a, uint32_t& r0, uint32_t& r1,
                                        uint32_t& r2, uint32_t& r3) {
    asm volatile("ldmatrix.sync.aligned.m8n8.x4.trans.shared.b16 {%0,%1,%2,%3}, [%4];"
                 : "=r"(r0), "=r"(r1), "=r"(r2), "=r"(r3) : "r"(a));
}
__device__ __forceinline__ void ldm_x2(uint32_t a, uint32_t& r0, uint32_t& r1) {
    asm volatile("ldmatrix.sync.aligned.m8n8.x2.shared.b16 {%0,%1}, [%2];"
                 : "=r"(r0), "=r"(r1) : "r"(a));
}
__device__ __forceinline__ void mma16816(float* c, const uint32_t* a, const uint32_t* b) {
    asm volatile("mma.sync.aligned.m16n8k16.row.col.f32.bf16.bf16.f32 "
                 "{%0,%1,%2,%3},{%4,%5,%6,%7},{%8,%9},{%0,%1,%2,%3};"
                 : "+f"(c[0]), "+f"(c[1]), "+f"(c[2]), "+f"(c[3])
                 : "r"(a[0]), "r"(a[1]), "r"(a[2]), "r"(a[3]), "r"(b[0]), "r"(b[1]));
}
__device__ __forceinline__ void mma16816h(float* c, const uint32_t* a, const uint32_t* b) {
    asm volatile("mma.sync.aligned.m16n8k16.row.col.f32.f16.f16.f32 "
                 "{%0,%1,%2,%3},{%4,%5,%6,%7},{%8,%9},{%0,%1,%2,%3};"
                 : "+f"(c[0]), "+f"(c[1]), "+f"(c[2]), "+f"(c[3])
                 : "r"(a[0]), "r"(a[1]), "r"(a[2]), "r"(a[3]), "r"(b[0]), "r"(b[1]));
}
__device__ __forceinline__ void pksplit(float x, float y, uint32_t& hi, uint32_t& lo) {
    __nv_bfloat162 h = __floats2bfloat162_rn(x, y);
    __nv_bfloat162 l = __floats2bfloat162_rn(x - __bfloat162float(h.x),
                                             y - __bfloat162float(h.y));
    hi = *(uint32_t*)&h; lo = *(uint32_t*)&l;
}

// ---------------- prep ----------------
__global__ void split_hidden(const float4* __restrict__ in,
                             __nv_bfloat16* __restrict__ hi, __nv_bfloat16* __restrict__ lo)
{
    int i = blockIdx.x * 256 + threadIdx.x;
    float4 v = in[i];
    float f[4] = {v.x, v.y, v.z, v.w};
    __nv_bfloat16 h4[4], l4[4];
#pragma unroll
    for (int j = 0; j < 4; ++j) {
        h4[j] = __float2bfloat16(f[j]);
        l4[j] = __float2bfloat16(f[j] - __bfloat162float(h4[j]));
    }
    *(uint2*)(hi + (size_t)i * 4) = *(uint2*)h4;
    *(uint2*)(lo + (size_t)i * 4) = *(uint2*)l4;
}

__global__ void transpose_split(const float* __restrict__ w0, const float* __restrict__ w1,
                                const float* __restrict__ w2, const float* __restrict__ w3,
                                __nv_bfloat16* __restrict__ ohi, __nv_bfloat16* __restrict__ olo)
{
    __shared__ float t[32][33];
    const float* w = blockIdx.z == 0 ? w0 : blockIdx.z == 1 ? w1 : blockIdx.z == 2 ? w2 : w3;
    size_t zoff = (size_t)blockIdx.z * DM * DM;
    int x0 = blockIdx.x * 32, y0 = blockIdx.y * 32;
    for (int i = threadIdx.y; i < 32; i += 8)
        t[i][threadIdx.x] = w[(size_t)(y0 + i) * DM + x0 + threadIdx.x];
    __syncthreads();
    for (int i = threadIdx.y; i < 32; i += 8) {
        float v = t[threadIdx.x][i];
        __nv_bfloat16 hb = __float2bfloat16(v);
        __nv_bfloat16 lb = __float2bfloat16(v - __bfloat162float(hb));
        size_t o = zoff + (size_t)(x0 + i) * DM + y0 + threadIdx.x;
        ohi[o] = hb; olo[o] = lb;
    }
}

// ---------------- HMMA split-bf16 GEMM (3-stage, occ 1 — round-4 shape) ----------------
// mode 0: fp32 row-major out. mode 1: bf16 hi/lo head-major. mode 2: fp16 head-major.
#define KCH   32
#define NKT   (DM / KCH)
#define ROWB  80
#define OFF_AL (128 * 40)
#define OFF_BH (2 * 128 * 40)
#define OFF_BL (3 * 128 * 40)
#define STG_BYTES (4 * 128 * 40 * 2)
#define GEMM_SMEM (3 * STG_BYTES)

__global__ __launch_bounds__(256, 1) void gemm_hmma(
    const __nv_bfloat16* __restrict__ Ah, const __nv_bfloat16* __restrict__ Al,
    const __nv_bfloat16* __restrict__ Bh, const __nv_bfloat16* __restrict__ Bl,
    float* __restrict__ outF, __nv_bfloat16* __restrict__ outH,
    __nv_bfloat16* __restrict__ outL, __half* __restrict__ outV, int mode)
{
    extern __shared__ __align__(16) char dsm[];
    const uint32_t base = smem_u32(dsm);
    const int tid = threadIdx.x, lane = tid & 31, wid = tid >> 5;
    const int warpM = wid & 1, warpN = wid >> 1;
    const int m0 = blockIdx.y * 128, n0 = blockIdx.x * 128;

    const __nv_bfloat16* Ahp = Ah + (size_t)m0 * DM;
    const __nv_bfloat16* Alp = Al + (size_t)m0 * DM;
    const __nv_bfloat16* Bhp = Bh + (size_t)n0 * DM;
    const __nv_bfloat16* Blp = Bl + (size_t)n0 * DM;

    const int lrow = tid >> 2;
    const int lu   = tid & 3;

    auto issue = [&](int kc, int st) {
        uint32_t sb = base + st * STG_BYTES;
#pragma unroll
        for (int t = 0; t < 2; ++t) {
            int row = lrow + t * 64;
            uint32_t d = sb + row * ROWB + lu * 16;
            size_t  go = (size_t)row * DM + kc + lu * 8;
            cp16(d,              Ahp + go);
            cp16(d + OFF_AL * 2, Alp + go);
            cp16(d + OFF_BH * 2, Bhp + go);
            cp16(d + OFF_BL * 2, Blp + go);
        }
        cp_commit();
    };

    float acc[4][4][4];
#pragma unroll
    for (int i = 0; i < 4; ++i)
#pragma unroll
        for (int j = 0; j < 4; ++j)
#pragma unroll
            for (int r = 0; r < 4; ++r) acc[i][j][r] = 0.f;

    issue(0, 0);
    issue(KCH, 1);

    const uint32_t aRow = (uint32_t)(warpM * 64 + (lane & 15));
    const uint32_t aCol = (uint32_t)(((lane >> 4) & 1) * 16);
    const uint32_t bRow = (uint32_t)(warpN * 32 + (lane & 7));
    const uint32_t bCol = (uint32_t)(((lane >> 3) & 1) * 16);

    for (int kt = 0; kt < NKT; ++kt) {
        int st = kt % 3;
        if (kt + 2 < NKT) issue((kt + 2) * KCH, (kt + 2) % 3);
        else cp_commit();
        cp_wait<2>();
        __syncthreads();

        uint32_t sb = base + st * STG_BYTES;
#pragma unroll
        for (int s = 0; s < 2; ++s) {
            uint32_t ah[4][4], al[4][4], bh[4][2], bl[4][2];
#pragma unroll
            for (int i = 0; i < 4; ++i) {
                uint32_t a = sb + (aRow + i * 16) * ROWB + s * 32 + aCol;
                ldm_x4(a,              ah[i][0], ah[i][1], ah[i][2], ah[i][3]);
                ldm_x4(a + OFF_AL * 2, al[i][0], al[i][1], al[i][2], al[i][3]);
            }
#pragma unroll
            for (int j = 0; j < 4; ++j) {
                uint32_t b = sb + (bRow + j * 8) * ROWB + s * 32 + bCol;
                ldm_x2(b + OFF_BH * 2, bh[j][0], bh[j][1]);
                ldm_x2(b + OFF_BL * 2, bl[j][0], bl[j][1]);
            }
#pragma unroll
            for (int i = 0; i < 4; ++i)
#pragma unroll
                for (int j = 0; j < 4; ++j) {
                    mma16816(acc[i][j], ah[i], bh[j]);
                    mma16816(acc[i][j], ah[i], bl[j]);
                    mma16816(acc[i][j], al[i], bh[j]);
                }
        }
        __syncthreads();
    }

#pragma unroll
    for (int i = 0; i < 4; ++i) {
        int mA = m0 + warpM * 64 + i * 16 + (lane >> 2);
        int mB = mA + 8;
#pragma unroll
        for (int j = 0; j < 4; ++j) {
            int n = n0 + warpN * 32 + j * 8 + ((lane & 3) << 1);
            if (mode == 0) {
                *(float2*)(outF + (size_t)mA * DM + n) = make_float2(acc[i][j][0], acc[i][j][1]);
                *(float2*)(outF + (size_t)mB * DM + n) = make_float2(acc[i][j][2], acc[i][j][3]);
            } else {
                int hh = n >> 6, dd = n & 63;
                int bA = mA >> 11, sA = mA & (S_LEN - 1);
                int bB = mB >> 11, sB = mB & (S_LEN - 1);
                size_t oA = ((size_t)(bA * NH + hh) * S_LEN + sA) * DK + dd;
                size_t oB = ((size_t)(bB * NH + hh) * S_LEN + sB) * DK + dd;
                if (mode == 1) {
                    uint32_t h0, l0, h1, l1;
                    pksplit(acc[i][j][0], acc[i][j][1], h0, l0);
                    pksplit(acc[i][j][2], acc[i][j][3], h1, l1);
                    *(uint32_t*)(outH + oA) = h0; *(uint32_t*)(outL + oA) = l0;
                    *(uint32_t*)(outH + oB) = h1; *(uint32_t*)(outL + oB) = l1;
                } else {
                    __half2 v0 = __floats2half2_rn(acc[i][j][0], acc[i][j][1]);
                    __half2 v1 = __floats2half2_rn(acc[i][j][2], acc[i][j][3]);
                    *(uint32_t*)(outV + oA) = *(uint32_t*)&v0;
                    *(uint32_t*)(outV + oB) = *(uint32_t*)&v1;
                }
            }
        }
    }
}

// ---------------- HMMA flash attention (QK split-bf16, PV fp16) ----------------
__device__ __forceinline__ int t5_bucket(int delta)
{
    int base = (delta > 0) ? 16 : 0;
    int a = delta < 0 ? -delta : delta;
    int bucket;
    if (a < 8) bucket = a;
    else if (a >= 128) bucket = 15;
    else {
        int t = 31 - __clz(a);
        int f = (a * a >= (1 << (2 * t + 1))) ? 1 : 0;
        bucket = 2 + 2 * t + f;
        if (bucket > 15) bucket = 15;
    }
    return base + bucket;
}

#define PQ        144
#define A_QH      0
#define A_QL      18432
#define A_BUF     36864
#define A_BUFSZ   27648                  // KH, KL, V (64 rows x 144 B each)
#define A_KH      0
#define A_KL      9216
#define A_V       18432
#define A_BIAS    (A_BUF + 2*A_BUFSZ)    // 92160
#define ATT_SMEM  (A_BIAS + 1152)        // 93312

__global__ __launch_bounds__(256, 2) void attn_mma(
    const __nv_bfloat16* __restrict__ qh, const __nv_bfloat16* __restrict__ ql,
    const __nv_bfloat16* __restrict__ kh, const __nv_bfloat16* __restrict__ kl,
    const __half* __restrict__ vf, const float* __restrict__ rel_bias,
    __nv_bfloat16* __restrict__ chi, __nv_bfloat16* __restrict__ clo)
{
    extern __shared__ __align__(16) char asmem[];
    const uint32_t base = smem_u32(asmem);
    float* bias = (float*)(asmem + A_BIAS);

    const int tid = threadIdx.x, lane = tid & 31, wid = tid >> 5;
    const int bh = blockIdx.y;
    const int hd = bh & (NH - 1);
    const int b  = bh >> 4;
    const int q0 = blockIdx.x * 128;
    const size_t bo = (size_t)bh * S_LEN * DK;

    for (int i = tid; i < 257; i += 256)
        bias[i] = rel_bias[t5_bucket(i - 128) * NH + hd];

#pragma unroll
    for (int it = 0; it < 8; ++it) {
        int idx = tid + it * 256;
        int sub = idx & 1023, row = sub >> 3, u = sub & 7;
        const __nv_bfloat16* src = (it < 4) ? qh : ql;
        cp16(base + (it < 4 ? A_QH : A_QL) + row * PQ + u * 16,
             src + bo + (size_t)(q0 + row) * DK + u * 8);
    }
    auto issue_kv = [&](int t, int buf) {
        uint32_t bb = base + A_BUF + buf * A_BUFSZ;
#pragma unroll
        for (int it = 0; it < 6; ++it) {
            int idx = tid + it * 256;
            int sub = idx & 511, row = sub >> 3, u = sub & 7;
            if (it < 4) {
                const __nv_bfloat16* src = (it < 2) ? kh : kl;
                uint32_t toff = (it < 2) ? A_KH : A_KL;
                cp16(bb + toff + row * PQ + u * 16,
                     src + bo + (size_t)(t * 64 + row) * DK + u * 8);
            } else {
                cp16(bb + A_V + row * PQ + u * 16,
                     vf + bo + (size_t)(t * 64 + row) * DK + u * 8);
            }
        }
        cp_commit();
    };
    issue_kv(0, 0);
    issue_kv(1, 1);

    const int g  = lane >> 2;
    const int tc = lane & 3;
    const int qg0 = q0 + wid * 16 + g;
    const int qg1 = qg0 + 8;

    float acc_o[8][4];
#pragma unroll
    for (int j = 0; j < 8; ++j)
#pragma unroll
        for (int r = 0; r < 4; ++r) acc_o[j][r] = 0.f;
    float m0 = -1e30f, m1 = -1e30f, l0 = 0.f, l1 = 0.f;

    const uint32_t aBase = base + (wid * 16 + (lane & 15)) * PQ + ((lane >> 4) & 1) * 16;
    const uint32_t bRowSel = ((lane >> 4) & 1) * 8 + (lane & 7);
    const uint32_t bColSel = ((lane >> 3) & 1) * 16;
    const uint32_t vRowSel = ((lane >> 3) & 1) * 8 + (lane & 7);
    const uint32_t vColSel = ((lane >> 4) & 1) * 16;

    for (int t = 0; t < 32; ++t) {
        if (t + 2 < 32) cp_wait<1>(); else cp_wait<0>();
        __syncthreads();
        uint32_t kb = base + A_BUF + (t & 1) * A_BUFSZ;

        // ---- S = Q K^T (split-bf16, 3 mma) ----
        float s[8][4];
#pragma unroll
        for (int j = 0; j < 8; ++j)
#pragma unroll
            for (int r = 0; r < 4; ++r) s[j][r] = 0.f;

#pragma unroll
        for (int ks = 0; ks < 4; ++ks) {
            uint32_t ah[4], al[4];
            ldm_x4(aBase + ks * 32,        ah[0], ah[1], ah[2], ah[3]);
            ldm_x4(aBase + A_QL + ks * 32, al[0], al[1], al[2], al[3]);
#pragma unroll
            for (int nb2 = 0; nb2 < 4; ++nb2) {
                uint32_t bAddr = kb + A_KH + (nb2 * 16 + bRowSel) * PQ + bColSel + ks * 32;
                uint32_t h0, h1, h2, h3, u0, u1, u2, u3;
                ldm_x4(bAddr,        h0, h1, h2, h3);
                ldm_x4(bAddr + A_KL - A_KH, u0, u1, u2, u3);
                uint32_t bh0[2] = {h0, h1}, bh1[2] = {h2, h3};
                uint32_t bl0[2] = {u0, u1}, bl1[2] = {u2, u3};
                mma16816(s[2*nb2],   ah, bh0); mma16816(s[2*nb2],   ah, bl0);
                mma16816(s[2*nb2],   al, bh0);
                mma16816(s[2*nb2+1], ah, bh1); mma16816(s[2*nb2+1], ah, bl1);
                mma16816(s[2*nb2+1], al, bh1);
            }
        }

        // ---- bias + online softmax ----
        int ktb = t * 64;
        float rm0 = -1e30f, rm1 = -1e30f;
#pragma unroll
        for (int nb = 0; nb < 8; ++nb) {
            int kg = ktb + nb * 8 + tc * 2;
            int d00 = kg - qg0, d10 = kg - qg1;
            int i00 = min(max(d00,     -128), 128) + 128;
            int i01 = min(max(d00 + 1, -128), 128) + 128;
            int i10 = min(max(d10,     -128), 128) + 128;
            int i11 = min(max(d10 + 1, -128), 128) + 128;
            s[nb][0] += bias[i00]; s[nb][1] += bias[i01];
            s[nb][2] += bias[i10]; s[nb][3] += bias[i11];
            rm0 = fmaxf(rm0, fmaxf(s[nb][0], s[nb][1]));
            rm1 = fmaxf(rm1, fmaxf(s[nb][2], s[nb][3]));
        }
        rm0 = fmaxf(rm0, __shfl_xor_sync(0xffffffffu, rm0, 1));
        rm0 = fmaxf(rm0, __shfl_xor_sync(0xffffffffu, rm0, 2));
        rm1 = fmaxf(rm1, __shfl_xor_sync(0xffffffffu, rm1, 1));
        rm1 = fmaxf(rm1, __shfl_xor_sync(0xffffffffu, rm1, 2));

        float mn0 = fmaxf(m0, rm0), mn1 = fmaxf(m1, rm1);
        float c0 = __expf(m0 - mn0), c1 = __expf(m1 - mn1);
        m0 = mn0; m1 = mn1;

        float ps0 = 0.f, ps1 = 0.f;
#pragma unroll
        for (int nb = 0; nb < 8; ++nb) {
            s[nb][0] = __expf(s[nb][0] - mn0); s[nb][1] = __expf(s[nb][1] - mn0);
            s[nb][2] = __expf(s[nb][2] - mn1); s[nb][3] = __expf(s[nb][3] - mn1);
            ps0 += s[nb][0] + s[nb][1];
            ps1 += s[nb][2] + s[nb][3];
        }
        ps0 += __shfl_xor_sync(0xffffffffu, ps0, 1);
        ps0 += __shfl_xor_sync(0xffffffffu, ps0, 2);
        ps1 += __shfl_xor_sync(0xffffffffu, ps1, 1);
        ps1 += __shfl_xor_sync(0xffffffffu, ps1, 2);
        l0 = l0 * c0 + ps0; l1 = l1 * c1 + ps1;

#pragma unroll
        for (int j = 0; j < 8; ++j) {
            acc_o[j][0] *= c0; acc_o[j][1] *= c0;
            acc_o[j][2] *= c1; acc_o[j][3] *= c1;
        }

        // ---- O += P V (single fp16 mma) ----
#pragma unroll
        for (int ks = 0; ks < 4; ++ks) {
            uint32_t ap[4];
            __half2 p0 = __floats2half2_rn(s[2*ks][0],   s[2*ks][1]);
            __half2 p1 = __floats2half2_rn(s[2*ks][2],   s[2*ks][3]);
            __half2 p2 = __floats2half2_rn(s[2*ks+1][0], s[2*ks+1][1]);
            __half2 p3 = __floats2half2_rn(s[2*ks+1][2], s[2*ks+1][3]);
            ap[0] = *(uint32_t*)&p0; ap[1] = *(uint32_t*)&p1;
            ap[2] = *(uint32_t*)&p2; ap[3] = *(uint32_t*)&p3;
#pragma unroll
            for (int db2 = 0; db2 < 4; ++db2) {
                uint32_t vAddr = kb + A_V + (ks * 16 + vRowSel) * PQ + db2 * 32 + vColSel;
                uint32_t h0, h1, h2, h3;
                ldm_x4t(vAddr, h0, h1, h2, h3);
                uint32_t v0[2] = {h0, h1}, v1[2] = {h2, h3};
                mma16816h(acc_o[2*db2],   ap, v0);
                mma16816h(acc_o[2*db2+1], ap, v1);
            }
        }
        __syncthreads();
        if (t + 2 < 32) issue_kv(t + 2, t & 1);
    }

    // ---- epilogue ----
    float inv0 = 1.f / l0, inv1 = 1.f / l1;
#pragma unroll
    for (int db = 0; db < 8; ++db) {
        int dcol = hd * DK + db * 8 + tc * 2;
        size_t o0 = ((size_t)b * S_LEN + qg0) * DM + dcol;
        size_t o1 = ((size_t)b * S_LEN + qg1) * DM + dcol;
        uint32_t h0, lo0, h1, lo1;
        pksplit(acc_o[db][0] * inv0, acc_o[db][1] * inv0, h0, lo0);
        pksplit(acc_o[db][2] * inv1, acc_o[db][3] * inv1, h1, lo1);
        *(uint32_t*)(chi + o0) = h0; *(uint32_t*)(clo + o0) = lo0;
        *(uint32_t*)(chi + o1) = h1; *(uint32_t*)(clo + o1) = lo1;
    }
}

// ---------------------------------------------------------------------------
extern "C" void kernel_launch(void* const* d_in, const int* in_sizes, int n_in,
                              void* d_out, int out_size)
{
    const float* hidden  = (const float*)d_in[0];
    const float* wq      = (const float*)d_in[1];
    const float* wk      = (const float*)d_in[2];
    const float* wv      = (const float*)d_in[3];
    const float* wo      = (const float*)d_in[4];
    const float* relbias = (const float*)d_in[5];
    float* out = (float*)d_out;

    __nv_bfloat16 *hhi, *hlo, *whi, *wlo, *chi, *clo;
    __nv_bfloat16 *qh, *ql, *kh, *kl;
    __half *vf;
    cudaGetSymbolAddress((void**)&hhi, g_h_hi);
    cudaGetSymbolAddress((void**)&hlo, g_h_lo);
    cudaGetSymbolAddress((void**)&whi, g_wt_hi);
    cudaGetSymbolAddress((void**)&wlo, g_wt_lo);
    cudaGetSymbolAddress((void**)&qh,  g_qh);
    cudaGetSymbolAddress((void**)&ql,  g_ql);
    cudaGetSymbolAddress((void**)&kh,  g_kh);
    cudaGetSymbolAddress((void**)&kl,  g_kl);
    cudaGetSymbolAddress((void**)&vf,  g_vf);
    cudaGetSymbolAddress((void**)&chi, g_ctx_hi);
    cudaGetSymbolAddress((void**)&clo, g_ctx_lo);

    cudaFuncSetAttribute(gemm_hmma, cudaFuncAttributeMaxDynamicSharedMemorySize, GEMM_SMEM);
    cudaFuncSetAttribute(attn_mma,  cudaFuncAttributeMaxDynamicSharedMemorySize, ATT_SMEM);

    split_hidden<<<MT * DM / 1024, 256>>>((const float4*)hidden, hhi, hlo);
    transpose_split<<<dim3(32, 32, 4), dim3(32, 8)>>>(wq, wk, wv, wo, whi, wlo);

    dim3 gG(DM / 128, MT / 128);
    const size_t WSZ = (size_t)DM * DM;
    gemm_hmma<<<gG, 256, GEMM_SMEM>>>(hhi, hlo, whi + 0*WSZ, wlo + 0*WSZ,
                                      nullptr, qh, ql, nullptr, 1);
    gemm_hmma<<<gG, 256, GEMM_SMEM>>>(hhi, hlo, whi + 1*WSZ, wlo + 1*WSZ,
                                      nullptr, kh, kl, nullptr, 1);
    gemm_hmma<<<gG, 256, GEMM_SMEM>>>(hhi, hlo, whi + 2*WSZ, wlo + 2*WSZ,
                                      nullptr, nullptr, nullptr, vf, 2);

    dim3 gA(S_LEN / 128, BATCH * NH);
    attn_mma<<<gA, 256, ATT_SMEM>>>(qh, ql, kh, kl, vf, relbias, chi, clo);

    gemm_hmma<<<gG, 256, GEMM_SMEM>>>(chi, clo, whi + 3*WSZ, wlo + 3*WSZ,
                                      out, nullptr, nullptr, nullptr, 0);
}

// round 8
// speedup vs baseline: 3.4225x; 1.0258x over previous
#include <cuda_runtime.h>
#include <cuda_bf16.h>
#include <cuda_fp16.h>
#include <cstdint>

#define BATCH 4
#define S_LEN 2048
#define NH    16
#define DK    64
#define DM    1024
#define MT    (BATCH*S_LEN)
#define BHSZ  ((size_t)BATCH * NH * S_LEN * DK)

__device__ __nv_bfloat16 g_h_hi[MT * DM];
__device__ __nv_bfloat16 g_h_lo[MT * DM];
__device__ __nv_bfloat16 g_wt_hi[4 * DM * DM];
__device__ __nv_bfloat16 g_wt_lo[4 * DM * DM];
__device__ __nv_bfloat16 g_qh[BHSZ], g_ql[BHSZ];
__device__ __nv_bfloat16 g_kh[BHSZ], g_kl[BHSZ];
__device__ __half        g_vf[BHSZ];
__device__ __nv_bfloat16 g_ctx_hi[MT * DM];
__device__ __nv_bfloat16 g_ctx_lo[MT * DM];

// ---------------- helpers ----------------
__device__ __forceinline__ uint32_t smem_u32(const void* p) {
    uint32_t a;
    asm("{ .reg .u64 t; cvta.to.shared.u64 t, %1; cvt.u32.u64 %0, t; }" : "=r"(a) : "l"(p));
    return a;
}
__device__ __forceinline__ void cp16(uint32_t dst, const void* src) {
    asm volatile("cp.async.cg.shared.global [%0], [%1], 16;" :: "r"(dst), "l"(src));
}
__device__ __forceinline__ void cp_commit() { asm volatile("cp.async.commit_group;" ::: "memory"); }
template<int N> __device__ __forceinline__ void cp_wait() {
    asm volatile("cp.async.wait_group %0;" :: "n"(N) : "memory");
}
__device__ __forceinline__ void ldm_x4(uint32_t a, uint32_t& r0, uint32_t& r1,
                                       uint32_t& r2, uint32_t& r3) {
    asm volatile("ldmatrix.sync.aligned.m8n8.x4.shared.b16 {%0,%1,%2,%3}, [%4];"
                 : "=r"(r0), "=r"(r1), "=r"(r2), "=r"(r3) : "r"(a));
}
__device__ __forceinline__ void ldm_x4t(uint32_t a, uint32_t& r0, uint32_t& r1,
                                        uint32_t& r2, uint32_t& r3) {
    asm volatile("ldmatrix.sync.aligned.m8n8.x4.trans.shared.b16 {%0,%1,%2,%3}, [%4];"
                 : "=r"(r0), "=r"(r1), "=r"(r2), "=r"(r3) : "r"(a));
}
__device__ __forceinline__ void ldm_x2(uint32_t a, uint32_t& r0, uint32_t& r1) {
    asm volatile("ldmatrix.sync.aligned.m8n8.x2.shared.b16 {%0,%1}, [%2];"
                 : "=r"(r0), "=r"(r1) : "r"(a));
}
__device__ __forceinline__ void mma16816(float* c, const uint32_t* a, const uint32_t* b) {
    asm volatile("mma.sync.aligned.m16n8k16.row.col.f32.bf16.bf16.f32 "
                 "{%0,%1,%2,%3},{%4,%5,%6,%7},{%8,%9},{%0,%1,%2,%3};"
                 : "+f"(c[0]), "+f"(c[1]), "+f"(c[2]), "+f"(c[3])
                 : "r"(a[0]), "r"(a[1]), "r"(a[2]), "r"(a[3]), "r"(b[0]), "r"(b[1]));
}
__device__ __forceinline__ void mma16816h(float* c, const uint32_t* a, const uint32_t* b) {
    asm volatile("mma.sync.aligned.m16n8k16.row.col.f32.f16.f16.f32 "
                 "{%0,%1,%2,%3},{%4,%5,%6,%7},{%8,%9},{%0,%1,%2,%3};"
                 : "+f"(c[0]), "+f"(c[1]), "+f"(c[2]), "+f"(c[3])
                 : "r"(a[0]), "r"(a[1]), "r"(a[2]), "r"(a[3]), "r"(b[0]), "r"(b[1]));
}
__device__ __forceinline__ void pksplit(float x, float y, uint32_t& hi, uint32_t& lo) {
    __nv_bfloat162 h = __floats2bfloat162_rn(x, y);
    __nv_bfloat162 l = __floats2bfloat162_rn(x - __bfloat162float(h.x),
                                             y - __bfloat162float(h.y));
    hi = *(uint32_t*)&h; lo = *(uint32_t*)&l;
}

// ---------------- prep ----------------
__global__ void split_hidden(const float4* __restrict__ in,
                             __nv_bfloat16* __restrict__ hi, __nv_bfloat16* __restrict__ lo)
{
    int i = blockIdx.x * 256 + threadIdx.x;
    float4 v = in[i];
    float f[4] = {v.x, v.y, v.z, v.w};
    __nv_bfloat16 h4[4], l4[4];
#pragma unroll
    for (int j = 0; j < 4; ++j) {
        h4[j] = __float2bfloat16(f[j]);
        l4[j] = __float2bfloat16(f[j] - __bfloat162float(h4[j]));
    }
    *(uint2*)(hi + (size_t)i * 4) = *(uint2*)h4;
    *(uint2*)(lo + (size_t)i * 4) = *(uint2*)l4;
}

__global__ void transpose_split(const float* __restrict__ w0, const float* __restrict__ w1,
                                const float* __restrict__ w2, const float* __restrict__ w3,
                                __nv_bfloat16* __restrict__ ohi, __nv_bfloat16* __restrict__ olo)
{
    __shared__ float t[32][33];
    const float* w = blockIdx.z == 0 ? w0 : blockIdx.z == 1 ? w1 : blockIdx.z == 2 ? w2 : w3;
    size_t zoff = (size_t)blockIdx.z * DM * DM;
    int x0 = blockIdx.x * 32, y0 = blockIdx.y * 32;
    for (int i = threadIdx.y; i < 32; i += 8)
        t[i][threadIdx.x] = w[(size_t)(y0 + i) * DM + x0 + threadIdx.x];
    __syncthreads();
    for (int i = threadIdx.y; i < 32; i += 8) {
        float v = t[threadIdx.x][i];
        __nv_bfloat16 hb = __float2bfloat16(v);
        __nv_bfloat16 lb = __float2bfloat16(v - __bfloat162float(hb));
        size_t o = zoff + (size_t)(x0 + i) * DM + y0 + threadIdx.x;
        ohi[o] = hb; olo[o] = lb;
    }
}

// ---------------- HMMA split-bf16 GEMM (3-stage, occ 1) ----------------
// mode 0: fp32 row-major. mode 1: fused QKV head-major (q,k bf16 pair; v fp16).
#define KCH   32
#define NKT   (DM / KCH)
#define ROWB  80
#define OFF_AL (128 * 40)
#define OFF_BH (2 * 128 * 40)
#define OFF_BL (3 * 128 * 40)
#define STG_BYTES (4 * 128 * 40 * 2)
#define GEMM_SMEM (3 * STG_BYTES)

__global__ __launch_bounds__(256, 1) void gemm_hmma(
    const __nv_bfloat16* __restrict__ Ah, const __nv_bfloat16* __restrict__ Al,
    const __nv_bfloat16* __restrict__ Bh, const __nv_bfloat16* __restrict__ Bl,
    float* __restrict__ outF,
    __nv_bfloat16* __restrict__ qh, __nv_bfloat16* __restrict__ ql,
    __nv_bfloat16* __restrict__ kh, __nv_bfloat16* __restrict__ kl,
    __half* __restrict__ vf, int mode)
{
    extern __shared__ __align__(16) char dsm[];
    const uint32_t base = smem_u32(dsm);
    const int tid = threadIdx.x, lane = tid & 31, wid = tid >> 5;
    const int warpM = wid & 1, warpN = wid >> 1;
    const int m0 = blockIdx.y * 128, n0 = blockIdx.x * 128;

    const __nv_bfloat16* Ahp = Ah + (size_t)m0 * DM;
    const __nv_bfloat16* Alp = Al + (size_t)m0 * DM;
    const __nv_bfloat16* Bhp = Bh + (size_t)n0 * DM;
    const __nv_bfloat16* Blp = Bl + (size_t)n0 * DM;

    const int lrow = tid >> 2;
    const int lu   = tid & 3;

    auto issue = [&](int kc, int st) {
        uint32_t sb = base + st * STG_BYTES;
#pragma unroll
        for (int t = 0; t < 2; ++t) {
            int row = lrow + t * 64;
            uint32_t d = sb + row * ROWB + lu * 16;
            size_t  go = (size_t)row * DM + kc + lu * 8;
            cp16(d,              Ahp + go);
            cp16(d + OFF_AL * 2, Alp + go);
            cp16(d + OFF_BH * 2, Bhp + go);
            cp16(d + OFF_BL * 2, Blp + go);
        }
        cp_commit();
    };

    float acc[4][4][4];
#pragma unroll
    for (int i = 0; i < 4; ++i)
#pragma unroll
        for (int j = 0; j < 4; ++j)
#pragma unroll
            for (int r = 0; r < 4; ++r) acc[i][j][r] = 0.f;

    issue(0, 0);
    issue(KCH, 1);

    const uint32_t aRow = (uint32_t)(warpM * 64 + (lane & 15));
    const uint32_t aCol = (uint32_t)(((lane >> 4) & 1) * 16);
    const uint32_t bRow = (uint32_t)(warpN * 32 + (lane & 7));
    const uint32_t bCol = (uint32_t)(((lane >> 3) & 1) * 16);

    for (int kt = 0; kt < NKT; ++kt) {
        int st = kt % 3;
        if (kt + 2 < NKT) issue((kt + 2) * KCH, (kt + 2) % 3);
        else cp_commit();
        cp_wait<2>();
        __syncthreads();

        uint32_t sb = base + st * STG_BYTES;
#pragma unroll
        for (int s = 0; s < 2; ++s) {
            uint32_t ah[4][4], al[4][4], bh[4][2], bl[4][2];
#pragma unroll
            for (int i = 0; i < 4; ++i) {
                uint32_t a = sb + (aRow + i * 16) * ROWB + s * 32 + aCol;
                ldm_x4(a,              ah[i][0], ah[i][1], ah[i][2], ah[i][3]);
                ldm_x4(a + OFF_AL * 2, al[i][0], al[i][1], al[i][2], al[i][3]);
            }
#pragma unroll
            for (int j = 0; j < 4; ++j) {
                uint32_t b = sb + (bRow + j * 8) * ROWB + s * 32 + bCol;
                ldm_x2(b + OFF_BH * 2, bh[j][0], bh[j][1]);
                ldm_x2(b + OFF_BL * 2, bl[j][0], bl[j][1]);
            }
#pragma unroll
            for (int i = 0; i < 4; ++i)
#pragma unroll
                for (int j = 0; j < 4; ++j) {
                    mma16816(acc[i][j], ah[i], bh[j]);
                    mma16816(acc[i][j], ah[i], bl[j]);
                    mma16816(acc[i][j], al[i], bh[j]);
                }
        }
        __syncthreads();
    }

    const int which = n0 >> 10;    // 0=q, 1=k, 2=v (fused QKV mode)
    __nv_bfloat16* oH = (which == 0) ? qh : kh;
    __nv_bfloat16* oL = (which == 0) ? ql : kl;

#pragma unroll
    for (int i = 0; i < 4; ++i) {
        int mA = m0 + warpM * 64 + i * 16 + (lane >> 2);
        int mB = mA + 8;
#pragma unroll
        for (int j = 0; j < 4; ++j) {
            int n = n0 + warpN * 32 + j * 8 + ((lane & 3) << 1);
            if (mode == 0) {
                *(float2*)(outF + (size_t)mA * DM + n) = make_float2(acc[i][j][0], acc[i][j][1]);
                *(float2*)(outF + (size_t)mB * DM + n) = make_float2(acc[i][j][2], acc[i][j][3]);
            } else {
                int nn = n & 1023;
                int hh = nn >> 6, dd = nn & 63;
                int bA = mA >> 11, sA = mA & (S_LEN - 1);
                int bB = mB >> 11, sB = mB & (S_LEN - 1);
                size_t oA = ((size_t)(bA * NH + hh) * S_LEN + sA) * DK + dd;
                size_t oB = ((size_t)(bB * NH + hh) * S_LEN + sB) * DK + dd;
                if (which == 2) {
                    __half2 v0 = __floats2half2_rn(acc[i][j][0], acc[i][j][1]);
                    __half2 v1 = __floats2half2_rn(acc[i][j][2], acc[i][j][3]);
                    *(uint32_t*)(vf + oA) = *(uint32_t*)&v0;
                    *(uint32_t*)(vf + oB) = *(uint32_t*)&v1;
                } else {
                    uint32_t h0, l0, h1, l1;
                    pksplit(acc[i][j][0], acc[i][j][1], h0, l0);
                    pksplit(acc[i][j][2], acc[i][j][3], h1, l1);
                    *(uint32_t*)(oH + oA) = h0; *(uint32_t*)(oL + oA) = l0;
                    *(uint32_t*)(oH + oB) = h1; *(uint32_t*)(oL + oB) = l1;
                }
            }
        }
    }
}

// ---------------- HMMA flash attention (4 warps, 32 q-rows/warp, occ 2) ----------------
__device__ __forceinline__ int t5_bucket(int delta)
{
    int base = (delta > 0) ? 16 : 0;
    int a = delta < 0 ? -delta : delta;
    int bucket;
    if (a < 8) bucket = a;
    else if (a >= 128) bucket = 15;
    else {
        int t = 31 - __clz(a);
        int f = (a * a >= (1 << (2 * t + 1))) ? 1 : 0;
        bucket = 2 + 2 * t + f;
        if (bucket > 15) bucket = 15;
    }
    return base + bucket;
}

#define PQ        144
#define A_QH      0
#define A_QL      18432
#define A_BUF     36864
#define A_BUFSZ   27648
#define A_KH      0
#define A_KL      9216
#define A_V       18432
#define A_BIAS    (A_BUF + 2*A_BUFSZ)
#define ATT_SMEM  (A_BIAS + 1152)

__global__ __launch_bounds__(128, 2) void attn_mma(
    const __nv_bfloat16* __restrict__ qh, const __nv_bfloat16* __restrict__ ql,
    const __nv_bfloat16* __restrict__ kh, const __nv_bfloat16* __restrict__ kl,
    const __half* __restrict__ vf, const float* __restrict__ rel_bias,
    __nv_bfloat16* __restrict__ chi, __nv_bfloat16* __restrict__ clo)
{
    extern __shared__ __align__(16) char asmem[];
    const uint32_t base = smem_u32(asmem);
    float* bias = (float*)(asmem + A_BIAS);

    const int tid = threadIdx.x, lane = tid & 31, wid = tid >> 5;   // 4 warps
    const int bh = blockIdx.y;
    const int hd = bh & (NH - 1);
    const int b  = bh >> 4;
    const int q0 = blockIdx.x * 128;
    const size_t bo = (size_t)bh * S_LEN * DK;

    for (int i = tid; i < 257; i += 128)
        bias[i] = rel_bias[t5_bucket(i - 128) * NH + hd];

    // Q tile (hi+lo): 128 rows x 64, 2048 cp16 over 128 threads
#pragma unroll
    for (int it = 0; it < 16; ++it) {
        int idx = tid + it * 128;
        int sub = idx & 1023, row = sub >> 3, u = sub & 7;
        const __nv_bfloat16* src = (it < 8) ? qh : ql;
        cp16(base + (it < 8 ? A_QH : A_QL) + row * PQ + u * 16,
             src + bo + (size_t)(q0 + row) * DK + u * 8);
    }
    auto issue_kv = [&](int t, int buf) {
        uint32_t bb = base + A_BUF + buf * A_BUFSZ;
#pragma unroll
        for (int it = 0; it < 12; ++it) {
            int idx = tid + it * 128;
            int sub = idx & 511, row = sub >> 3, u = sub & 7;
            if (it < 8) {
                const __nv_bfloat16* src = (it < 4) ? kh : kl;
                uint32_t toff = (it < 4) ? A_KH : A_KL;
                cp16(bb + toff + row * PQ + u * 16,
                     src + bo + (size_t)(t * 64 + row) * DK + u * 8);
            } else {
                cp16(bb + A_V + row * PQ + u * 16,
                     vf + bo + (size_t)(t * 64 + row) * DK + u * 8);
            }
        }
        cp_commit();
    };
    issue_kv(0, 0);
    issue_kv(1, 1);

    const int g  = lane >> 2;
    const int tc = lane & 3;
    int qg[2][2];
#pragma unroll
    for (int i = 0; i < 2; ++i) {
        qg[i][0] = q0 + wid * 32 + i * 16 + g;
        qg[i][1] = qg[i][0] + 8;
    }

    float acc_o[2][8][4];
#pragma unroll
    for (int i = 0; i < 2; ++i)
#pragma unroll
        for (int j = 0; j < 8; ++j)
#pragma unroll
            for (int r = 0; r < 4; ++r) acc_o[i][j][r] = 0.f;
    float mx[2][2] = {{-1e30f, -1e30f}, {-1e30f, -1e30f}};
    float ls[2][2] = {{0.f, 0.f}, {0.f, 0.f}};

    const uint32_t aBase = base + (wid * 32 + (lane & 15)) * PQ + ((lane >> 4) & 1) * 16;
    const uint32_t bRowSel = ((lane >> 4) & 1) * 8 + (lane & 7);
    const uint32_t bColSel = ((lane >> 3) & 1) * 16;
    const uint32_t vRowSel = ((lane >> 3) & 1) * 8 + (lane & 7);
    const uint32_t vColSel = ((lane >> 4) & 1) * 16;

    for (int t = 0; t < 32; ++t) {
        if (t + 2 < 32) cp_wait<1>(); else cp_wait<0>();
        __syncthreads();
        uint32_t kb = base + A_BUF + (t & 1) * A_BUFSZ;

        // ---- S = Q K^T (split-bf16, 3 mma), two 16-row tiles per warp ----
        float s[2][8][4];
#pragma unroll
        for (int i = 0; i < 2; ++i)
#pragma unroll
            for (int j = 0; j < 8; ++j)
#pragma unroll
                for (int r = 0; r < 4; ++r) s[i][j][r] = 0.f;

#pragma unroll
        for (int ks = 0; ks < 4; ++ks) {
            uint32_t qhf[2][4], qlf[2][4];
#pragma unroll
            for (int i = 0; i < 2; ++i) {
                uint32_t a = aBase + i * (16 * PQ) + ks * 32;
                ldm_x4(a,        qhf[i][0], qhf[i][1], qhf[i][2], qhf[i][3]);
                ldm_x4(a + A_QL, qlf[i][0], qlf[i][1], qlf[i][2], qlf[i][3]);
            }
#pragma unroll
            for (int nb2 = 0; nb2 < 4; ++nb2) {
                uint32_t bAddr = kb + A_KH + (nb2 * 16 + bRowSel) * PQ + bColSel + ks * 32;
                uint32_t h0, h1, h2, h3, u0, u1, u2, u3;
                ldm_x4(bAddr,                 h0, h1, h2, h3);
                ldm_x4(bAddr + (A_KL - A_KH), u0, u1, u2, u3);
                uint32_t bh0[2] = {h0, h1}, bh1[2] = {h2, h3};
                uint32_t bl0[2] = {u0, u1}, bl1[2] = {u2, u3};
#pragma unroll
                for (int i = 0; i < 2; ++i) {
                    mma16816(s[i][2*nb2],   qhf[i], bh0); mma16816(s[i][2*nb2],   qhf[i], bl0);
                    mma16816(s[i][2*nb2],   qlf[i], bh0);
                    mma16816(s[i][2*nb2+1], qhf[i], bh1); mma16816(s[i][2*nb2+1], qhf[i], bl1);
                    mma16816(s[i][2*nb2+1], qlf[i], bh1);
                }
            }
        }

        // ---- bias + online softmax ----
        int ktb = t * 64;
#pragma unroll
        for (int i = 0; i < 2; ++i) {
            float rm0 = -1e30f, rm1 = -1e30f;
#pragma unroll
            for (int nb = 0; nb < 8; ++nb) {
                int kg = ktb + nb * 8 + tc * 2;
                int d00 = kg - qg[i][0], d10 = kg - qg[i][1];
                int i00 = min(max(d00,     -128), 128) + 128;
                int i01 = min(max(d00 + 1, -128), 128) + 128;
                int i10 = min(max(d10,     -128), 128) + 128;
                int i11 = min(max(d10 + 1, -128), 128) + 128;
                s[i][nb][0] += bias[i00]; s[i][nb][1] += bias[i01];
                s[i][nb][2] += bias[i10]; s[i][nb][3] += bias[i11];
                rm0 = fmaxf(rm0, fmaxf(s[i][nb][0], s[i][nb][1]));
                rm1 = fmaxf(rm1, fmaxf(s[i][nb][2], s[i][nb][3]));
            }
            rm0 = fmaxf(rm0, __shfl_xor_sync(0xffffffffu, rm0, 1));
            rm0 = fmaxf(rm0, __shfl_xor_sync(0xffffffffu, rm0, 2));
            rm1 = fmaxf(rm1, __shfl_xor_sync(0xffffffffu, rm1, 1));
            rm1 = fmaxf(rm1, __shfl_xor_sync(0xffffffffu, rm1, 2));

            float mn0 = fmaxf(mx[i][0], rm0), mn1 = fmaxf(mx[i][1], rm1);
            float c0 = __expf(mx[i][0] - mn0), c1 = __expf(mx[i][1] - mn1);
            mx[i][0] = mn0; mx[i][1] = mn1;

            float ps0 = 0.f, ps1 = 0.f;
#pragma unroll
            for (int nb = 0; nb < 8; ++nb) {
                s[i][nb][0] = __expf(s[i][nb][0] - mn0);
                s[i][nb][1] = __expf(s[i][nb][1] - mn0);
                s[i][nb][2] = __expf(s[i][nb][2] - mn1);
                s[i][nb][3] = __expf(s[i][nb][3] - mn1);
                ps0 += s[i][nb][0] + s[i][nb][1];
                ps1 += s[i][nb][2] + s[i][nb][3];
            }
            ps0 += __shfl_xor_sync(0xffffffffu, ps0, 1);
            ps0 += __shfl_xor_sync(0xffffffffu, ps0, 2);
            ps1 += __shfl_xor_sync(0xffffffffu, ps1, 1);
            ps1 += __shfl_xor_sync(0xffffffffu, ps1, 2);
            ls[i][0] = ls[i][0] * c0 + ps0;
            ls[i][1] = ls[i][1] * c1 + ps1;
#pragma unroll
            for (int j = 0; j < 8; ++j) {
                acc_o[i][j][0] *= c0; acc_o[i][j][1] *= c0;
                acc_o[i][j][2] *= c1; acc_o[i][j][3] *= c1;
            }
        }

        // ---- O += P V (fp16 mma, V frags shared across i) ----
#pragma unroll
        for (int ks = 0; ks < 4; ++ks) {
            uint32_t ap[2][4];
#pragma unroll
            for (int i = 0; i < 2; ++i) {
                __half2 p0 = __floats2half2_rn(s[i][2*ks][0],   s[i][2*ks][1]);
                __half2 p1 = __floats2half2_rn(s[i][2*ks][2],   s[i][2*ks][3]);
                __half2 p2 = __floats2half2_rn(s[i][2*ks+1][0], s[i][2*ks+1][1]);
                __half2 p3 = __floats2half2_rn(s[i][2*ks+1][2], s[i][2*ks+1][3]);
                ap[i][0] = *(uint32_t*)&p0; ap[i][1] = *(uint32_t*)&p1;
                ap[i][2] = *(uint32_t*)&p2; ap[i][3] = *(uint32_t*)&p3;
            }
#pragma unroll
            for (int db2 = 0; db2 < 4; ++db2) {
                uint32_t vAddr = kb + A_V + (ks * 16 + vRowSel) * PQ + db2 * 32 + vColSel;
                uint32_t h0, h1, h2, h3;
                ldm_x4t(vAddr, h0, h1, h2, h3);
                uint32_t v0[2] = {h0, h1}, v1[2] = {h2, h3};
#pragma unroll
                for (int i = 0; i < 2; ++i) {
                    mma16816h(acc_o[i][2*db2],   ap[i], v0);
                    mma16816h(acc_o[i][2*db2+1], ap[i], v1);
                }
            }
        }
        __syncthreads();
        if (t + 2 < 32) issue_kv(t + 2, t & 1);
    }

    // ---- epilogue ----
#pragma unroll
    for (int i = 0; i < 2; ++i) {
        float inv0 = 1.f / ls[i][0], inv1 = 1.f / ls[i][1];
#pragma unroll
        for (int db = 0; db < 8; ++db) {
            int dcol = hd * DK + db * 8 + tc * 2;
            size_t o0 = ((size_t)b * S_LEN + qg[i][0]) * DM + dcol;
            size_t o1 = ((size_t)b * S_LEN + qg[i][1]) * DM + dcol;
            uint32_t h0, lo0, h1, lo1;
            pksplit(acc_o[i][db][0] * inv0, acc_o[i][db][1] * inv0, h0, lo0);
            pksplit(acc_o[i][db][2] * inv1, acc_o[i][db][3] * inv1, h1, lo1);
            *(uint32_t*)(chi + o0) = h0; *(uint32_t*)(clo + o0) = lo0;
            *(uint32_t*)(chi + o1) = h1; *(uint32_t*)(clo + o1) = lo1;
        }
    }
}

// ---------------------------------------------------------------------------
extern "C" void kernel_launch(void* const* d_in, const int* in_sizes, int n_in,
                              void* d_out, int out_size)
{
    const float* hidden  = (const float*)d_in[0];
    const float* wq      = (const float*)d_in[1];
    const float* wk      = (const float*)d_in[2];
    const float* wv      = (const float*)d_in[3];
    const float* wo      = (const float*)d_in[4];
    const float* relbias = (const float*)d_in[5];
    float* out = (float*)d_out;

    __nv_bfloat16 *hhi, *hlo, *whi, *wlo, *chi, *clo;
    __nv_bfloat16 *qh, *ql, *kh, *kl;
    __half *vf;
    cudaGetSymbolAddress((void**)&hhi, g_h_hi);
    cudaGetSymbolAddress((void**)&hlo, g_h_lo);
    cudaGetSymbolAddress((void**)&whi, g_wt_hi);
    cudaGetSymbolAddress((void**)&wlo, g_wt_lo);
    cudaGetSymbolAddress((void**)&qh,  g_qh);
    cudaGetSymbolAddress((void**)&ql,  g_ql);
    cudaGetSymbolAddress((void**)&kh,  g_kh);
    cudaGetSymbolAddress((void**)&kl,  g_kl);
    cudaGetSymbolAddress((void**)&vf,  g_vf);
    cudaGetSymbolAddress((void**)&chi, g_ctx_hi);
    cudaGetSymbolAddress((void**)&clo, g_ctx_lo);

    cudaFuncSetAttribute(gemm_hmma, cudaFuncAttributeMaxDynamicSharedMemorySize, GEMM_SMEM);
    cudaFuncSetAttribute(attn_mma,  cudaFuncAttributeMaxDynamicSharedMemorySize, ATT_SMEM);

    split_hidden<<<MT * DM / 1024, 256>>>((const float4*)hidden, hhi, hlo);
    transpose_split<<<dim3(32, 32, 4), dim3(32, 8)>>>(wq, wk, wv, wo, whi, wlo);

    const size_t WSZ = (size_t)DM * DM;
    // Fused QKV: N = 3072 over contiguous wq|wk|wv transposed weights
    gemm_hmma<<<dim3(24, 64), 256, GEMM_SMEM>>>(hhi, hlo, whi, wlo,
                                                nullptr, qh, ql, kh, kl, vf, 1);

    attn_mma<<<dim3(16, 64), 128, ATT_SMEM>>>(qh, ql, kh, kl, vf, relbias, chi, clo);

    gemm_hmma<<<dim3(8, 64), 256, GEMM_SMEM>>>(chi, clo, whi + 3*WSZ, wlo + 3*WSZ,
                                               out, nullptr, nullptr, nullptr, nullptr,
                                               nullptr, 0);
}

// round 9
// speedup vs baseline: 3.5076x; 1.0249x over previous
#include <cuda_runtime.h>
#include <cuda_bf16.h>
#include <cuda_fp16.h>
#include <cstdint>

#define BATCH 4
#define S_LEN 2048
#define NH    16
#define DK    64
#define DM    1024
#define MT    (BATCH*S_LEN)
#define BHSZ  ((size_t)BATCH * NH * S_LEN * DK)

__device__ __nv_bfloat16 g_h_hi[MT * DM];
__device__ __nv_bfloat16 g_h_lo[MT * DM];
__device__ __nv_bfloat16 g_wt_hi[4 * DM * DM];
__device__ __nv_bfloat16 g_wt_lo[4 * DM * DM];
__device__ __nv_bfloat16 g_qh[BHSZ], g_ql[BHSZ];
__device__ __nv_bfloat16 g_kh[BHSZ], g_kl[BHSZ];
__device__ __half        g_vf[BHSZ];
__device__ __nv_bfloat16 g_ctx_hi[MT * DM];
__device__ __nv_bfloat16 g_ctx_lo[MT * DM];

// ---------------- helpers ----------------
__device__ __forceinline__ uint32_t smem_u32(const void* p) {
    uint32_t a;
    asm("{ .reg .u64 t; cvta.to.shared.u64 t, %1; cvt.u32.u64 %0, t; }" : "=r"(a) : "l"(p));
    return a;
}
__device__ __forceinline__ void cp16(uint32_t dst, const void* src) {
    asm volatile("cp.async.cg.shared.global [%0], [%1], 16;" :: "r"(dst), "l"(src));
}
__device__ __forceinline__ void cp_commit() { asm volatile("cp.async.commit_group;" ::: "memory"); }
template<int N> __device__ __forceinline__ void cp_wait() {
    asm volatile("cp.async.wait_group %0;" :: "n"(N) : "memory");
}
__device__ __forceinline__ void ldm_x4(uint32_t a, uint32_t& r0, uint32_t& r1,
                                       uint32_t& r2, uint32_t& r3) {
    asm volatile("ldmatrix.sync.aligned.m8n8.x4.shared.b16 {%0,%1,%2,%3}, [%4];"
                 : "=r"(r0), "=r"(r1), "=r"(r2), "=r"(r3) : "r"(a));
}
__device__ __forceinline__ void ldm_x4t(uint32_t a, uint32_t& r0, uint32_t& r1,
                                        uint32_t& r2, uint32_t& r3) {
    asm volatile("ldmatrix.sync.aligned.m8n8.x4.trans.shared.b16 {%0,%1,%2,%3}, [%4];"
                 : "=r"(r0), "=r"(r1), "=r"(r2), "=r"(r3) : "r"(a));
}
__device__ __forceinline__ void ldm_x2(uint32_t a, uint32_t& r0, uint32_t& r1) {
    asm volatile("ldmatrix.sync.aligned.m8n8.x2.shared.b16 {%0,%1}, [%2];"
                 : "=r"(r0), "=r"(r1) : "r"(a));
}
__device__ __forceinline__ void mma16816(float* c, const uint32_t* a, const uint32_t* b) {
    asm volatile("mma.sync.aligned.m16n8k16.row.col.f32.bf16.bf16.f32 "
                 "{%0,%1,%2,%3},{%4,%5,%6,%7},{%8,%9},{%0,%1,%2,%3};"
                 : "+f"(c[0]), "+f"(c[1]), "+f"(c[2]), "+f"(c[3])
                 : "r"(a[0]), "r"(a[1]), "r"(a[2]), "r"(a[3]), "r"(b[0]), "r"(b[1]));
}
__device__ __forceinline__ void mma16816h(float* c, const uint32_t* a, const uint32_t* b) {
    asm volatile("mma.sync.aligned.m16n8k16.row.col.f32.f16.f16.f32 "
                 "{%0,%1,%2,%3},{%4,%5,%6,%7},{%8,%9},{%0,%1,%2,%3};"
                 : "+f"(c[0]), "+f"(c[1]), "+f"(c[2]), "+f"(c[3])
                 : "r"(a[0]), "r"(a[1]), "r"(a[2]), "r"(a[3]), "r"(b[0]), "r"(b[1]));
}
__device__ __forceinline__ void pksplit(float x, float y, uint32_t& hi, uint32_t& lo) {
    __nv_bfloat162 h = __floats2bfloat162_rn(x, y);
    __nv_bfloat162 l = __floats2bfloat162_rn(x - __bfloat162float(h.x),
                                             y - __bfloat162float(h.y));
    hi = *(uint32_t*)&h; lo = *(uint32_t*)&l;
}

// ---------------- prep ----------------
__global__ void split_hidden(const float4* __restrict__ in,
                             __nv_bfloat16* __restrict__ hi, __nv_bfloat16* __restrict__ lo)
{
    int i = blockIdx.x * 256 + threadIdx.x;
    float4 v = in[i];
    float f[4] = {v.x, v.y, v.z, v.w};
    __nv_bfloat16 h4[4], l4[4];
#pragma unroll
    for (int j = 0; j < 4; ++j) {
        h4[j] = __float2bfloat16(f[j]);
        l4[j] = __float2bfloat16(f[j] - __bfloat162float(h4[j]));
    }
    *(uint2*)(hi + (size_t)i * 4) = *(uint2*)h4;
    *(uint2*)(lo + (size_t)i * 4) = *(uint2*)l4;
}

__global__ void transpose_split(const float* __restrict__ w0, const float* __restrict__ w1,
                                const float* __restrict__ w2, const float* __restrict__ w3,
                                __nv_bfloat16* __restrict__ ohi, __nv_bfloat16* __restrict__ olo)
{
    __shared__ float t[32][33];
    const float* w = blockIdx.z == 0 ? w0 : blockIdx.z == 1 ? w1 : blockIdx.z == 2 ? w2 : w3;
    size_t zoff = (size_t)blockIdx.z * DM * DM;
    int x0 = blockIdx.x * 32, y0 = blockIdx.y * 32;
    for (int i = threadIdx.y; i < 32; i += 8)
        t[i][threadIdx.x] = w[(size_t)(y0 + i) * DM + x0 + threadIdx.x];
    __syncthreads();
    for (int i = threadIdx.y; i < 32; i += 8) {
        float v = t[threadIdx.x][i];
        __nv_bfloat16 hb = __float2bfloat16(v);
        __nv_bfloat16 lb = __float2bfloat16(v - __bfloat162float(hb));
        size_t o = zoff + (size_t)(x0 + i) * DM + y0 + threadIdx.x;
        ohi[o] = hb; olo[o] = lb;
    }
}

// ---------------- HMMA split-bf16 GEMM (3-stage, occ 1) ----------------
// mode 0: fp32 row-major. mode 1: fused QKV head-major (q,k bf16 pair; v fp16).
#define KCH   32
#define NKT   (DM / KCH)
#define ROWB  80
#define OFF_AL (128 * 40)
#define OFF_BH (2 * 128 * 40)
#define OFF_BL (3 * 128 * 40)
#define STG_BYTES (4 * 128 * 40 * 2)
#define GEMM_SMEM (3 * STG_BYTES)

__global__ __launch_bounds__(256, 1) void gemm_hmma(
    const __nv_bfloat16* __restrict__ Ah, const __nv_bfloat16* __restrict__ Al,
    const __nv_bfloat16* __restrict__ Bh, const __nv_bfloat16* __restrict__ Bl,
    float* __restrict__ outF,
    __nv_bfloat16* __restrict__ qh, __nv_bfloat16* __restrict__ ql,
    __nv_bfloat16* __restrict__ kh, __nv_bfloat16* __restrict__ kl,
    __half* __restrict__ vf, int mode)
{
    extern __shared__ __align__(16) char dsm[];
    const uint32_t base = smem_u32(dsm);
    const int tid = threadIdx.x, lane = tid & 31, wid = tid >> 5;
    const int warpM = wid & 1, warpN = wid >> 1;
    const int m0 = blockIdx.y * 128, n0 = blockIdx.x * 128;

    const __nv_bfloat16* Ahp = Ah + (size_t)m0 * DM;
    const __nv_bfloat16* Alp = Al + (size_t)m0 * DM;
    const __nv_bfloat16* Bhp = Bh + (size_t)n0 * DM;
    const __nv_bfloat16* Blp = Bl + (size_t)n0 * DM;

    const int lrow = tid >> 2;
    const int lu   = tid & 3;

    auto issue = [&](int kc, int st) {
        uint32_t sb = base + st * STG_BYTES;
#pragma unroll
        for (int t = 0; t < 2; ++t) {
            int row = lrow + t * 64;
            uint32_t d = sb + row * ROWB + lu * 16;
            size_t  go = (size_t)row * DM + kc + lu * 8;
            cp16(d,              Ahp + go);
            cp16(d + OFF_AL * 2, Alp + go);
            cp16(d + OFF_BH * 2, Bhp + go);
            cp16(d + OFF_BL * 2, Blp + go);
        }
        cp_commit();
    };

    float acc[4][4][4];
#pragma unroll
    for (int i = 0; i < 4; ++i)
#pragma unroll
        for (int j = 0; j < 4; ++j)
#pragma unroll
            for (int r = 0; r < 4; ++r) acc[i][j][r] = 0.f;

    issue(0, 0);
    issue(KCH, 1);

    const uint32_t aRow = (uint32_t)(warpM * 64 + (lane & 15));
    const uint32_t aCol = (uint32_t)(((lane >> 4) & 1) * 16);
    const uint32_t bRow = (uint32_t)(warpN * 32 + (lane & 7));
    const uint32_t bCol = (uint32_t)(((lane >> 3) & 1) * 16);

    for (int kt = 0; kt < NKT; ++kt) {
        int st = kt % 3;
        if (kt + 2 < NKT) issue((kt + 2) * KCH, (kt + 2) % 3);
        else cp_commit();
        cp_wait<2>();
        __syncthreads();

        uint32_t sb = base + st * STG_BYTES;
#pragma unroll
        for (int s = 0; s < 2; ++s) {
            uint32_t ah[4][4], al[4][4], bh[4][2], bl[4][2];
#pragma unroll
            for (int i = 0; i < 4; ++i) {
                uint32_t a = sb + (aRow + i * 16) * ROWB + s * 32 + aCol;
                ldm_x4(a,              ah[i][0], ah[i][1], ah[i][2], ah[i][3]);
                ldm_x4(a + OFF_AL * 2, al[i][0], al[i][1], al[i][2], al[i][3]);
            }
#pragma unroll
            for (int j = 0; j < 4; ++j) {
                uint32_t b = sb + (bRow + j * 8) * ROWB + s * 32 + bCol;
                ldm_x2(b + OFF_BH * 2, bh[j][0], bh[j][1]);
                ldm_x2(b + OFF_BL * 2, bl[j][0], bl[j][1]);
            }
#pragma unroll
            for (int i = 0; i < 4; ++i)
#pragma unroll
                for (int j = 0; j < 4; ++j) {
                    mma16816(acc[i][j], ah[i], bh[j]);
                    mma16816(acc[i][j], ah[i], bl[j]);
                    mma16816(acc[i][j], al[i], bh[j]);
                }
        }
        __syncthreads();
    }

    const int which = n0 >> 10;    // 0=q, 1=k, 2=v (fused QKV mode)
    __nv_bfloat16* oH = (which == 0) ? qh : kh;
    __nv_bfloat16* oL = (which == 0) ? ql : kl;

#pragma unroll
    for (int i = 0; i < 4; ++i) {
        int mA = m0 + warpM * 64 + i * 16 + (lane >> 2);
        int mB = mA + 8;
#pragma unroll
        for (int j = 0; j < 4; ++j) {
            int n = n0 + warpN * 32 + j * 8 + ((lane & 3) << 1);
            if (mode == 0) {
                *(float2*)(outF + (size_t)mA * DM + n) = make_float2(acc[i][j][0], acc[i][j][1]);
                *(float2*)(outF + (size_t)mB * DM + n) = make_float2(acc[i][j][2], acc[i][j][3]);
            } else {
                int nn = n & 1023;
                int hh = nn >> 6, dd = nn & 63;
                int bA = mA >> 11, sA = mA & (S_LEN - 1);
                int bB = mB >> 11, sB = mB & (S_LEN - 1);
                size_t oA = ((size_t)(bA * NH + hh) * S_LEN + sA) * DK + dd;
                size_t oB = ((size_t)(bB * NH + hh) * S_LEN + sB) * DK + dd;
                if (which == 2) {
                    __half2 v0 = __floats2half2_rn(acc[i][j][0], acc[i][j][1]);
                    __half2 v1 = __floats2half2_rn(acc[i][j][2], acc[i][j][3]);
                    *(uint32_t*)(vf + oA) = *(uint32_t*)&v0;
                    *(uint32_t*)(vf + oB) = *(uint32_t*)&v1;
                } else {
                    uint32_t h0, l0, h1, l1;
                    pksplit(acc[i][j][0], acc[i][j][1], h0, l0);
                    pksplit(acc[i][j][2], acc[i][j][3], h1, l1);
                    *(uint32_t*)(oH + oA) = h0; *(uint32_t*)(oL + oA) = l0;
                    *(uint32_t*)(oH + oB) = h1; *(uint32_t*)(oL + oB) = l1;
                }
            }
        }
    }
}

// ---------------- HMMA flash attention (8 warps, 16 q-rows/warp, occ 2) ----------------
__device__ __forceinline__ int t5_bucket(int delta)
{
    int base = (delta > 0) ? 16 : 0;
    int a = delta < 0 ? -delta : delta;
    int bucket;
    if (a < 8) bucket = a;
    else if (a >= 128) bucket = 15;
    else {
        int t = 31 - __clz(a);
        int f = (a * a >= (1 << (2 * t + 1))) ? 1 : 0;
        bucket = 2 + 2 * t + f;
        if (bucket > 15) bucket = 15;
    }
    return base + bucket;
}

#define PQ        144
#define A_QH      0
#define A_QL      18432
#define A_BUF     36864
#define A_BUFSZ   27648                  // KH, KL, V (64 rows x 144 B each)
#define A_KH      0
#define A_KL      9216
#define A_V       18432
#define A_BIAS    (A_BUF + 2*A_BUFSZ)
#define ATT_SMEM  (A_BIAS + 1152)

__global__ __launch_bounds__(256, 2) void attn_mma(
    const __nv_bfloat16* __restrict__ qh, const __nv_bfloat16* __restrict__ ql,
    const __nv_bfloat16* __restrict__ kh, const __nv_bfloat16* __restrict__ kl,
    const __half* __restrict__ vf, const float* __restrict__ rel_bias,
    __nv_bfloat16* __restrict__ chi, __nv_bfloat16* __restrict__ clo)
{
    extern __shared__ __align__(16) char asmem[];
    const uint32_t base = smem_u32(asmem);
    float* bias = (float*)(asmem + A_BIAS);

    const int tid = threadIdx.x, lane = tid & 31, wid = tid >> 5;
    const int bh = blockIdx.y;
    const int hd = bh & (NH - 1);
    const int b  = bh >> 4;
    const int q0 = blockIdx.x * 128;
    const size_t bo = (size_t)bh * S_LEN * DK;

    for (int i = tid; i < 257; i += 256)
        bias[i] = rel_bias[t5_bucket(i - 128) * NH + hd];

#pragma unroll
    for (int it = 0; it < 8; ++it) {
        int idx = tid + it * 256;
        int sub = idx & 1023, row = sub >> 3, u = sub & 7;
        const __nv_bfloat16* src = (it < 4) ? qh : ql;
        cp16(base + (it < 4 ? A_QH : A_QL) + row * PQ + u * 16,
             src + bo + (size_t)(q0 + row) * DK + u * 8);
    }
    auto issue_kv = [&](int t, int buf) {
        uint32_t bb = base + A_BUF + buf * A_BUFSZ;
#pragma unroll
        for (int it = 0; it < 6; ++it) {
            int idx = tid + it * 256;
            int sub = idx & 511, row = sub >> 3, u = sub & 7;
            if (it < 4) {
                const __nv_bfloat16* src = (it < 2) ? kh : kl;
                uint32_t toff = (it < 2) ? A_KH : A_KL;
                cp16(bb + toff + row * PQ + u * 16,
                     src + bo + (size_t)(t * 64 + row) * DK + u * 8);
            } else {
                cp16(bb + A_V + row * PQ + u * 16,
                     vf + bo + (size_t)(t * 64 + row) * DK + u * 8);
            }
        }
        cp_commit();
    };
    issue_kv(0, 0);
    issue_kv(1, 1);

    const int g  = lane >> 2;
    const int tc = lane & 3;
    const int qg0 = q0 + wid * 16 + g;
    const int qg1 = qg0 + 8;

    float acc_o[8][4];
#pragma unroll
    for (int j = 0; j < 8; ++j)
#pragma unroll
        for (int r = 0; r < 4; ++r) acc_o[j][r] = 0.f;
    float m0 = -1e30f, m1 = -1e30f, l0 = 0.f, l1 = 0.f;

    const uint32_t aBase = base + (wid * 16 + (lane & 15)) * PQ + ((lane >> 4) & 1) * 16;
    const uint32_t bRowSel = ((lane >> 4) & 1) * 8 + (lane & 7);
    const uint32_t bColSel = ((lane >> 3) & 1) * 16;
    const uint32_t vRowSel = ((lane >> 3) & 1) * 8 + (lane & 7);
    const uint32_t vColSel = ((lane >> 4) & 1) * 16;

    for (int t = 0; t < 32; ++t) {
        if (t + 2 < 32) cp_wait<1>(); else cp_wait<0>();
        __syncthreads();
        uint32_t kb = base + A_BUF + (t & 1) * A_BUFSZ;

        // ---- S = Q K^T (split-bf16, 3 mma) ----
        float s[8][4];
#pragma unroll
        for (int j = 0; j < 8; ++j)
#pragma unroll
            for (int r = 0; r < 4; ++r) s[j][r] = 0.f;

#pragma unroll
        for (int ks = 0; ks < 4; ++ks) {
            uint32_t ah[4], al[4];
            ldm_x4(aBase + ks * 32,        ah[0], ah[1], ah[2], ah[3]);
            ldm_x4(aBase + A_QL + ks * 32, al[0], al[1], al[2], al[3]);
#pragma unroll
            for (int nb2 = 0; nb2 < 4; ++nb2) {
                uint32_t bAddr = kb + A_KH + (nb2 * 16 + bRowSel) * PQ + bColSel + ks * 32;
                uint32_t h0, h1, h2, h3, u0, u1, u2, u3;
                ldm_x4(bAddr,                 h0, h1, h2, h3);
                ldm_x4(bAddr + (A_KL - A_KH), u0, u1, u2, u3);
                uint32_t bh0[2] = {h0, h1}, bh1[2] = {h2, h3};
                uint32_t bl0[2] = {u0, u1}, bl1[2] = {u2, u3};
                mma16816(s[2*nb2],   ah, bh0); mma16816(s[2*nb2],   ah, bl0);
                mma16816(s[2*nb2],   al, bh0);
                mma16816(s[2*nb2+1], ah, bh1); mma16816(s[2*nb2+1], ah, bl1);
                mma16816(s[2*nb2+1], al, bh1);
            }
        }

        // ---- bias + online softmax ----
        int ktb = t * 64;
        float rm0 = -1e30f, rm1 = -1e30f;
#pragma unroll
        for (int nb = 0; nb < 8; ++nb) {
            int kg = ktb + nb * 8 + tc * 2;
            int d00 = kg - qg0, d10 = kg - qg1;
            int i00 = min(max(d00,     -128), 128) + 128;
            int i01 = min(max(d00 + 1, -128), 128) + 128;
            int i10 = min(max(d10,     -128), 128) + 128;
            int i11 = min(max(d10 + 1, -128), 128) + 128;
            s[nb][0] += bias[i00]; s[nb][1] += bias[i01];
            s[nb][2] += bias[i10]; s[nb][3] += bias[i11];
            rm0 = fmaxf(rm0, fmaxf(s[nb][0], s[nb][1]));
            rm1 = fmaxf(rm1, fmaxf(s[nb][2], s[nb][3]));
        }
        rm0 = fmaxf(rm0, __shfl_xor_sync(0xffffffffu, rm0, 1));
        rm0 = fmaxf(rm0, __shfl_xor_sync(0xffffffffu, rm0, 2));
        rm1 = fmaxf(rm1, __shfl_xor_sync(0xffffffffu, rm1, 1));
        rm1 = fmaxf(rm1, __shfl_xor_sync(0xffffffffu, rm1, 2));

        float mn0 = fmaxf(m0, rm0), mn1 = fmaxf(m1, rm1);
        float c0 = __expf(m0 - mn0), c1 = __expf(m1 - mn1);
        m0 = mn0; m1 = mn1;

        float ps0 = 0.f, ps1 = 0.f;
#pragma unroll
        for (int nb = 0; nb < 8; ++nb) {
            s[nb][0] = __expf(s[nb][0] - mn0); s[nb][1] = __expf(s[nb][1] - mn0);
            s[nb][2] = __expf(s[nb][2] - mn1); s[nb][3] = __expf(s[nb][3] - mn1);
            ps0 += s[nb][0] + s[nb][1];
            ps1 += s[nb][2] + s[nb][3];
        }
        ps0 += __shfl_xor_sync(0xffffffffu, ps0, 1);
        ps0 += __shfl_xor_sync(0xffffffffu, ps0, 2);
        ps1 += __shfl_xor_sync(0xffffffffu, ps1, 1);
        ps1 += __shfl_xor_sync(0xffffffffu, ps1, 2);
        l0 = l0 * c0 + ps0; l1 = l1 * c1 + ps1;

#pragma unroll
        for (int j = 0; j < 8; ++j) {
            acc_o[j][0] *= c0; acc_o[j][1] *= c0;
            acc_o[j][2] *= c1; acc_o[j][3] *= c1;
        }

        // ---- O += P V (single fp16 mma) ----
#pragma unroll
        for (int ks = 0; ks < 4; ++ks) {
            uint32_t ap[4];
            __half2 p0 = __floats2half2_rn(s[2*ks][0],   s[2*ks][1]);
            __half2 p1 = __floats2half2_rn(s[2*ks][2],   s[2*ks][3]);
            __half2 p2 = __floats2half2_rn(s[2*ks+1][0], s[2*ks+1][1]);
            __half2 p3 = __floats2half2_rn(s[2*ks+1][2], s[2*ks+1][3]);
            ap[0] = *(uint32_t*)&p0; ap[1] = *(uint32_t*)&p1;
            ap[2] = *(uint32_t*)&p2; ap[3] = *(uint32_t*)&p3;
#pragma unroll
            for (int db2 = 0; db2 < 4; ++db2) {
                uint32_t vAddr = kb + A_V + (ks * 16 + vRowSel) * PQ + db2 * 32 + vColSel;
                uint32_t h0, h1, h2, h3;
                ldm_x4t(vAddr, h0, h1, h2, h3);
                uint32_t v0[2] = {h0, h1}, v1[2] = {h2, h3};
                mma16816h(acc_o[2*db2],   ap, v0);
                mma16816h(acc_o[2*db2+1], ap, v1);
            }
        }
        __syncthreads();
        if (t + 2 < 32) issue_kv(t + 2, t & 1);
    }

    // ---- epilogue ----
    float inv0 = 1.f / l0, inv1 = 1.f / l1;
#pragma unroll
    for (int db = 0; db < 8; ++db) {
        int dcol = hd * DK + db * 8 + tc * 2;
        size_t o0 = ((size_t)b * S_LEN + qg0) * DM + dcol;
        size_t o1 = ((size_t)b * S_LEN + qg1) * DM + dcol;
        uint32_t h0, lo0, h1, lo1;
        pksplit(acc_o[db][0] * inv0, acc_o[db][1] * inv0, h0, lo0);
        pksplit(acc_o[db][2] * inv1, acc_o[db][3] * inv1, h1, lo1);
        *(uint32_t*)(chi + o0) = h0; *(uint32_t*)(clo + o0) = lo0;
        *(uint32_t*)(chi + o1) = h1; *(uint32_t*)(clo + o1) = lo1;
    }
}

// ---------------------------------------------------------------------------
extern "C" void kernel_launch(void* const* d_in, const int* in_sizes, int n_in,
                              void* d_out, int out_size)
{
    const float* hidden  = (const float*)d_in[0];
    const float* wq      = (const float*)d_in[1];
    const float* wk      = (const float*)d_in[2];
    const float* wv      = (const float*)d_in[3];
    const float* wo      = (const float*)d_in[4];
    const float* relbias = (const float*)d_in[5];
    float* out = (float*)d_out;

    __nv_bfloat16 *hhi, *hlo, *whi, *wlo, *chi, *clo;
    __nv_bfloat16 *qh, *ql, *kh, *kl;
    __half *vf;
    cudaGetSymbolAddress((void**)&hhi, g_h_hi);
    cudaGetSymbolAddress((void**)&hlo, g_h_lo);
    cudaGetSymbolAddress((void**)&whi, g_wt_hi);
    cudaGetSymbolAddress((void**)&wlo, g_wt_lo);
    cudaGetSymbolAddress((void**)&qh,  g_qh);
    cudaGetSymbolAddress((void**)&ql,  g_ql);
    cudaGetSymbolAddress((void**)&kh,  g_kh);
    cudaGetSymbolAddress((void**)&kl,  g_kl);
    cudaGetSymbolAddress((void**)&vf,  g_vf);
    cudaGetSymbolAddress((void**)&chi, g_ctx_hi);
    cudaGetSymbolAddress((void**)&clo, g_ctx_lo);

    cudaFuncSetAttribute(gemm_hmma, cudaFuncAttributeMaxDynamicSharedMemorySize, GEMM_SMEM);
    cudaFuncSetAttribute(attn_mma,  cudaFuncAttributeMaxDynamicSharedMemorySize, ATT_SMEM);

    split_hidden<<<MT * DM / 1024, 256>>>((const float4*)hidden, hhi, hlo);
    transpose_split<<<dim3(32, 32, 4), dim3(32, 8)>>>(wq, wk, wv, wo, whi, wlo);

    const size_t WSZ = (size_t)DM * DM;
    // Fused QKV: N = 3072 over contiguous wq|wk|wv transposed weights
    gemm_hmma<<<dim3(24, 64), 256, GEMM_SMEM>>>(hhi, hlo, whi, wlo,
                                                nullptr, qh, ql, kh, kl, vf, 1);

    attn_mma<<<dim3(16, 64), 256, ATT_SMEM>>>(qh, ql, kh, kl, vf, relbias, chi, clo);

    gemm_hmma<<<dim3(8, 64), 256, GEMM_SMEM>>>(chi, clo, whi + 3*WSZ, wlo + 3*WSZ,
                                               out, nullptr, nullptr, nullptr, nullptr,
                                               nullptr, 0);
}

// round 10
// speedup vs baseline: 3.8345x; 1.0932x over previous
#include <cuda_runtime.h>
#include <cuda_bf16.h>
#include <cuda_fp16.h>
#include <cstdint>

#define BATCH 4
#define S_LEN 2048
#define NH    16
#define DK    64
#define DM    1024
#define MT    (BATCH*S_LEN)
#define BHSZ  ((size_t)BATCH * NH * S_LEN * DK)

__device__ __nv_bfloat16 g_h_hi[MT * DM];
__device__ __nv_bfloat16 g_h_lo[MT * DM];
__device__ __nv_bfloat16 g_wt_hi[3 * DM * DM];   // wq|wk|wv transposed, bf16 split
__device__ __nv_bfloat16 g_wt_lo[3 * DM * DM];
__device__ __half        g_wo_hi[DM * DM];       // wo transposed, fp16 split
__device__ __half        g_wo_lo[DM * DM];
__device__ __nv_bfloat16 g_qh[BHSZ], g_ql[BHSZ];
__device__ __nv_bfloat16 g_kh[BHSZ], g_kl[BHSZ];
__device__ __half        g_vf[BHSZ];
__device__ __half        g_ctx[MT * DM];         // ctx fp16 single

// ---------------- helpers ----------------
__device__ __forceinline__ uint32_t smem_u32(const void* p) {
    uint32_t a;
    asm("{ .reg .u64 t; cvta.to.shared.u64 t, %1; cvt.u32.u64 %0, t; }" : "=r"(a) : "l"(p));
    return a;
}
__device__ __forceinline__ void cp16(uint32_t dst, const void* src) {
    asm volatile("cp.async.cg.shared.global [%0], [%1], 16;" :: "r"(dst), "l"(src));
}
__device__ __forceinline__ void cp_commit() { asm volatile("cp.async.commit_group;" ::: "memory"); }
template<int N> __device__ __forceinline__ void cp_wait() {
    asm volatile("cp.async.wait_group %0;" :: "n"(N) : "memory");
}
__device__ __forceinline__ void ldm_x4(uint32_t a, uint32_t& r0, uint32_t& r1,
                                       uint32_t& r2, uint32_t& r3) {
    asm volatile("ldmatrix.sync.aligned.m8n8.x4.shared.b16 {%0,%1,%2,%3}, [%4];"
                 : "=r"(r0), "=r"(r1), "=r"(r2), "=r"(r3) : "r"(a));
}
__device__ __forceinline__ void ldm_x4t(uint32_t a, uint32_t& r0, uint32_t& r1,
                                        uint32_t& r2, uint32_t& r3) {
    asm volatile("ldmatrix.sync.aligned.m8n8.x4.trans.shared.b16 {%0,%1,%2,%3}, [%4];"
                 : "=r"(r0), "=r"(r1), "=r"(r2), "=r"(r3) : "r"(a));
}
__device__ __forceinline__ void ldm_x2(uint32_t a, uint32_t& r0, uint32_t& r1) {
    asm volatile("ldmatrix.sync.aligned.m8n8.x2.shared.b16 {%0,%1}, [%2];"
                 : "=r"(r0), "=r"(r1) : "r"(a));
}
__device__ __forceinline__ void mma16816(float* c, const uint32_t* a, const uint32_t* b) {
    asm volatile("mma.sync.aligned.m16n8k16.row.col.f32.bf16.bf16.f32 "
                 "{%0,%1,%2,%3},{%4,%5,%6,%7},{%8,%9},{%0,%1,%2,%3};"
                 : "+f"(c[0]), "+f"(c[1]), "+f"(c[2]), "+f"(c[3])
                 : "r"(a[0]), "r"(a[1]), "r"(a[2]), "r"(a[3]), "r"(b[0]), "r"(b[1]));
}
__device__ __forceinline__ void mma16816h(float* c, const uint32_t* a, const uint32_t* b) {
    asm volatile("mma.sync.aligned.m16n8k16.row.col.f32.f16.f16.f32 "
                 "{%0,%1,%2,%3},{%4,%5,%6,%7},{%8,%9},{%0,%1,%2,%3};"
                 : "+f"(c[0]), "+f"(c[1]), "+f"(c[2]), "+f"(c[3])
                 : "r"(a[0]), "r"(a[1]), "r"(a[2]), "r"(a[3]), "r"(b[0]), "r"(b[1]));
}
__device__ __forceinline__ void pksplit(float x, float y, uint32_t& hi, uint32_t& lo) {
    __nv_bfloat162 h = __floats2bfloat162_rn(x, y);
    __nv_bfloat162 l = __floats2bfloat162_rn(x - __bfloat162float(h.x),
                                             y - __bfloat162float(h.y));
    hi = *(uint32_t*)&h; lo = *(uint32_t*)&l;
}

// ---------------- prep ----------------
__global__ void split_hidden(const float4* __restrict__ in,
                             __nv_bfloat16* __restrict__ hi, __nv_bfloat16* __restrict__ lo)
{
    int i = blockIdx.x * 256 + threadIdx.x;
    float4 v = in[i];
    float f[4] = {v.x, v.y, v.z, v.w};
    __nv_bfloat16 h4[4], l4[4];
#pragma unroll
    for (int j = 0; j < 4; ++j) {
        h4[j] = __float2bfloat16(f[j]);
        l4[j] = __float2bfloat16(f[j] - __bfloat162float(h4[j]));
    }
    *(uint2*)(hi + (size_t)i * 4) = *(uint2*)h4;
    *(uint2*)(lo + (size_t)i * 4) = *(uint2*)l4;
}

__global__ void transpose_split(const float* __restrict__ w0, const float* __restrict__ w1,
                                const float* __restrict__ w2, const float* __restrict__ w3,
                                __nv_bfloat16* __restrict__ ohi, __nv_bfloat16* __restrict__ olo,
                                __half* __restrict__ wohi, __half* __restrict__ wolo)
{
    __shared__ float t[32][33];
    const float* w = blockIdx.z == 0 ? w0 : blockIdx.z == 1 ? w1 : blockIdx.z == 2 ? w2 : w3;
    int x0 = blockIdx.x * 32, y0 = blockIdx.y * 32;
    for (int i = threadIdx.y; i < 32; i += 8)
        t[i][threadIdx.x] = w[(size_t)(y0 + i) * DM + x0 + threadIdx.x];
    __syncthreads();
    if (blockIdx.z < 3) {
        size_t zoff = (size_t)blockIdx.z * DM * DM;
        for (int i = threadIdx.y; i < 32; i += 8) {
            float v = t[threadIdx.x][i];
            __nv_bfloat16 hb = __float2bfloat16(v);
            __nv_bfloat16 lb = __float2bfloat16(v - __bfloat162float(hb));
            size_t o = zoff + (size_t)(x0 + i) * DM + y0 + threadIdx.x;
            ohi[o] = hb; olo[o] = lb;
        }
    } else {
        for (int i = threadIdx.y; i < 32; i += 8) {
            float v = t[threadIdx.x][i];
            __half hh = __float2half_rn(v);
            __half hl = __float2half_rn(v - __half2float(hh));
            size_t o = (size_t)(x0 + i) * DM + y0 + threadIdx.x;
            wohi[o] = hh; wolo[o] = hl;
        }
    }
}

// ---------------- fused QKV GEMM: split-bf16, 4-stage single-sync ----------------
#define KCH   32
#define NKT   (DM / KCH)
#define ROWB  80
#define TSZ   (128 * 80)               // bytes per tile (128 rows x 80 B)
#define QSTG  (4 * TSZ)                // Ah,Al,Bh,Bl per stage = 40960
#define QKV_SMEM (4 * QSTG)            // 163840

__global__ __launch_bounds__(256, 1) void gemm_qkv(
    const __nv_bfloat16* __restrict__ Ah, const __nv_bfloat16* __restrict__ Al,
    const __nv_bfloat16* __restrict__ Bh, const __nv_bfloat16* __restrict__ Bl,
    __nv_bfloat16* __restrict__ qh, __nv_bfloat16* __restrict__ ql,
    __nv_bfloat16* __restrict__ kh, __nv_bfloat16* __restrict__ kl,
    __half* __restrict__ vf)
{
    extern __shared__ __align__(16) char dsm[];
    const uint32_t base = smem_u32(dsm);
    const int tid = threadIdx.x, lane = tid & 31, wid = tid >> 5;
    const int warpM = wid & 1, warpN = wid >> 1;
    const int m0 = blockIdx.y * 128, n0 = blockIdx.x * 128;

    const __nv_bfloat16* Ahp = Ah + (size_t)m0 * DM;
    const __nv_bfloat16* Alp = Al + (size_t)m0 * DM;
    const __nv_bfloat16* Bhp = Bh + (size_t)n0 * DM;
    const __nv_bfloat16* Blp = Bl + (size_t)n0 * DM;

    const int lrow = tid >> 2;
    const int lu   = tid & 3;

    auto issue = [&](int kc, int st) {
        uint32_t sb = base + st * QSTG;
#pragma unroll
        for (int t = 0; t < 2; ++t) {
            int row = lrow + t * 64;
            uint32_t d = sb + row * ROWB + lu * 16;
            size_t  go = (size_t)row * DM + kc + lu * 8;
            cp16(d,           Ahp + go);
            cp16(d + TSZ,     Alp + go);
            cp16(d + 2 * TSZ, Bhp + go);
            cp16(d + 3 * TSZ, Blp + go);
        }
        cp_commit();
    };

    float acc[4][4][4];
#pragma unroll
    for (int i = 0; i < 4; ++i)
#pragma unroll
        for (int j = 0; j < 4; ++j)
#pragma unroll
            for (int r = 0; r < 4; ++r) acc[i][j][r] = 0.f;

    issue(0, 0); issue(KCH, 1); issue(2 * KCH, 2);

    const uint32_t aRow = (uint32_t)(warpM * 64 + (lane & 15));
    const uint32_t aCol = (uint32_t)(((lane >> 4) & 1) * 16);
    const uint32_t bRow = (uint32_t)(warpN * 32 + (lane & 7));
    const uint32_t bCol = (uint32_t)(((lane >> 3) & 1) * 16);

    for (int kt = 0; kt < NKT; ++kt) {
        cp_wait<2>();
        __syncthreads();
        if (kt + 3 < NKT) issue((kt + 3) * KCH, (kt + 3) & 3);
        else cp_commit();

        uint32_t sb = base + (kt & 3) * QSTG;
#pragma unroll
        for (int s = 0; s < 2; ++s) {
            uint32_t ah[4][4], al[4][4], bh[4][2], bl[4][2];
#pragma unroll
            for (int i = 0; i < 4; ++i) {
                uint32_t a = sb + (aRow + i * 16) * ROWB + s * 32 + aCol;
                ldm_x4(a,       ah[i][0], ah[i][1], ah[i][2], ah[i][3]);
                ldm_x4(a + TSZ, al[i][0], al[i][1], al[i][2], al[i][3]);
            }
#pragma unroll
            for (int j = 0; j < 4; ++j) {
                uint32_t b = sb + (bRow + j * 8) * ROWB + s * 32 + bCol;
                ldm_x2(b + 2 * TSZ, bh[j][0], bh[j][1]);
                ldm_x2(b + 3 * TSZ, bl[j][0], bl[j][1]);
            }
#pragma unroll
            for (int i = 0; i < 4; ++i)
#pragma unroll
                for (int j = 0; j < 4; ++j) {
                    mma16816(acc[i][j], ah[i], bh[j]);
                    mma16816(acc[i][j], ah[i], bl[j]);
                    mma16816(acc[i][j], al[i], bh[j]);
                }
        }
    }

    const int which = n0 >> 10;    // 0=q, 1=k, 2=v
    __nv_bfloat16* oH = (which == 0) ? qh : kh;
    __nv_bfloat16* oL = (which == 0) ? ql : kl;

#pragma unroll
    for (int i = 0; i < 4; ++i) {
        int mA = m0 + warpM * 64 + i * 16 + (lane >> 2);
        int mB = mA + 8;
#pragma unroll
        for (int j = 0; j < 4; ++j) {
            int n = n0 + warpN * 32 + j * 8 + ((lane & 3) << 1);
            int nn = n & 1023;
            int hh = nn >> 6, dd = nn & 63;
            int bA = mA >> 11, sA = mA & (S_LEN - 1);
            int bB = mB >> 11, sB = mB & (S_LEN - 1);
            size_t oA = ((size_t)(bA * NH + hh) * S_LEN + sA) * DK + dd;
            size_t oB = ((size_t)(bB * NH + hh) * S_LEN + sB) * DK + dd;
            if (which == 2) {
                __half2 v0 = __floats2half2_rn(acc[i][j][0], acc[i][j][1]);
                __half2 v1 = __floats2half2_rn(acc[i][j][2], acc[i][j][3]);
                *(uint32_t*)(vf + oA) = *(uint32_t*)&v0;
                *(uint32_t*)(vf + oB) = *(uint32_t*)&v1;
            } else {
                uint32_t h0, l0, h1, l1;
                pksplit(acc[i][j][0], acc[i][j][1], h0, l0);
                pksplit(acc[i][j][2], acc[i][j][3], h1, l1);
                *(uint32_t*)(oH + oA) = h0; *(uint32_t*)(oL + oA) = l0;
                *(uint32_t*)(oH + oB) = h1; *(uint32_t*)(oL + oB) = l1;
            }
        }
    }
}

// ---------------- out-projection GEMM: fp16 A single + fp16 B split, 2 MMA ----------------
#define OSTG (3 * TSZ)                 // A, Bh, Bl = 30720
#define OUT_SMEM (4 * OSTG)            // 122880

__global__ __launch_bounds__(256, 1) void gemm_out(
    const __half* __restrict__ Af,
    const __half* __restrict__ Bh, const __half* __restrict__ Bl,
    float* __restrict__ outF)
{
    extern __shared__ __align__(16) char dsm[];
    const uint32_t base = smem_u32(dsm);
    const int tid = threadIdx.x, lane = tid & 31, wid = tid >> 5;
    const int warpM = wid & 1, warpN = wid >> 1;
    const int m0 = blockIdx.y * 128, n0 = blockIdx.x * 128;

    const __half* Ap  = Af + (size_t)m0 * DM;
    const __half* Bhp = Bh + (size_t)n0 * DM;
    const __half* Blp = Bl + (size_t)n0 * DM;

    const int lrow = tid >> 2;
    const int lu   = tid & 3;

    auto issue = [&](int kc, int st) {
        uint32_t sb = base + st * OSTG;
#pragma unroll
        for (int t = 0; t < 2; ++t) {
            int row = lrow + t * 64;
            uint32_t d = sb + row * ROWB + lu * 16;
            size_t  go = (size_t)row * DM + kc + lu * 8;
            cp16(d,           Ap  + go);
            cp16(d + TSZ,     Bhp + go);
            cp16(d + 2 * TSZ, Blp + go);
        }
        cp_commit();
    };

    float acc[4][4][4];
#pragma unroll
    for (int i = 0; i < 4; ++i)
#pragma unroll
        for (int j = 0; j < 4; ++j)
#pragma unroll
            for (int r = 0; r < 4; ++r) acc[i][j][r] = 0.f;

    issue(0, 0); issue(KCH, 1); issue(2 * KCH, 2);

    const uint32_t aRow = (uint32_t)(warpM * 64 + (lane & 15));
    const uint32_t aCol = (uint32_t)(((lane >> 4) & 1) * 16);
    const uint32_t bRow = (uint32_t)(warpN * 32 + (lane & 7));
    const uint32_t bCol = (uint32_t)(((lane >> 3) & 1) * 16);

    for (int kt = 0; kt < NKT; ++kt) {
        cp_wait<2>();
        __syncthreads();
        if (kt + 3 < NKT) issue((kt + 3) * KCH, (kt + 3) & 3);
        else cp_commit();

        uint32_t sb = base + (kt & 3) * OSTG;
#pragma unroll
        for (int s = 0; s < 2; ++s) {
            uint32_t af[4][4], bh[4][2], bl[4][2];
#pragma unroll
            for (int i = 0; i < 4; ++i) {
                uint32_t a = sb + (aRow + i * 16) * ROWB + s * 32 + aCol;
                ldm_x4(a, af[i][0], af[i][1], af[i][2], af[i][3]);
            }
#pragma unroll
            for (int j = 0; j < 4; ++j) {
                uint32_t b = sb + (bRow + j * 8) * ROWB + s * 32 + bCol;
                ldm_x2(b + TSZ,     bh[j][0], bh[j][1]);
                ldm_x2(b + 2 * TSZ, bl[j][0], bl[j][1]);
            }
#pragma unroll
            for (int i = 0; i < 4; ++i)
#pragma unroll
                for (int j = 0; j < 4; ++j) {
                    mma16816h(acc[i][j], af[i], bh[j]);
                    mma16816h(acc[i][j], af[i], bl[j]);
                }
        }
    }

#pragma unroll
    for (int i = 0; i < 4; ++i) {
        int mA = m0 + warpM * 64 + i * 16 + (lane >> 2);
        int mB = mA + 8;
#pragma unroll
        for (int j = 0; j < 4; ++j) {
            int n = n0 + warpN * 32 + j * 8 + ((lane & 3) << 1);
            *(float2*)(outF + (size_t)mA * DM + n) = make_float2(acc[i][j][0], acc[i][j][1]);
            *(float2*)(outF + (size_t)mB * DM + n) = make_float2(acc[i][j][2], acc[i][j][3]);
        }
    }
}

// ---------------- HMMA flash attention (8 warps, occ 2, ext bias table) ----------------
__device__ __forceinline__ int t5_bucket(int delta)
{
    int base = (delta > 0) ? 16 : 0;
    int a = delta < 0 ? -delta : delta;
    int bucket;
    if (a < 8) bucket = a;
    else if (a >= 128) bucket = 15;
    else {
        int t = 31 - __clz(a);
        int f = (a * a >= (1 << (2 * t + 1))) ? 1 : 0;
        bucket = 2 + 2 * t + f;
        if (bucket > 15) bucket = 15;
    }
    return base + bucket;
}

#define PQ        144
#define A_QH      0
#define A_QL      18432
#define A_BUF     36864
#define A_BUFSZ   27648                  // KH, KL, V (64 rows x 144 B)
#define A_KH      0
#define A_KL      9216
#define A_V       18432
#define A_BIAS    (A_BUF + 2*A_BUFSZ)    // 92160
#define BIAS_N    4096                   // deltas [-2047, 2048]
#define ATT_SMEM  (A_BIAS + BIAS_N*4)    // 108544

__global__ __launch_bounds__(256, 2) void attn_mma(
    const __nv_bfloat16* __restrict__ qh, const __nv_bfloat16* __restrict__ ql,
    const __nv_bfloat16* __restrict__ kh, const __nv_bfloat16* __restrict__ kl,
    const __half* __restrict__ vf, const float* __restrict__ rel_bias,
    __half* __restrict__ cf)
{
    extern __shared__ __align__(16) char asmem[];
    const uint32_t base = smem_u32(asmem);
    float* bias = (float*)(asmem + A_BIAS);

    const int tid = threadIdx.x, lane = tid & 31, wid = tid >> 5;
    const int bh = blockIdx.y;
    const int hd = bh & (NH - 1);
    const int b  = bh >> 4;
    const int q0 = blockIdx.x * 128;
    const size_t bo = (size_t)bh * S_LEN * DK;

    for (int i = tid; i < BIAS_N; i += 256)
        bias[i] = rel_bias[t5_bucket(i - 2047) * NH + hd];

#pragma unroll
    for (int it = 0; it < 8; ++it) {
        int idx = tid + it * 256;
        int sub = idx & 1023, row = sub >> 3, u = sub & 7;
        const __nv_bfloat16* src = (it < 4) ? qh : ql;
        cp16(base + (it < 4 ? A_QH : A_QL) + row * PQ + u * 16,
             src + bo + (size_t)(q0 + row) * DK + u * 8);
    }
    auto issue_kv = [&](int t, int buf) {
        uint32_t bb = base + A_BUF + buf * A_BUFSZ;
#pragma unroll
        for (int it = 0; it < 6; ++it) {
            int idx = tid + it * 256;
            int sub = idx & 511, row = sub >> 3, u = sub & 7;
            if (it < 4) {
                const __nv_bfloat16* src = (it < 2) ? kh : kl;
                uint32_t toff = (it < 2) ? A_KH : A_KL;
                cp16(bb + toff + row * PQ + u * 16,
                     src + bo + (size_t)(t * 64 + row) * DK + u * 8);
            } else {
                cp16(bb + A_V + row * PQ + u * 16,
                     vf + bo + (size_t)(t * 64 + row) * DK + u * 8);
            }
        }
        cp_commit();
    };
    issue_kv(0, 0);
    issue_kv(1, 1);

    const int g  = lane >> 2;
    const int tc = lane & 3;
    const int qg0 = q0 + wid * 16 + g;
    const int qg1 = qg0 + 8;

    float acc_o[8][4];
#pragma unroll
    for (int j = 0; j < 8; ++j)
#pragma unroll
        for (int r = 0; r < 4; ++r) acc_o[j][r] = 0.f;
    float m0 = -1e30f, m1 = -1e30f, l0 = 0.f, l1 = 0.f;

    const uint32_t aBase = base + (wid * 16 + (lane & 15)) * PQ + ((lane >> 4) & 1) * 16;
    const uint32_t bRowSel = ((lane >> 4) & 1) * 8 + (lane & 7);
    const uint32_t bColSel = ((lane >> 3) & 1) * 16;
    const uint32_t vRowSel = ((lane >> 3) & 1) * 8 + (lane & 7);
    const uint32_t vColSel = ((lane >> 4) & 1) * 16;

    for (int t = 0; t < 32; ++t) {
        if (t + 2 < 32) cp_wait<1>(); else cp_wait<0>();
        __syncthreads();
        uint32_t kb = base + A_BUF + (t & 1) * A_BUFSZ;

        // ---- S = Q K^T (split-bf16, 3 mma) ----
        float s[8][4];
#pragma unroll
        for (int j = 0; j < 8; ++j)
#pragma unroll
            for (int r = 0; r < 4; ++r) s[j][r] = 0.f;

#pragma unroll
        for (int ks = 0; ks < 4; ++ks) {
            uint32_t ah[4], al[4];
            ldm_x4(aBase + ks * 32,        ah[0], ah[1], ah[2], ah[3]);
            ldm_x4(aBase + A_QL + ks * 32, al[0], al[1], al[2], al[3]);
#pragma unroll
            for (int nb2 = 0; nb2 < 4; ++nb2) {
                uint32_t bAddr = kb + A_KH + (nb2 * 16 + bRowSel) * PQ + bColSel + ks * 32;
                uint32_t h0, h1, h2, h3, u0, u1, u2, u3;
                ldm_x4(bAddr,                 h0, h1, h2, h3);
                ldm_x4(bAddr + (A_KL - A_KH), u0, u1, u2, u3);
                uint32_t bh0[2] = {h0, h1}, bh1[2] = {h2, h3};
                uint32_t bl0[2] = {u0, u1}, bl1[2] = {u2, u3};
                mma16816(s[2*nb2],   ah, bh0); mma16816(s[2*nb2],   ah, bl0);
                mma16816(s[2*nb2],   al, bh0);
                mma16816(s[2*nb2+1], ah, bh1); mma16816(s[2*nb2+1], ah, bl1);
                mma16816(s[2*nb2+1], al, bh1);
            }
        }

        // ---- bias (no clamps: extended table) + online softmax ----
        int ktb = t * 64;
        float rm0 = -1e30f, rm1 = -1e30f;
        int i0base = ktb + tc * 2 - qg0 + 2047;
        int i1base = ktb + tc * 2 - qg1 + 2047;
#pragma unroll
        for (int nb = 0; nb < 8; ++nb) {
            int i00 = i0base + nb * 8;
            int i10 = i1base + nb * 8;
            s[nb][0] += bias[i00]; s[nb][1] += bias[i00 + 1];
            s[nb][2] += bias[i10]; s[nb][3] += bias[i10 + 1];
            rm0 = fmaxf(rm0, fmaxf(s[nb][0], s[nb][1]));
            rm1 = fmaxf(rm1, fmaxf(s[nb][2], s[nb][3]));
        }
        rm0 = fmaxf(rm0, __shfl_xor_sync(0xffffffffu, rm0, 1));
        rm0 = fmaxf(rm0, __shfl_xor_sync(0xffffffffu, rm0, 2));
        rm1 = fmaxf(rm1, __shfl_xor_sync(0xffffffffu, rm1, 1));
        rm1 = fmaxf(rm1, __shfl_xor_sync(0xffffffffu, rm1, 2));

        float mn0 = fmaxf(m0, rm0), mn1 = fmaxf(m1, rm1);
        float c0 = __expf(m0 - mn0), c1 = __expf(m1 - mn1);
        m0 = mn0; m1 = mn1;

        float ps0 = 0.f, ps1 = 0.f;
#pragma unroll
        for (int nb = 0; nb < 8; ++nb) {
            s[nb][0] = __expf(s[nb][0] - mn0); s[nb][1] = __expf(s[nb][1] - mn0);
            s[nb][2] = __expf(s[nb][2] - mn1); s[nb][3] = __expf(s[nb][3] - mn1);
            ps0 += s[nb][0] + s[nb][1];
            ps1 += s[nb][2] + s[nb][3];
        }
        ps0 += __shfl_xor_sync(0xffffffffu, ps0, 1);
        ps0 += __shfl_xor_sync(0xffffffffu, ps0, 2);
        ps1 += __shfl_xor_sync(0xffffffffu, ps1, 1);
        ps1 += __shfl_xor_sync(0xffffffffu, ps1, 2);
        l0 = l0 * c0 + ps0; l1 = l1 * c1 + ps1;

#pragma unroll
        for (int j = 0; j < 8; ++j) {
            acc_o[j][0] *= c0; acc_o[j][1] *= c0;
            acc_o[j][2] *= c1; acc_o[j][3] *= c1;
        }

        // ---- O += P V (fp16 mma) ----
#pragma unroll
        for (int ks = 0; ks < 4; ++ks) {
            uint32_t ap[4];
            __half2 p0 = __floats2half2_rn(s[2*ks][0],   s[2*ks][1]);
            __half2 p1 = __floats2half2_rn(s[2*ks][2],   s[2*ks][3]);
            __half2 p2 = __floats2half2_rn(s[2*ks+1][0], s[2*ks+1][1]);
            __half2 p3 = __floats2half2_rn(s[2*ks+1][2], s[2*ks+1][3]);
            ap[0] = *(uint32_t*)&p0; ap[1] = *(uint32_t*)&p1;
            ap[2] = *(uint32_t*)&p2; ap[3] = *(uint32_t*)&p3;
#pragma unroll
            for (int db2 = 0; db2 < 4; ++db2) {
                uint32_t vAddr = kb + A_V + (ks * 16 + vRowSel) * PQ + db2 * 32 + vColSel;
                uint32_t h0, h1, h2, h3;
                ldm_x4t(vAddr, h0, h1, h2, h3);
                uint32_t v0[2] = {h0, h1}, v1[2] = {h2, h3};
                mma16816h(acc_o[2*db2],   ap, v0);
                mma16816h(acc_o[2*db2+1], ap, v1);
            }
        }
        __syncthreads();
        if (t + 2 < 32) issue_kv(t + 2, t & 1);
    }

    // ---- epilogue: ctx fp16 single ----
    float inv0 = 1.f / l0, inv1 = 1.f / l1;
#pragma unroll
    for (int db = 0; db < 8; ++db) {
        int dcol = hd * DK + db * 8 + tc * 2;
        size_t o0 = ((size_t)b * S_LEN + qg0) * DM + dcol;
        size_t o1 = ((size_t)b * S_LEN + qg1) * DM + dcol;
        __half2 w0 = __floats2half2_rn(acc_o[db][0] * inv0, acc_o[db][1] * inv0);
        __half2 w1 = __floats2half2_rn(acc_o[db][2] * inv1, acc_o[db][3] * inv1);
        *(uint32_t*)(cf + o0) = *(uint32_t*)&w0;
        *(uint32_t*)(cf + o1) = *(uint32_t*)&w1;
    }
}

// ---------------------------------------------------------------------------
extern "C" void kernel_launch(void* const* d_in, const int* in_sizes, int n_in,
                              void* d_out, int out_size)
{
    const float* hidden  = (const float*)d_in[0];
    const float* wq      = (const float*)d_in[1];
    const float* wk      = (const float*)d_in[2];
    const float* wv      = (const float*)d_in[3];
    const float* wo      = (const float*)d_in[4];
    const float* relbias = (const float*)d_in[5];
    float* out = (float*)d_out;

    __nv_bfloat16 *hhi, *hlo, *whi, *wlo, *qh, *ql, *kh, *kl;
    __half *vf, *cf, *wohi, *wolo;
    cudaGetSymbolAddress((void**)&hhi,  g_h_hi);
    cudaGetSymbolAddress((void**)&hlo,  g_h_lo);
    cudaGetSymbolAddress((void**)&whi,  g_wt_hi);
    cudaGetSymbolAddress((void**)&wlo,  g_wt_lo);
    cudaGetSymbolAddress((void**)&wohi, g_wo_hi);
    cudaGetSymbolAddress((void**)&wolo, g_wo_lo);
    cudaGetSymbolAddress((void**)&qh,   g_qh);
    cudaGetSymbolAddress((void**)&ql,   g_ql);
    cudaGetSymbolAddress((void**)&kh,   g_kh);
    cudaGetSymbolAddress((void**)&kl,   g_kl);
    cudaGetSymbolAddress((void**)&vf,   g_vf);
    cudaGetSymbolAddress((void**)&cf,   g_ctx);

    cudaFuncSetAttribute(gemm_qkv, cudaFuncAttributeMaxDynamicSharedMemorySize, QKV_SMEM);
    cudaFuncSetAttribute(gemm_out, cudaFuncAttributeMaxDynamicSharedMemorySize, OUT_SMEM);
    cudaFuncSetAttribute(attn_mma, cudaFuncAttributeMaxDynamicSharedMemorySize, ATT_SMEM);

    split_hidden<<<MT * DM / 1024, 256>>>((const float4*)hidden, hhi, hlo);
    transpose_split<<<dim3(32, 32, 4), dim3(32, 8)>>>(wq, wk, wv, wo, whi, wlo, wohi, wolo);

    gemm_qkv<<<dim3(24, 64), 256, QKV_SMEM>>>(hhi, hlo, whi, wlo, qh, ql, kh, kl, vf);

    attn_mma<<<dim3(16, 64), 256, ATT_SMEM>>>(qh, ql, kh, kl, vf, relbias, cf);

    gemm_out<<<dim3(8, 64), 256, OUT_SMEM>>>(cf, wohi, wolo, out);
}

// round 11
// speedup vs baseline: 3.9229x; 1.0231x over previous
#include <cuda_runtime.h>
#include <cuda_bf16.h>
#include <cuda_fp16.h>
#include <cstdint>

#define BATCH 4
#define S_LEN 2048
#define NH    16
#define DK    64
#define DM    1024
#define MT    (BATCH*S_LEN)
#define BHSZ  ((size_t)BATCH * NH * S_LEN * DK)

__device__ __nv_bfloat16 g_h_hi[MT * DM];
__device__ __nv_bfloat16 g_h_lo[MT * DM];
__device__ __nv_bfloat16 g_wt_hi[3 * DM * DM];
__device__ __nv_bfloat16 g_wt_lo[3 * DM * DM];
__device__ __half        g_wo_hi[DM * DM];
__device__ __half        g_wo_lo[DM * DM];
__device__ __nv_bfloat16 g_qh[BHSZ], g_ql[BHSZ];
__device__ __nv_bfloat16 g_kh[BHSZ], g_kl[BHSZ];
__device__ __half        g_vf[BHSZ];
__device__ __half        g_ctx[MT * DM];

// ---------------- helpers ----------------
__device__ __forceinline__ uint32_t smem_u32(const void* p) {
    uint32_t a;
    asm("{ .reg .u64 t; cvta.to.shared.u64 t, %1; cvt.u32.u64 %0, t; }" : "=r"(a) : "l"(p));
    return a;
}
__device__ __forceinline__ void cp16(uint32_t dst, const void* src) {
    asm volatile("cp.async.cg.shared.global [%0], [%1], 16;" :: "r"(dst), "l"(src));
}
__device__ __forceinline__ void cp_commit() { asm volatile("cp.async.commit_group;" ::: "memory"); }
template<int N> __device__ __forceinline__ void cp_wait() {
    asm volatile("cp.async.wait_group %0;" :: "n"(N) : "memory");
}
__device__ __forceinline__ void ldm_x4(uint32_t a, uint32_t& r0, uint32_t& r1,
                                       uint32_t& r2, uint32_t& r3) {
    asm volatile("ldmatrix.sync.aligned.m8n8.x4.shared.b16 {%0,%1,%2,%3}, [%4];"
                 : "=r"(r0), "=r"(r1), "=r"(r2), "=r"(r3) : "r"(a));
}
__device__ __forceinline__ void ldm_x4t(uint32_t a, uint32_t& r0, uint32_t& r1,
                                        uint32_t& r2, uint32_t& r3) {
    asm volatile("ldmatrix.sync.aligned.m8n8.x4.trans.shared.b16 {%0,%1,%2,%3}, [%4];"
                 : "=r"(r0), "=r"(r1), "=r"(r2), "=r"(r3) : "r"(a));
}
__device__ __forceinline__ void ldm_x2(uint32_t a, uint32_t& r0, uint32_t& r1) {
    asm volatile("ldmatrix.sync.aligned.m8n8.x2.shared.b16 {%0,%1}, [%2];"
                 : "=r"(r0), "=r"(r1) : "r"(a));
}
__device__ __forceinline__ void mma16816(float* c, const uint32_t* a, const uint32_t* b) {
    asm volatile("mma.sync.aligned.m16n8k16.row.col.f32.bf16.bf16.f32 "
                 "{%0,%1,%2,%3},{%4,%5,%6,%7},{%8,%9},{%0,%1,%2,%3};"
                 : "+f"(c[0]), "+f"(c[1]), "+f"(c[2]), "+f"(c[3])
                 : "r"(a[0]), "r"(a[1]), "r"(a[2]), "r"(a[3]), "r"(b[0]), "r"(b[1]));
}
__device__ __forceinline__ void mma16816h(float* c, const uint32_t* a, const uint32_t* b) {
    asm volatile("mma.sync.aligned.m16n8k16.row.col.f32.f16.f16.f32 "
                 "{%0,%1,%2,%3},{%4,%5,%6,%7},{%8,%9},{%0,%1,%2,%3};"
                 : "+f"(c[0]), "+f"(c[1]), "+f"(c[2]), "+f"(c[3])
                 : "r"(a[0]), "r"(a[1]), "r"(a[2]), "r"(a[3]), "r"(b[0]), "r"(b[1]));
}
__device__ __forceinline__ void pksplit(float x, float y, uint32_t& hi, uint32_t& lo) {
    __nv_bfloat162 h = __floats2bfloat162_rn(x, y);
    __nv_bfloat162 l = __floats2bfloat162_rn(x - __bfloat162float(h.x),
                                             y - __bfloat162float(h.y));
    hi = *(uint32_t*)&h; lo = *(uint32_t*)&l;
}

// ---------------- prep ----------------
__global__ void split_hidden(const float4* __restrict__ in,
                             __nv_bfloat16* __restrict__ hi, __nv_bfloat16* __restrict__ lo)
{
    int i = blockIdx.x * 256 + threadIdx.x;
    float4 v = in[i];
    float f[4] = {v.x, v.y, v.z, v.w};
    __nv_bfloat16 h4[4], l4[4];
#pragma unroll
    for (int j = 0; j < 4; ++j) {
        h4[j] = __float2bfloat16(f[j]);
        l4[j] = __float2bfloat16(f[j] - __bfloat162float(h4[j]));
    }
    *(uint2*)(hi + (size_t)i * 4) = *(uint2*)h4;
    *(uint2*)(lo + (size_t)i * 4) = *(uint2*)l4;
}

__global__ void transpose_split(const float* __restrict__ w0, const float* __restrict__ w1,
                                const float* __restrict__ w2, const float* __restrict__ w3,
                                __nv_bfloat16* __restrict__ ohi, __nv_bfloat16* __restrict__ olo,
                                __half* __restrict__ wohi, __half* __restrict__ wolo)
{
    __shared__ float t[32][33];
    const float* w = blockIdx.z == 0 ? w0 : blockIdx.z == 1 ? w1 : blockIdx.z == 2 ? w2 : w3;
    int x0 = blockIdx.x * 32, y0 = blockIdx.y * 32;
    for (int i = threadIdx.y; i < 32; i += 8)
        t[i][threadIdx.x] = w[(size_t)(y0 + i) * DM + x0 + threadIdx.x];
    __syncthreads();
    if (blockIdx.z < 3) {
        size_t zoff = (size_t)blockIdx.z * DM * DM;
        for (int i = threadIdx.y; i < 32; i += 8) {
            float v = t[threadIdx.x][i];
            __nv_bfloat16 hb = __float2bfloat16(v);
            __nv_bfloat16 lb = __float2bfloat16(v - __bfloat162float(hb));
            size_t o = zoff + (size_t)(x0 + i) * DM + y0 + threadIdx.x;
            ohi[o] = hb; olo[o] = lb;
        }
    } else {
        for (int i = threadIdx.y; i < 32; i += 8) {
            float v = t[threadIdx.x][i];
            __half hh = __float2half_rn(v);
            __half hl = __float2half_rn(v - __half2float(hh));
            size_t o = (size_t)(x0 + i) * DM + y0 + threadIdx.x;
            wohi[o] = hh; wolo[o] = hl;
        }
    }
}

// ---------------- fused QKV GEMM: split-bf16, KCH=16, 4-stage, occ 2 ----------------
#define KC2   16
#define NK2   (DM / KC2)               // 64
#define RW2   48                       // 32 B data + pad, 3x16 => conflict-free
#define T2    (128 * 48)               // 6144 bytes per tile
#define QST2  (4 * T2)                 // 24576 per stage
#define QKV_SMEM (4 * QST2)            // 98304

__global__ __launch_bounds__(256, 2) void gemm_qkv(
    const __nv_bfloat16* __restrict__ Ah, const __nv_bfloat16* __restrict__ Al,
    const __nv_bfloat16* __restrict__ Bh, const __nv_bfloat16* __restrict__ Bl,
    __nv_bfloat16* __restrict__ qh, __nv_bfloat16* __restrict__ ql,
    __nv_bfloat16* __restrict__ kh, __nv_bfloat16* __restrict__ kl,
    __half* __restrict__ vf)
{
    extern __shared__ __align__(16) char dsm[];
    const uint32_t base = smem_u32(dsm);
    const int tid = threadIdx.x, lane = tid & 31, wid = tid >> 5;
    const int warpM = wid & 1, warpN = wid >> 1;
    const int m0 = blockIdx.y * 128, n0 = blockIdx.x * 128;

    const __nv_bfloat16* Ahp = Ah + (size_t)m0 * DM;
    const __nv_bfloat16* Alp = Al + (size_t)m0 * DM;
    const __nv_bfloat16* Bhp = Bh + (size_t)n0 * DM;
    const __nv_bfloat16* Blp = Bl + (size_t)n0 * DM;

    const int lrow = tid >> 1;          // 0..127
    const int lu   = tid & 1;           // 16B unit in 32B row

    auto issue = [&](int kc, int st) {
        uint32_t sb = base + st * QST2;
        uint32_t d  = sb + lrow * RW2 + lu * 16;
        size_t   go = (size_t)lrow * DM + kc + lu * 8;
        cp16(d,          Ahp + go);
        cp16(d + T2,     Alp + go);
        cp16(d + 2 * T2, Bhp + go);
        cp16(d + 3 * T2, Blp + go);
        cp_commit();
    };

    float acc[4][4][4];
#pragma unroll
    for (int i = 0; i < 4; ++i)
#pragma unroll
        for (int j = 0; j < 4; ++j)
#pragma unroll
            for (int r = 0; r < 4; ++r) acc[i][j][r] = 0.f;

    issue(0, 0); issue(KC2, 1); issue(2 * KC2, 2);

    const uint32_t aRow = (uint32_t)(warpM * 64 + (lane & 15));
    const uint32_t aCol = (uint32_t)(((lane >> 4) & 1) * 16);
    const uint32_t bRow = (uint32_t)(warpN * 32 + (lane & 7));
    const uint32_t bCol = (uint32_t)(((lane >> 3) & 1) * 16);

    for (int kt = 0; kt < NK2; ++kt) {
        cp_wait<2>();
        __syncthreads();
        if (kt + 3 < NK2) issue((kt + 3) * KC2, (kt + 3) & 3);
        else cp_commit();

        uint32_t sb = base + (kt & 3) * QST2;
        // B fragments first (32 regs live), then stream A per-i (8 regs)
        uint32_t bh[4][2], bl[4][2];
#pragma unroll
        for (int j = 0; j < 4; ++j) {
            uint32_t b = sb + 2 * T2 + (bRow + j * 8) * RW2 + bCol;
            ldm_x2(b,      bh[j][0], bh[j][1]);
            ldm_x2(b + T2, bl[j][0], bl[j][1]);
        }
#pragma unroll
        for (int i = 0; i < 4; ++i) {
            uint32_t a = sb + (aRow + i * 16) * RW2 + aCol;
            uint32_t ah[4], al[4];
            ldm_x4(a,      ah[0], ah[1], ah[2], ah[3]);
            ldm_x4(a + T2, al[0], al[1], al[2], al[3]);
#pragma unroll
            for (int j = 0; j < 4; ++j) {
                mma16816(acc[i][j], ah, bh[j]);
                mma16816(acc[i][j], ah, bl[j]);
                mma16816(acc[i][j], al, bh[j]);
            }
        }
    }

    const int which = n0 >> 10;    // 0=q, 1=k, 2=v
    __nv_bfloat16* oH = (which == 0) ? qh : kh;
    __nv_bfloat16* oL = (which == 0) ? ql : kl;

#pragma unroll
    for (int i = 0; i < 4; ++i) {
        int mA = m0 + warpM * 64 + i * 16 + (lane >> 2);
        int mB = mA + 8;
#pragma unroll
        for (int j = 0; j < 4; ++j) {
            int n = n0 + warpN * 32 + j * 8 + ((lane & 3) << 1);
            int nn = n & 1023;
            int hh = nn >> 6, dd = nn & 63;
            int bA = mA >> 11, sA = mA & (S_LEN - 1);
            int bB = mB >> 11, sB = mB & (S_LEN - 1);
            size_t oA = ((size_t)(bA * NH + hh) * S_LEN + sA) * DK + dd;
            size_t oB = ((size_t)(bB * NH + hh) * S_LEN + sB) * DK + dd;
            if (which == 2) {
                __half2 v0 = __floats2half2_rn(acc[i][j][0], acc[i][j][1]);
                __half2 v1 = __floats2half2_rn(acc[i][j][2], acc[i][j][3]);
                *(uint32_t*)(vf + oA) = *(uint32_t*)&v0;
                *(uint32_t*)(vf + oB) = *(uint32_t*)&v1;
            } else {
                uint32_t h0, l0, h1, l1;
                pksplit(acc[i][j][0], acc[i][j][1], h0, l0);
                pksplit(acc[i][j][2], acc[i][j][3], h1, l1);
                *(uint32_t*)(oH + oA) = h0; *(uint32_t*)(oL + oA) = l0;
                *(uint32_t*)(oH + oB) = h1; *(uint32_t*)(oL + oB) = l1;
            }
        }
    }
}

// ---------------- out-projection GEMM: fp16, KCH=16, 4-stage, occ 2 ----------------
#define OST2 (3 * T2)                  // 18432 per stage
#define OUT_SMEM (4 * OST2)            // 73728

__global__ __launch_bounds__(256, 2) void gemm_out(
    const __half* __restrict__ Af,
    const __half* __restrict__ Bh, const __half* __restrict__ Bl,
    float* __restrict__ outF)
{
    extern __shared__ __align__(16) char dsm[];
    const uint32_t base = smem_u32(dsm);
    const int tid = threadIdx.x, lane = tid & 31, wid = tid >> 5;
    const int warpM = wid & 1, warpN = wid >> 1;
    const int m0 = blockIdx.y * 128, n0 = blockIdx.x * 128;

    const __half* Ap  = Af + (size_t)m0 * DM;
    const __half* Bhp = Bh + (size_t)n0 * DM;
    const __half* Blp = Bl + (size_t)n0 * DM;

    const int lrow = tid >> 1;
    const int lu   = tid & 1;

    auto issue = [&](int kc, int st) {
        uint32_t sb = base + st * OST2;
        uint32_t d  = sb + lrow * RW2 + lu * 16;
        size_t   go = (size_t)lrow * DM + kc + lu * 8;
        cp16(d,          Ap  + go);
        cp16(d + T2,     Bhp + go);
        cp16(d + 2 * T2, Blp + go);
        cp_commit();
    };

    float acc[4][4][4];
#pragma unroll
    for (int i = 0; i < 4; ++i)
#pragma unroll
        for (int j = 0; j < 4; ++j)
#pragma unroll
            for (int r = 0; r < 4; ++r) acc[i][j][r] = 0.f;

    issue(0, 0); issue(KC2, 1); issue(2 * KC2, 2);

    const uint32_t aRow = (uint32_t)(warpM * 64 + (lane & 15));
    const uint32_t aCol = (uint32_t)(((lane >> 4) & 1) * 16);
    const uint32_t bRow = (uint32_t)(warpN * 32 + (lane & 7));
    const uint32_t bCol = (uint32_t)(((lane >> 3) & 1) * 16);

    for (int kt = 0; kt < NK2; ++kt) {
        cp_wait<2>();
        __syncthreads();
        if (kt + 3 < NK2) issue((kt + 3) * KC2, (kt + 3) & 3);
        else cp_commit();

        uint32_t sb = base + (kt & 3) * OST2;
        uint32_t bh[4][2], bl[4][2];
#pragma unroll
        for (int j = 0; j < 4; ++j) {
            uint32_t b = sb + T2 + (bRow + j * 8) * RW2 + bCol;
            ldm_x2(b,      bh[j][0], bh[j][1]);
            ldm_x2(b + T2, bl[j][0], bl[j][1]);
        }
#pragma unroll
        for (int i = 0; i < 4; ++i) {
            uint32_t a = sb + (aRow + i * 16) * RW2 + aCol;
            uint32_t af[4];
            ldm_x4(a, af[0], af[1], af[2], af[3]);
#pragma unroll
            for (int j = 0; j < 4; ++j) {
                mma16816h(acc[i][j], af, bh[j]);
                mma16816h(acc[i][j], af, bl[j]);
            }
        }
    }

#pragma unroll
    for (int i = 0; i < 4; ++i) {
        int mA = m0 + warpM * 64 + i * 16 + (lane >> 2);
        int mB = mA + 8;
#pragma unroll
        for (int j = 0; j < 4; ++j) {
            int n = n0 + warpN * 32 + j * 8 + ((lane & 3) << 1);
            *(float2*)(outF + (size_t)mA * DM + n) = make_float2(acc[i][j][0], acc[i][j][1]);
            *(float2*)(outF + (size_t)mB * DM + n) = make_float2(acc[i][j][2], acc[i][j][3]);
        }
    }
}

// ---------------- HMMA flash attention (8 warps, occ 2, ext bias table) ----------------
__device__ __forceinline__ int t5_bucket(int delta)
{
    int base = (delta > 0) ? 16 : 0;
    int a = delta < 0 ? -delta : delta;
    int bucket;
    if (a < 8) bucket = a;
    else if (a >= 128) bucket = 15;
    else {
        int t = 31 - __clz(a);
        int f = (a * a >= (1 << (2 * t + 1))) ? 1 : 0;
        bucket = 2 + 2 * t + f;
        if (bucket > 15) bucket = 15;
    }
    return base + bucket;
}

#define PQ        144
#define A_QH      0
#define A_QL      18432
#define A_BUF     36864
#define A_BUFSZ   27648
#define A_KH      0
#define A_KL      9216
#define A_V       18432
#define A_BIAS    (A_BUF + 2*A_BUFSZ)
#define BIAS_N    4096
#define ATT_SMEM  (A_BIAS + BIAS_N*4)

__global__ __launch_bounds__(256, 2) void attn_mma(
    const __nv_bfloat16* __restrict__ qh, const __nv_bfloat16* __restrict__ ql,
    const __nv_bfloat16* __restrict__ kh, const __nv_bfloat16* __restrict__ kl,
    const __half* __restrict__ vf, const float* __restrict__ rel_bias,
    __half* __restrict__ cf)
{
    extern __shared__ __align__(16) char asmem[];
    const uint32_t base = smem_u32(asmem);
    float* bias = (float*)(asmem + A_BIAS);

    const int tid = threadIdx.x, lane = tid & 31, wid = tid >> 5;
    const int bh = blockIdx.y;
    const int hd = bh & (NH - 1);
    const int b  = bh >> 4;
    const int q0 = blockIdx.x * 128;
    const size_t bo = (size_t)bh * S_LEN * DK;

    for (int i = tid; i < BIAS_N; i += 256)
        bias[i] = rel_bias[t5_bucket(i - 2047) * NH + hd];

#pragma unroll
    for (int it = 0; it < 8; ++it) {
        int idx = tid + it * 256;
        int sub = idx & 1023, row = sub >> 3, u = sub & 7;
        const __nv_bfloat16* src = (it < 4) ? qh : ql;
        cp16(base + (it < 4 ? A_QH : A_QL) + row * PQ + u * 16,
             src + bo + (size_t)(q0 + row) * DK + u * 8);
    }
    auto issue_kv = [&](int t, int buf) {
        uint32_t bb = base + A_BUF + buf * A_BUFSZ;
#pragma unroll
        for (int it = 0; it < 6; ++it) {
            int idx = tid + it * 256;
            int sub = idx & 511, row = sub >> 3, u = sub & 7;
            if (it < 4) {
                const __nv_bfloat16* src = (it < 2) ? kh : kl;
                uint32_t toff = (it < 2) ? A_KH : A_KL;
                cp16(bb + toff + row * PQ + u * 16,
                     src + bo + (size_t)(t * 64 + row) * DK + u * 8);
            } else {
                cp16(bb + A_V + row * PQ + u * 16,
                     vf + bo + (size_t)(t * 64 + row) * DK + u * 8);
            }
        }
        cp_commit();
    };
    issue_kv(0, 0);
    issue_kv(1, 1);

    const int g  = lane >> 2;
    const int tc = lane & 3;
    const int qg0 = q0 + wid * 16 + g;
    const int qg1 = qg0 + 8;

    float acc_o[8][4];
#pragma unroll
    for (int j = 0; j < 8; ++j)
#pragma unroll
        for (int r = 0; r < 4; ++r) acc_o[j][r] = 0.f;
    float m0 = -1e30f, m1 = -1e30f, l0 = 0.f, l1 = 0.f;

    const uint32_t aBase = base + (wid * 16 + (lane & 15)) * PQ + ((lane >> 4) & 1) * 16;
    const uint32_t bRowSel = ((lane >> 4) & 1) * 8 + (lane & 7);
    const uint32_t bColSel = ((lane >> 3) & 1) * 16;
    const uint32_t vRowSel = ((lane >> 3) & 1) * 8 + (lane & 7);
    const uint32_t vColSel = ((lane >> 4) & 1) * 16;

    for (int t = 0; t < 32; ++t) {
        if (t + 2 < 32) cp_wait<1>(); else cp_wait<0>();
        __syncthreads();
        uint32_t kb = base + A_BUF + (t & 1) * A_BUFSZ;

        float s[8][4];
#pragma unroll
        for (int j = 0; j < 8; ++j)
#pragma unroll
            for (int r = 0; r < 4; ++r) s[j][r] = 0.f;

#pragma unroll
        for (int ks = 0; ks < 4; ++ks) {
            uint32_t ah[4], al[4];
            ldm_x4(aBase + ks * 32,        ah[0], ah[1], ah[2], ah[3]);
            ldm_x4(aBase + A_QL + ks * 32, al[0], al[1], al[2], al[3]);
#pragma unroll
            for (int nb2 = 0; nb2 < 4; ++nb2) {
                uint32_t bAddr = kb + A_KH + (nb2 * 16 + bRowSel) * PQ + bColSel + ks * 32;
                uint32_t h0, h1, h2, h3, u0, u1, u2, u3;
                ldm_x4(bAddr,                 h0, h1, h2, h3);
                ldm_x4(bAddr + (A_KL - A_KH), u0, u1, u2, u3);
                uint32_t bh0[2] = {h0, h1}, bh1[2] = {h2, h3};
                uint32_t bl0[2] = {u0, u1}, bl1[2] = {u2, u3};
                mma16816(s[2*nb2],   ah, bh0); mma16816(s[2*nb2],   ah, bl0);
                mma16816(s[2*nb2],   al, bh0);
                mma16816(s[2*nb2+1], ah, bh1); mma16816(s[2*nb2+1], ah, bl1);
                mma16816(s[2*nb2+1], al, bh1);
            }
        }

        int ktb = t * 64;
        float rm0 = -1e30f, rm1 = -1e30f;
        int i0base = ktb + tc * 2 - qg0 + 2047;
        int i1base = ktb + tc * 2 - qg1 + 2047;
#pragma unroll
        for (int nb = 0; nb < 8; ++nb) {
            int i00 = i0base + nb * 8;
            int i10 = i1base + nb * 8;
            s[nb][0] += bias[i00]; s[nb][1] += bias[i00 + 1];
            s[nb][2] += bias[i10]; s[nb][3] += bias[i10 + 1];
            rm0 = fmaxf(rm0, fmaxf(s[nb][0], s[nb][1]));
            rm1 = fmaxf(rm1, fmaxf(s[nb][2], s[nb][3]));
        }
        rm0 = fmaxf(rm0, __shfl_xor_sync(0xffffffffu, rm0, 1));
        rm0 = fmaxf(rm0, __shfl_xor_sync(0xffffffffu, rm0, 2));
        rm1 = fmaxf(rm1, __shfl_xor_sync(0xffffffffu, rm1, 1));
        rm1 = fmaxf(rm1, __shfl_xor_sync(0xffffffffu, rm1, 2));

        float mn0 = fmaxf(m0, rm0), mn1 = fmaxf(m1, rm1);
        float c0 = __expf(m0 - mn0), c1 = __expf(m1 - mn1);
        m0 = mn0; m1 = mn1;

        float ps0 = 0.f, ps1 = 0.f;
#pragma unroll
        for (int nb = 0; nb < 8; ++nb) {
            s[nb][0] = __expf(s[nb][0] - mn0); s[nb][1] = __expf(s[nb][1] - mn0);
            s[nb][2] = __expf(s[nb][2] - mn1); s[nb][3] = __expf(s[nb][3] - mn1);
            ps0 += s[nb][0] + s[nb][1];
            ps1 += s[nb][2] + s[nb][3];
        }
        ps0 += __shfl_xor_sync(0xffffffffu, ps0, 1);
        ps0 += __shfl_xor_sync(0xffffffffu, ps0, 2);
        ps1 += __shfl_xor_sync(0xffffffffu, ps1, 1);
        ps1 += __shfl_xor_sync(0xffffffffu, ps1, 2);
        l0 = l0 * c0 + ps0; l1 = l1 * c1 + ps1;

#pragma unroll
        for (int j = 0; j < 8; ++j) {
            acc_o[j][0] *= c0; acc_o[j][1] *= c0;
            acc_o[j][2] *= c1; acc_o[j][3] *= c1;
        }

#pragma unroll
        for (int ks = 0; ks < 4; ++ks) {
            uint32_t ap[4];
            __half2 p0 = __floats2half2_rn(s[2*ks][0],   s[2*ks][1]);
            __half2 p1 = __floats2half2_rn(s[2*ks][2],   s[2*ks][3]);
            __half2 p2 = __floats2half2_rn(s[2*ks+1][0], s[2*ks+1][1]);
            __half2 p3 = __floats2half2_rn(s[2*ks+1][2], s[2*ks+1][3]);
            ap[0] = *(uint32_t*)&p0; ap[1] = *(uint32_t*)&p1;
            ap[2] = *(uint32_t*)&p2; ap[3] = *(uint32_t*)&p3;
#pragma unroll
            for (int db2 = 0; db2 < 4; ++db2) {
                uint32_t vAddr = kb + A_V + (ks * 16 + vRowSel) * PQ + db2 * 32 + vColSel;
                uint32_t h0, h1, h2, h3;
                ldm_x4t(vAddr, h0, h1, h2, h3);
                uint32_t v0[2] = {h0, h1}, v1[2] = {h2, h3};
                mma16816h(acc_o[2*db2],   ap, v0);
                mma16816h(acc_o[2*db2+1], ap, v1);
            }
        }
        __syncthreads();
        if (t + 2 < 32) issue_kv(t + 2, t & 1);
    }

    float inv0 = 1.f / l0, inv1 = 1.f / l1;
#pragma unroll
    for (int db = 0; db < 8; ++db) {
        int dcol = hd * DK + db * 8 + tc * 2;
        size_t o0 = ((size_t)b * S_LEN + qg0) * DM + dcol;
        size_t o1 = ((size_t)b * S_LEN + qg1) * DM + dcol;
        __half2 w0 = __floats2half2_rn(acc_o[db][0] * inv0, acc_o[db][1] * inv0);
        __half2 w1 = __floats2half2_rn(acc_o[db][2] * inv1, acc_o[db][3] * inv1);
        *(uint32_t*)(cf + o0) = *(uint32_t*)&w0;
        *(uint32_t*)(cf + o1) = *(uint32_t*)&w1;
    }
}

// ---------------------------------------------------------------------------
extern "C" void kernel_launch(void* const* d_in, const int* in_sizes, int n_in,
                              void* d_out, int out_size)
{
    const float* hidden  = (const float*)d_in[0];
    const float* wq      = (const float*)d_in[1];
    const float* wk      = (const float*)d_in[2];
    const float* wv      = (const float*)d_in[3];
    const float* wo      = (const float*)d_in[4];
    const float* relbias = (const float*)d_in[5];
    float* out = (float*)d_out;

    __nv_bfloat16 *hhi, *hlo, *whi, *wlo, *qh, *ql, *kh, *kl;
    __half *vf, *cf, *wohi, *wolo;
    cudaGetSymbolAddress((void**)&hhi,  g_h_hi);
    cudaGetSymbolAddress((void**)&hlo,  g_h_lo);
    cudaGetSymbolAddress((void**)&whi,  g_wt_hi);
    cudaGetSymbolAddress((void**)&wlo,  g_wt_lo);
    cudaGetSymbolAddress((void**)&wohi, g_wo_hi);
    cudaGetSymbolAddress((void**)&wolo, g_wo_lo);
    cudaGetSymbolAddress((void**)&qh,   g_qh);
    cudaGetSymbolAddress((void**)&ql,   g_ql);
    cudaGetSymbolAddress((void**)&kh,   g_kh);
    cudaGetSymbolAddress((void**)&kl,   g_kl);
    cudaGetSymbolAddress((void**)&vf,   g_vf);
    cudaGetSymbolAddress((void**)&cf,   g_ctx);

    cudaFuncSetAttribute(gemm_qkv, cudaFuncAttributeMaxDynamicSharedMemorySize, QKV_SMEM);
    cudaFuncSetAttribute(gemm_out, cudaFuncAttributeMaxDynamicSharedMemorySize, OUT_SMEM);
    cudaFuncSetAttribute(attn_mma, cudaFuncAttributeMaxDynamicSharedMemorySize, ATT_SMEM);

    split_hidden<<<MT * DM / 1024, 256>>>((const float4*)hidden, hhi, hlo);
    transpose_split<<<dim3(32, 32, 4), dim3(32, 8)>>>(wq, wk, wv, wo, whi, wlo, wohi, wolo);

    gemm_qkv<<<dim3(24, 64), 256, QKV_SMEM>>>(hhi, hlo, whi, wlo, qh, ql, kh, kl, vf);

    attn_mma<<<dim3(16, 64), 256, ATT_SMEM>>>(qh, ql, kh, kl, vf, relbias, cf);

    gemm_out<<<dim3(8, 64), 256, OUT_SMEM>>>(cf, wohi, wolo, out);
}

// round 12
// speedup vs baseline: 4.4070x; 1.1234x over previous
#include <cuda_runtime.h>
#include <cuda_bf16.h>
#include <cuda_fp16.h>
#include <cstdint>

#define BATCH 4
#define S_LEN 2048
#define NH    16
#define DK    64
#define DM    1024
#define MT    (BATCH*S_LEN)
#define BHSZ  ((size_t)BATCH * NH * S_LEN * DK)

__device__ __nv_bfloat16 g_h_hi[MT * DM];
__device__ __nv_bfloat16 g_h_lo[MT * DM];
__device__ __half        g_h_f[MT * DM];
__device__ __nv_bfloat16 g_wt_hi[2 * DM * DM];   // wq|wk transposed, bf16 split
__device__ __nv_bfloat16 g_wt_lo[2 * DM * DM];
__device__ __half        g_wv_hi[DM * DM];       // wv transposed, fp16 split
__device__ __half        g_wv_lo[DM * DM];
__device__ __half        g_wo_f[DM * DM];        // wo transposed, fp16 single
__device__ __nv_bfloat16 g_qh[BHSZ], g_ql[BHSZ];
__device__ __nv_bfloat16 g_kh[BHSZ], g_kl[BHSZ];
__device__ __half        g_vf[BHSZ];
__device__ __half        g_ctx[MT * DM];

// ---------------- helpers ----------------
__device__ __forceinline__ uint32_t smem_u32(const void* p) {
    uint32_t a;
    asm("{ .reg .u64 t; cvta.to.shared.u64 t, %1; cvt.u32.u64 %0, t; }" : "=r"(a) : "l"(p));
    return a;
}
__device__ __forceinline__ void cp16(uint32_t dst, const void* src) {
    asm volatile("cp.async.cg.shared.global [%0], [%1], 16;" :: "r"(dst), "l"(src));
}
__device__ __forceinline__ void cp_commit() { asm volatile("cp.async.commit_group;" ::: "memory"); }
template<int N> __device__ __forceinline__ void cp_wait() {
    asm volatile("cp.async.wait_group %0;" :: "n"(N) : "memory");
}
__device__ __forceinline__ void ldm_x4(uint32_t a, uint32_t& r0, uint32_t& r1,
                                       uint32_t& r2, uint32_t& r3) {
    asm volatile("ldmatrix.sync.aligned.m8n8.x4.shared.b16 {%0,%1,%2,%3}, [%4];"
                 : "=r"(r0), "=r"(r1), "=r"(r2), "=r"(r3) : "r"(a));
}
__device__ __forceinline__ void ldm_x4t(uint32_t a, uint32_t& r0, uint32_t& r1,
                                        uint32_t& r2, uint32_t& r3) {
    asm volatile("ldmatrix.sync.aligned.m8n8.x4.trans.shared.b16 {%0,%1,%2,%3}, [%4];"
                 : "=r"(r0), "=r"(r1), "=r"(r2), "=r"(r3) : "r"(a));
}
__device__ __forceinline__ void ldm_x2(uint32_t a, uint32_t& r0, uint32_t& r1) {
    asm volatile("ldmatrix.sync.aligned.m8n8.x2.shared.b16 {%0,%1}, [%2];"
                 : "=r"(r0), "=r"(r1) : "r"(a));
}
__device__ __forceinline__ void mma16816(float* c, const uint32_t* a, const uint32_t* b) {
    asm volatile("mma.sync.aligned.m16n8k16.row.col.f32.bf16.bf16.f32 "
                 "{%0,%1,%2,%3},{%4,%5,%6,%7},{%8,%9},{%0,%1,%2,%3};"
                 : "+f"(c[0]), "+f"(c[1]), "+f"(c[2]), "+f"(c[3])
                 : "r"(a[0]), "r"(a[1]), "r"(a[2]), "r"(a[3]), "r"(b[0]), "r"(b[1]));
}
__device__ __forceinline__ void mma16816h(float* c, const uint32_t* a, const uint32_t* b) {
    asm volatile("mma.sync.aligned.m16n8k16.row.col.f32.f16.f16.f32 "
                 "{%0,%1,%2,%3},{%4,%5,%6,%7},{%8,%9},{%0,%1,%2,%3};"
                 : "+f"(c[0]), "+f"(c[1]), "+f"(c[2]), "+f"(c[3])
                 : "r"(a[0]), "r"(a[1]), "r"(a[2]), "r"(a[3]), "r"(b[0]), "r"(b[1]));
}
__device__ __forceinline__ void pksplit(float x, float y, uint32_t& hi, uint32_t& lo) {
    __nv_bfloat162 h = __floats2bfloat162_rn(x, y);
    __nv_bfloat162 l = __floats2bfloat162_rn(x - __bfloat162float(h.x),
                                             y - __bfloat162float(h.y));
    hi = *(uint32_t*)&h; lo = *(uint32_t*)&l;
}

// ---------------- prep ----------------
__global__ void split_hidden(const float4* __restrict__ in,
                             __nv_bfloat16* __restrict__ hi, __nv_bfloat16* __restrict__ lo,
                             __half* __restrict__ hf)
{
    int i = blockIdx.x * 256 + threadIdx.x;
    float4 v = in[i];
    float f[4] = {v.x, v.y, v.z, v.w};
    __nv_bfloat16 h4[4], l4[4];
    __half f4[4];
#pragma unroll
    for (int j = 0; j < 4; ++j) {
        h4[j] = __float2bfloat16(f[j]);
        l4[j] = __float2bfloat16(f[j] - __bfloat162float(h4[j]));
        f4[j] = __float2half_rn(f[j]);
    }
    *(uint2*)(hi + (size_t)i * 4) = *(uint2*)h4;
    *(uint2*)(lo + (size_t)i * 4) = *(uint2*)l4;
    *(uint2*)(hf + (size_t)i * 4) = *(uint2*)f4;
}

__global__ void transpose_split(const float* __restrict__ w0, const float* __restrict__ w1,
                                const float* __restrict__ w2, const float* __restrict__ w3,
                                __nv_bfloat16* __restrict__ ohi, __nv_bfloat16* __restrict__ olo,
                                __half* __restrict__ wvh, __half* __restrict__ wvl,
                                __half* __restrict__ wof)
{
    __shared__ float t[32][33];
    const float* w = blockIdx.z == 0 ? w0 : blockIdx.z == 1 ? w1 : blockIdx.z == 2 ? w2 : w3;
    int x0 = blockIdx.x * 32, y0 = blockIdx.y * 32;
    for (int i = threadIdx.y; i < 32; i += 8)
        t[i][threadIdx.x] = w[(size_t)(y0 + i) * DM + x0 + threadIdx.x];
    __syncthreads();
    if (blockIdx.z < 2) {
        size_t zoff = (size_t)blockIdx.z * DM * DM;
        for (int i = threadIdx.y; i < 32; i += 8) {
            float v = t[threadIdx.x][i];
            __nv_bfloat16 hb = __float2bfloat16(v);
            __nv_bfloat16 lb = __float2bfloat16(v - __bfloat162float(hb));
            size_t o = zoff + (size_t)(x0 + i) * DM + y0 + threadIdx.x;
            ohi[o] = hb; olo[o] = lb;
        }
    } else if (blockIdx.z == 2) {
        for (int i = threadIdx.y; i < 32; i += 8) {
            float v = t[threadIdx.x][i];
            __half hh = __float2half_rn(v);
            __half hl = __float2half_rn(v - __half2float(hh));
            size_t o = (size_t)(x0 + i) * DM + y0 + threadIdx.x;
            wvh[o] = hh; wvl[o] = hl;
        }
    } else {
        for (int i = threadIdx.y; i < 32; i += 8) {
            size_t o = (size_t)(x0 + i) * DM + y0 + threadIdx.x;
            wof[o] = __float2half_rn(t[threadIdx.x][i]);
        }
    }
}

// ---------------- fused QKV GEMM: KCH=16, 4-stage, occ 2 ----------------
// q,k: split-bf16 3 MMA. v: fp16 A single + fp16 B split, 2 MMA.
#define KC2   16
#define NK2   (DM / KC2)
#define RW2   48
#define T2    (128 * 48)
#define QST2  (4 * T2)
#define QKV_SMEM (4 * QST2)

__global__ __launch_bounds__(256, 2) void gemm_qkv(
    const __nv_bfloat16* __restrict__ Ah, const __nv_bfloat16* __restrict__ Al,
    const __half* __restrict__ Af,
    const __nv_bfloat16* __restrict__ Wqk_h, const __nv_bfloat16* __restrict__ Wqk_l,
    const __half* __restrict__ Wv_h, const __half* __restrict__ Wv_l,
    __nv_bfloat16* __restrict__ qh, __nv_bfloat16* __restrict__ ql,
    __nv_bfloat16* __restrict__ kh, __nv_bfloat16* __restrict__ kl,
    __half* __restrict__ vf)
{
    extern __shared__ __align__(16) char dsm[];
    const uint32_t base = smem_u32(dsm);
    const int tid = threadIdx.x, lane = tid & 31, wid = tid >> 5;
    const int warpM = wid & 1, warpN = wid >> 1;
    const int m0 = blockIdx.y * 128, n0 = blockIdx.x * 128;
    const int which = n0 >> 10;                 // 0=q, 1=k, 2=v
    const bool isV = (which == 2);

    const int lrow = tid >> 1;
    const int lu   = tid & 1;

    const __nv_bfloat16* Ahp = Ah + (size_t)m0 * DM;
    const __nv_bfloat16* Alp = Al + (size_t)m0 * DM;
    const __half*        Afp = Af + (size_t)m0 * DM;
    const __nv_bfloat16* Bhp = Wqk_h + (size_t)n0 * DM;
    const __nv_bfloat16* Blp = Wqk_l + (size_t)n0 * DM;
    const __half*        Vhp = Wv_h + (size_t)(n0 - 2048) * DM;
    const __half*        Vlp = Wv_l + (size_t)(n0 - 2048) * DM;

    auto issue = [&](int kc, int st) {
        uint32_t sb = base + st * QST2;
        uint32_t d  = sb + lrow * RW2 + lu * 16;
        size_t   go = (size_t)lrow * DM + kc + lu * 8;
        if (isV) {
            cp16(d,          Afp + go);
            cp16(d + 2 * T2, Vhp + go);
            cp16(d + 3 * T2, Vlp + go);
        } else {
            cp16(d,          Ahp + go);
            cp16(d + T2,     Alp + go);
            cp16(d + 2 * T2, Bhp + go);
            cp16(d + 3 * T2, Blp + go);
        }
        cp_commit();
    };

    float acc[4][4][4];
#pragma unroll
    for (int i = 0; i < 4; ++i)
#pragma unroll
        for (int j = 0; j < 4; ++j)
#pragma unroll
            for (int r = 0; r < 4; ++r) acc[i][j][r] = 0.f;

    issue(0, 0); issue(KC2, 1); issue(2 * KC2, 2);

    const uint32_t aRow = (uint32_t)(warpM * 64 + (lane & 15));
    const uint32_t aCol = (uint32_t)(((lane >> 4) & 1) * 16);
    const uint32_t bRow = (uint32_t)(warpN * 32 + (lane & 7));
    const uint32_t bCol = (uint32_t)(((lane >> 3) & 1) * 16);

    if (isV) {
        for (int kt = 0; kt < NK2; ++kt) {
            cp_wait<2>();
            __syncthreads();
            if (kt + 3 < NK2) issue((kt + 3) * KC2, (kt + 3) & 3);
            else cp_commit();

            uint32_t sb = base + (kt & 3) * QST2;
            uint32_t bh[4][2], bl[4][2];
#pragma unroll
            for (int j = 0; j < 4; ++j) {
                uint32_t b = sb + 2 * T2 + (bRow + j * 8) * RW2 + bCol;
                ldm_x2(b,      bh[j][0], bh[j][1]);
                ldm_x2(b + T2, bl[j][0], bl[j][1]);
            }
#pragma unroll
            for (int i = 0; i < 4; ++i) {
                uint32_t a = sb + (aRow + i * 16) * RW2 + aCol;
                uint32_t af[4];
                ldm_x4(a, af[0], af[1], af[2], af[3]);
#pragma unroll
                for (int j = 0; j < 4; ++j) {
                    mma16816h(acc[i][j], af, bh[j]);
                    mma16816h(acc[i][j], af, bl[j]);
                }
            }
        }
    } else {
        for (int kt = 0; kt < NK2; ++kt) {
            cp_wait<2>();
            __syncthreads();
            if (kt + 3 < NK2) issue((kt + 3) * KC2, (kt + 3) & 3);
            else cp_commit();

            uint32_t sb = base + (kt & 3) * QST2;
            uint32_t bh[4][2], bl[4][2];
#pragma unroll
            for (int j = 0; j < 4; ++j) {
                uint32_t b = sb + 2 * T2 + (bRow + j * 8) * RW2 + bCol;
                ldm_x2(b,      bh[j][0], bh[j][1]);
                ldm_x2(b + T2, bl[j][0], bl[j][1]);
            }
#pragma unroll
            for (int i = 0; i < 4; ++i) {
                uint32_t a = sb + (aRow + i * 16) * RW2 + aCol;
                uint32_t ah[4], al[4];
                ldm_x4(a,      ah[0], ah[1], ah[2], ah[3]);
                ldm_x4(a + T2, al[0], al[1], al[2], al[3]);
#pragma unroll
                for (int j = 0; j < 4; ++j) {
                    mma16816(acc[i][j], ah, bh[j]);
                    mma16816(acc[i][j], ah, bl[j]);
                    mma16816(acc[i][j], al, bh[j]);
                }
            }
        }
    }

    __nv_bfloat16* oH = (which == 0) ? qh : kh;
    __nv_bfloat16* oL = (which == 0) ? ql : kl;

#pragma unroll
    for (int i = 0; i < 4; ++i) {
        int mA = m0 + warpM * 64 + i * 16 + (lane >> 2);
        int mB = mA + 8;
#pragma unroll
        for (int j = 0; j < 4; ++j) {
            int n = n0 + warpN * 32 + j * 8 + ((lane & 3) << 1);
            int nn = n & 1023;
            int hh = nn >> 6, dd = nn & 63;
            int bA = mA >> 11, sA = mA & (S_LEN - 1);
            int bB = mB >> 11, sB = mB & (S_LEN - 1);
            size_t oA = ((size_t)(bA * NH + hh) * S_LEN + sA) * DK + dd;
            size_t oB = ((size_t)(bB * NH + hh) * S_LEN + sB) * DK + dd;
            if (isV) {
                __half2 v0 = __floats2half2_rn(acc[i][j][0], acc[i][j][1]);
                __half2 v1 = __floats2half2_rn(acc[i][j][2], acc[i][j][3]);
                *(uint32_t*)(vf + oA) = *(uint32_t*)&v0;
                *(uint32_t*)(vf + oB) = *(uint32_t*)&v1;
            } else {
                uint32_t h0, l0, h1, l1;
                pksplit(acc[i][j][0], acc[i][j][1], h0, l0);
                pksplit(acc[i][j][2], acc[i][j][3], h1, l1);
                *(uint32_t*)(oH + oA) = h0; *(uint32_t*)(oL + oA) = l0;
                *(uint32_t*)(oH + oB) = h1; *(uint32_t*)(oL + oB) = l1;
            }
        }
    }
}

// ---------------- out-projection GEMM: fp16 single x single, 1 MMA ----------------
#define OST3 (2 * T2)                  // A, B = 12288 per stage
#define OUT_SMEM (4 * OST3)            // 49152

__global__ __launch_bounds__(256, 2) void gemm_out(
    const __half* __restrict__ Af, const __half* __restrict__ Bf,
    float* __restrict__ outF)
{
    extern __shared__ __align__(16) char dsm[];
    const uint32_t base = smem_u32(dsm);
    const int tid = threadIdx.x, lane = tid & 31, wid = tid >> 5;
    const int warpM = wid & 1, warpN = wid >> 1;
    const int m0 = blockIdx.y * 128, n0 = blockIdx.x * 128;

    const __half* Ap = Af + (size_t)m0 * DM;
    const __half* Bp = Bf + (size_t)n0 * DM;

    const int lrow = tid >> 1;
    const int lu   = tid & 1;

    auto issue = [&](int kc, int st) {
        uint32_t sb = base + st * OST3;
        uint32_t d  = sb + lrow * RW2 + lu * 16;
        size_t   go = (size_t)lrow * DM + kc + lu * 8;
        cp16(d,      Ap + go);
        cp16(d + T2, Bp + go);
        cp_commit();
    };

    float acc[4][4][4];
#pragma unroll
    for (int i = 0; i < 4; ++i)
#pragma unroll
        for (int j = 0; j < 4; ++j)
#pragma unroll
            for (int r = 0; r < 4; ++r) acc[i][j][r] = 0.f;

    issue(0, 0); issue(KC2, 1); issue(2 * KC2, 2);

    const uint32_t aRow = (uint32_t)(warpM * 64 + (lane & 15));
    const uint32_t aCol = (uint32_t)(((lane >> 4) & 1) * 16);
    const uint32_t bRow = (uint32_t)(warpN * 32 + (lane & 7));
    const uint32_t bCol = (uint32_t)(((lane >> 3) & 1) * 16);

    for (int kt = 0; kt < NK2; ++kt) {
        cp_wait<2>();
        __syncthreads();
        if (kt + 3 < NK2) issue((kt + 3) * KC2, (kt + 3) & 3);
        else cp_commit();

        uint32_t sb = base + (kt & 3) * OST3;
        uint32_t bf[4][2];
#pragma unroll
        for (int j = 0; j < 4; ++j) {
            uint32_t b = sb + T2 + (bRow + j * 8) * RW2 + bCol;
            ldm_x2(b, bf[j][0], bf[j][1]);
        }
#pragma unroll
        for (int i = 0; i < 4; ++i) {
            uint32_t a = sb + (aRow + i * 16) * RW2 + aCol;
            uint32_t af[4];
            ldm_x4(a, af[0], af[1], af[2], af[3]);
#pragma unroll
            for (int j = 0; j < 4; ++j)
                mma16816h(acc[i][j], af, bf[j]);
        }
    }

#pragma unroll
    for (int i = 0; i < 4; ++i) {
        int mA = m0 + warpM * 64 + i * 16 + (lane >> 2);
        int mB = mA + 8;
#pragma unroll
        for (int j = 0; j < 4; ++j) {
            int n = n0 + warpN * 32 + j * 8 + ((lane & 3) << 1);
            *(float2*)(outF + (size_t)mA * DM + n) = make_float2(acc[i][j][0], acc[i][j][1]);
            *(float2*)(outF + (size_t)mB * DM + n) = make_float2(acc[i][j][2], acc[i][j][3]);
        }
    }
}

// ---------------- HMMA flash attention (unchanged from R10/11) ----------------
__device__ __forceinline__ int t5_bucket(int delta)
{
    int base = (delta > 0) ? 16 : 0;
    int a = delta < 0 ? -delta : delta;
    int bucket;
    if (a < 8) bucket = a;
    else if (a >= 128) bucket = 15;
    else {
        int t = 31 - __clz(a);
        int f = (a * a >= (1 << (2 * t + 1))) ? 1 : 0;
        bucket = 2 + 2 * t + f;
        if (bucket > 15) bucket = 15;
    }
    return base + bucket;
}

#define PQ        144
#define A_QH      0
#define A_QL      18432
#define A_BUF     36864
#define A_BUFSZ   27648
#define A_KH      0
#define A_KL      9216
#define A_V       18432
#define A_BIAS    (A_BUF + 2*A_BUFSZ)
#define BIAS_N    4096
#define ATT_SMEM  (A_BIAS + BIAS_N*4)

__global__ __launch_bounds__(256, 2) void attn_mma(
    const __nv_bfloat16* __restrict__ qh, const __nv_bfloat16* __restrict__ ql,
    const __nv_bfloat16* __restrict__ kh, const __nv_bfloat16* __restrict__ kl,
    const __half* __restrict__ vf, const float* __restrict__ rel_bias,
    __half* __restrict__ cf)
{
    extern __shared__ __align__(16) char asmem[];
    const uint32_t base = smem_u32(asmem);
    float* bias = (float*)(asmem + A_BIAS);

    const int tid = threadIdx.x, lane = tid & 31, wid = tid >> 5;
    const int bh = blockIdx.y;
    const int hd = bh & (NH - 1);
    const int b  = bh >> 4;
    const int q0 = blockIdx.x * 128;
    const size_t bo = (size_t)bh * S_LEN * DK;

    for (int i = tid; i < BIAS_N; i += 256)
        bias[i] = rel_bias[t5_bucket(i - 2047) * NH + hd];

#pragma unroll
    for (int it = 0; it < 8; ++it) {
        int idx = tid + it * 256;
        int sub = idx & 1023, row = sub >> 3, u = sub & 7;
        const __nv_bfloat16* src = (it < 4) ? qh : ql;
        cp16(base + (it < 4 ? A_QH : A_QL) + row * PQ + u * 16,
             src + bo + (size_t)(q0 + row) * DK + u * 8);
    }
    auto issue_kv = [&](int t, int buf) {
        uint32_t bb = base + A_BUF + buf * A_BUFSZ;
#pragma unroll
        for (int it = 0; it < 6; ++it) {
            int idx = tid + it * 256;
            int sub = idx & 511, row = sub >> 3, u = sub & 7;
            if (it < 4) {
                const __nv_bfloat16* src = (it < 2) ? kh : kl;
                uint32_t toff = (it < 2) ? A_KH : A_KL;
                cp16(bb + toff + row * PQ + u * 16,
                     src + bo + (size_t)(t * 64 + row) * DK + u * 8);
            } else {
                cp16(bb + A_V + row * PQ + u * 16,
                     vf + bo + (size_t)(t * 64 + row) * DK + u * 8);
            }
        }
        cp_commit();
    };
    issue_kv(0, 0);
    issue_kv(1, 1);

    const int g  = lane >> 2;
    const int tc = lane & 3;
    const int qg0 = q0 + wid * 16 + g;
    const int qg1 = qg0 + 8;

    float acc_o[8][4];
#pragma unroll
    for (int j = 0; j < 8; ++j)
#pragma unroll
        for (int r = 0; r < 4; ++r) acc_o[j][r] = 0.f;
    float m0 = -1e30f, m1 = -1e30f, l0 = 0.f, l1 = 0.f;

    const uint32_t aBase = base + (wid * 16 + (lane & 15)) * PQ + ((lane >> 4) & 1) * 16;
    const uint32_t bRowSel = ((lane >> 4) & 1) * 8 + (lane & 7);
    const uint32_t bColSel = ((lane >> 3) & 1) * 16;
    const uint32_t vRowSel = ((lane >> 3) & 1) * 8 + (lane & 7);
    const uint32_t vColSel = ((lane >> 4) & 1) * 16;

    for (int t = 0; t < 32; ++t) {
        if (t + 2 < 32) cp_wait<1>(); else cp_wait<0>();
        __syncthreads();
        uint32_t kb = base + A_BUF + (t & 1) * A_BUFSZ;

        float s[8][4];
#pragma unroll
        for (int j = 0; j < 8; ++j)
#pragma unroll
            for (int r = 0; r < 4; ++r) s[j][r] = 0.f;

#pragma unroll
        for (int ks = 0; ks < 4; ++ks) {
            uint32_t ah[4], al[4];
            ldm_x4(aBase + ks * 32,        ah[0], ah[1], ah[2], ah[3]);
            ldm_x4(aBase + A_QL + ks * 32, al[0], al[1], al[2], al[3]);
#pragma unroll
            for (int nb2 = 0; nb2 < 4; ++nb2) {
                uint32_t bAddr = kb + A_KH + (nb2 * 16 + bRowSel) * PQ + bColSel + ks * 32;
                uint32_t h0, h1, h2, h3, u0, u1, u2, u3;
                ldm_x4(bAddr,                 h0, h1, h2, h3);
                ldm_x4(bAddr + (A_KL - A_KH), u0, u1, u2, u3);
                uint32_t bh0[2] = {h0, h1}, bh1[2] = {h2, h3};
                uint32_t bl0[2] = {u0, u1}, bl1[2] = {u2, u3};
                mma16816(s[2*nb2],   ah, bh0); mma16816(s[2*nb2],   ah, bl0);
                mma16816(s[2*nb2],   al, bh0);
                mma16816(s[2*nb2+1], ah, bh1); mma16816(s[2*nb2+1], ah, bl1);
                mma16816(s[2*nb2+1], al, bh1);
            }
        }

        int ktb = t * 64;
        float rm0 = -1e30f, rm1 = -1e30f;
        int i0base = ktb + tc * 2 - qg0 + 2047;
        int i1base = ktb + tc * 2 - qg1 + 2047;
#pragma unroll
        for (int nb = 0; nb < 8; ++nb) {
            int i00 = i0base + nb * 8;
            int i10 = i1base + nb * 8;
            s[nb][0] += bias[i00]; s[nb][1] += bias[i00 + 1];
            s[nb][2] += bias[i10]; s[nb][3] += bias[i10 + 1];
            rm0 = fmaxf(rm0, fmaxf(s[nb][0], s[nb][1]));
            rm1 = fmaxf(rm1, fmaxf(s[nb][2], s[nb][3]));
        }
        rm0 = fmaxf(rm0, __shfl_xor_sync(0xffffffffu, rm0, 1));
        rm0 = fmaxf(rm0, __shfl_xor_sync(0xffffffffu, rm0, 2));
        rm1 = fmaxf(rm1, __shfl_xor_sync(0xffffffffu, rm1, 1));
        rm1 = fmaxf(rm1, __shfl_xor_sync(0xffffffffu, rm1, 2));

        float mn0 = fmaxf(m0, rm0), mn1 = fmaxf(m1, rm1);
        float c0 = __expf(m0 - mn0), c1 = __expf(m1 - mn1);
        m0 = mn0; m1 = mn1;

        float ps0 = 0.f, ps1 = 0.f;
#pragma unroll
        for (int nb = 0; nb < 8; ++nb) {
            s[nb][0] = __expf(s[nb][0] - mn0); s[nb][1] = __expf(s[nb][1] - mn0);
            s[nb][2] = __expf(s[nb][2] - mn1); s[nb][3] = __expf(s[nb][3] - mn1);
            ps0 += s[nb][0] + s[nb][1];
            ps1 += s[nb][2] + s[nb][3];
        }
        ps0 += __shfl_xor_sync(0xffffffffu, ps0, 1);
        ps0 += __shfl_xor_sync(0xffffffffu, ps0, 2);
        ps1 += __shfl_xor_sync(0xffffffffu, ps1, 1);
        ps1 += __shfl_xor_sync(0xffffffffu, ps1, 2);
        l0 = l0 * c0 + ps0; l1 = l1 * c1 + ps1;

#pragma unroll
        for (int j = 0; j < 8; ++j) {
            acc_o[j][0] *= c0; acc_o[j][1] *= c0;
            acc_o[j][2] *= c1; acc_o[j][3] *= c1;
        }

#pragma unroll
        for (int ks = 0; ks < 4; ++ks) {
            uint32_t ap[4];
            __half2 p0 = __floats2half2_rn(s[2*ks][0],   s[2*ks][1]);
            __half2 p1 = __floats2half2_rn(s[2*ks][2],   s[2*ks][3]);
            __half2 p2 = __floats2half2_rn(s[2*ks+1][0], s[2*ks+1][1]);
            __half2 p3 = __floats2half2_rn(s[2*ks+1][2], s[2*ks+1][3]);
            ap[0] = *(uint32_t*)&p0; ap[1] = *(uint32_t*)&p1;
            ap[2] = *(uint32_t*)&p2; ap[3] = *(uint32_t*)&p3;
#pragma unroll
            for (int db2 = 0; db2 < 4; ++db2) {
                uint32_t vAddr = kb + A_V + (ks * 16 + vRowSel) * PQ + db2 * 32 + vColSel;
                uint32_t h0, h1, h2, h3;
                ldm_x4t(vAddr, h0, h1, h2, h3);
                uint32_t v0[2] = {h0, h1}, v1[2] = {h2, h3};
                mma16816h(acc_o[2*db2],   ap, v0);
                mma16816h(acc_o[2*db2+1], ap, v1);
            }
        }
        __syncthreads();
        if (t + 2 < 32) issue_kv(t + 2, t & 1);
    }

    float inv0 = 1.f / l0, inv1 = 1.f / l1;
#pragma unroll
    for (int db = 0; db < 8; ++db) {
        int dcol = hd * DK + db * 8 + tc * 2;
        size_t o0 = ((size_t)b * S_LEN + qg0) * DM + dcol;
        size_t o1 = ((size_t)b * S_LEN + qg1) * DM + dcol;
        __half2 w0 = __floats2half2_rn(acc_o[db][0] * inv0, acc_o[db][1] * inv0);
        __half2 w1 = __floats2half2_rn(acc_o[db][2] * inv1, acc_o[db][3] * inv1);
        *(uint32_t*)(cf + o0) = *(uint32_t*)&w0;
        *(uint32_t*)(cf + o1) = *(uint32_t*)&w1;
    }
}

// ---------------------------------------------------------------------------
extern "C" void kernel_launch(void* const* d_in, const int* in_sizes, int n_in,
                              void* d_out, int out_size)
{
    const float* hidden  = (const float*)d_in[0];
    const float* wq      = (const float*)d_in[1];
    const float* wk      = (const float*)d_in[2];
    const float* wv      = (const float*)d_in[3];
    const float* wo      = (const float*)d_in[4];
    const float* relbias = (const float*)d_in[5];
    float* out = (float*)d_out;

    __nv_bfloat16 *hhi, *hlo, *whi, *wlo, *qh, *ql, *kh, *kl;
    __half *hf, *wvh, *wvl, *wof, *vf, *cf;
    cudaGetSymbolAddress((void**)&hhi, g_h_hi);
    cudaGetSymbolAddress((void**)&hlo, g_h_lo);
    cudaGetSymbolAddress((void**)&hf,  g_h_f);
    cudaGetSymbolAddress((void**)&whi, g_wt_hi);
    cudaGetSymbolAddress((void**)&wlo, g_wt_lo);
    cudaGetSymbolAddress((void**)&wvh, g_wv_hi);
    cudaGetSymbolAddress((void**)&wvl, g_wv_lo);
    cudaGetSymbolAddress((void**)&wof, g_wo_f);
    cudaGetSymbolAddress((void**)&qh,  g_qh);
    cudaGetSymbolAddress((void**)&ql,  g_ql);
    cudaGetSymbolAddress((void**)&kh,  g_kh);
    cudaGetSymbolAddress((void**)&kl,  g_kl);
    cudaGetSymbolAddress((void**)&vf,  g_vf);
    cudaGetSymbolAddress((void**)&cf,  g_ctx);

    cudaFuncSetAttribute(gemm_qkv, cudaFuncAttributeMaxDynamicSharedMemorySize, QKV_SMEM);
    cudaFuncSetAttribute(gemm_out, cudaFuncAttributeMaxDynamicSharedMemorySize, OUT_SMEM);
    cudaFuncSetAttribute(attn_mma, cudaFuncAttributeMaxDynamicSharedMemorySize, ATT_SMEM);

    split_hidden<<<MT * DM / 1024, 256>>>((const float4*)hidden, hhi, hlo, hf);
    transpose_split<<<dim3(32, 32, 4), dim3(32, 8)>>>(wq, wk, wv, wo, whi, wlo, wvh, wvl, wof);

    gemm_qkv<<<dim3(24, 64), 256, QKV_SMEM>>>(hhi, hlo, hf, whi, wlo, wvh, wvl,
                                              qh, ql, kh, kl, vf);

    attn_mma<<<dim3(16, 64), 256, ATT_SMEM>>>(qh, ql, kh, kl, vf, relbias, cf);

    gemm_out<<<dim3(8, 64), 256, OUT_SMEM>>>(cf, wof, out);
}

// round 13
// speedup vs baseline: 4.4375x; 1.0069x over previous
#include <cuda_runtime.h>
#include <cuda_bf16.h>
#include <cuda_fp16.h>
#include <cstdint>

#define BATCH 4
#define S_LEN 2048
#define NH    16
#define DK    64
#define DM    1024
#define MT    (BATCH*S_LEN)
#define BHSZ  ((size_t)BATCH * NH * S_LEN * DK)
#define LOG2E 1.4426950408889634f

__device__ __nv_bfloat16 g_h_hi[MT * DM];
__device__ __nv_bfloat16 g_h_lo[MT * DM];
__device__ __half        g_h_f[MT * DM];
__device__ __nv_bfloat16 g_wt_hi[2 * DM * DM];
__device__ __nv_bfloat16 g_wt_lo[2 * DM * DM];
__device__ __half        g_wv_hi[DM * DM];
__device__ __half        g_wv_lo[DM * DM];
__device__ __half        g_wo_f[DM * DM];
__device__ __nv_bfloat16 g_qh[BHSZ], g_ql[BHSZ];
__device__ __nv_bfloat16 g_kh[BHSZ], g_kl[BHSZ];   // pre-scaled by log2(e)
__device__ __half        g_vf[BHSZ];
__device__ __half        g_ctx[MT * DM];

// ---------------- helpers ----------------
__device__ __forceinline__ uint32_t smem_u32(const void* p) {
    uint32_t a;
    asm("{ .reg .u64 t; cvta.to.shared.u64 t, %1; cvt.u32.u64 %0, t; }" : "=r"(a) : "l"(p));
    return a;
}
__device__ __forceinline__ float ex2f(float x) {
    float y;
    asm("ex2.approx.f32 %0, %1;" : "=f"(y) : "f"(x));
    return y;
}
__device__ __forceinline__ void cp16(uint32_t dst, const void* src) {
    asm volatile("cp.async.cg.shared.global [%0], [%1], 16;" :: "r"(dst), "l"(src));
}
__device__ __forceinline__ void cp_commit() { asm volatile("cp.async.commit_group;" ::: "memory"); }
template<int N> __device__ __forceinline__ void cp_wait() {
    asm volatile("cp.async.wait_group %0;" :: "n"(N) : "memory");
}
__device__ __forceinline__ void ldm_x4(uint32_t a, uint32_t& r0, uint32_t& r1,
                                       uint32_t& r2, uint32_t& r3) {
    asm volatile("ldmatrix.sync.aligned.m8n8.x4.shared.b16 {%0,%1,%2,%3}, [%4];"
                 : "=r"(r0), "=r"(r1), "=r"(r2), "=r"(r3) : "r"(a));
}
__device__ __forceinline__ void ldm_x4t(uint32_t a, uint32_t& r0, uint32_t& r1,
                                        uint32_t& r2, uint32_t& r3) {
    asm volatile("ldmatrix.sync.aligned.m8n8.x4.trans.shared.b16 {%0,%1,%2,%3}, [%4];"
                 : "=r"(r0), "=r"(r1), "=r"(r2), "=r"(r3) : "r"(a));
}
__device__ __forceinline__ void ldm_x2(uint32_t a, uint32_t& r0, uint32_t& r1) {
    asm volatile("ldmatrix.sync.aligned.m8n8.x2.shared.b16 {%0,%1}, [%2];"
                 : "=r"(r0), "=r"(r1) : "r"(a));
}
__device__ __forceinline__ void mma16816(float* c, const uint32_t* a, const uint32_t* b) {
    asm volatile("mma.sync.aligned.m16n8k16.row.col.f32.bf16.bf16.f32 "
                 "{%0,%1,%2,%3},{%4,%5,%6,%7},{%8,%9},{%0,%1,%2,%3};"
                 : "+f"(c[0]), "+f"(c[1]), "+f"(c[2]), "+f"(c[3])
                 : "r"(a[0]), "r"(a[1]), "r"(a[2]), "r"(a[3]), "r"(b[0]), "r"(b[1]));
}
__device__ __forceinline__ void mma16816h(float* c, const uint32_t* a, const uint32_t* b) {
    asm volatile("mma.sync.aligned.m16n8k16.row.col.f32.f16.f16.f32 "
                 "{%0,%1,%2,%3},{%4,%5,%6,%7},{%8,%9},{%0,%1,%2,%3};"
                 : "+f"(c[0]), "+f"(c[1]), "+f"(c[2]), "+f"(c[3])
                 : "r"(a[0]), "r"(a[1]), "r"(a[2]), "r"(a[3]), "r"(b[0]), "r"(b[1]));
}
__device__ __forceinline__ void pksplit(float x, float y, uint32_t& hi, uint32_t& lo) {
    __nv_bfloat162 h = __floats2bfloat162_rn(x, y);
    __nv_bfloat162 l = __floats2bfloat162_rn(x - __bfloat162float(h.x),
                                             y - __bfloat162float(h.y));
    hi = *(uint32_t*)&h; lo = *(uint32_t*)&l;
}

// ---------------- prep ----------------
__global__ void split_hidden(const float4* __restrict__ in,
                             __nv_bfloat16* __restrict__ hi, __nv_bfloat16* __restrict__ lo,
                             __half* __restrict__ hf)
{
    int i = blockIdx.x * 256 + threadIdx.x;
    float4 v = in[i];
    float f[4] = {v.x, v.y, v.z, v.w};
    __nv_bfloat16 h4[4], l4[4];
    __half f4[4];
#pragma unroll
    for (int j = 0; j < 4; ++j) {
        h4[j] = __float2bfloat16(f[j]);
        l4[j] = __float2bfloat16(f[j] - __bfloat162float(h4[j]));
        f4[j] = __float2half_rn(f[j]);
    }
    *(uint2*)(hi + (size_t)i * 4) = *(uint2*)h4;
    *(uint2*)(lo + (size_t)i * 4) = *(uint2*)l4;
    *(uint2*)(hf + (size_t)i * 4) = *(uint2*)f4;
}

__global__ void transpose_split(const float* __restrict__ w0, const float* __restrict__ w1,
                                const float* __restrict__ w2, const float* __restrict__ w3,
                                __nv_bfloat16* __restrict__ ohi, __nv_bfloat16* __restrict__ olo,
                                __half* __restrict__ wvh, __half* __restrict__ wvl,
                                __half* __restrict__ wof)
{
    __shared__ float t[32][33];
    const float* w = blockIdx.z == 0 ? w0 : blockIdx.z == 1 ? w1 : blockIdx.z == 2 ? w2 : w3;
    int x0 = blockIdx.x * 32, y0 = blockIdx.y * 32;
    for (int i = threadIdx.y; i < 32; i += 8)
        t[i][threadIdx.x] = w[(size_t)(y0 + i) * DM + x0 + threadIdx.x];
    __syncthreads();
    if (blockIdx.z < 2) {
        size_t zoff = (size_t)blockIdx.z * DM * DM;
        for (int i = threadIdx.y; i < 32; i += 8) {
            float v = t[threadIdx.x][i];
            __nv_bfloat16 hb = __float2bfloat16(v);
            __nv_bfloat16 lb = __float2bfloat16(v - __bfloat162float(hb));
            size_t o = zoff + (size_t)(x0 + i) * DM + y0 + threadIdx.x;
            ohi[o] = hb; olo[o] = lb;
        }
    } else if (blockIdx.z == 2) {
        for (int i = threadIdx.y; i < 32; i += 8) {
            float v = t[threadIdx.x][i];
            __half hh = __float2half_rn(v);
            __half hl = __float2half_rn(v - __half2float(hh));
            size_t o = (size_t)(x0 + i) * DM + y0 + threadIdx.x;
            wvh[o] = hh; wvl[o] = hl;
        }
    } else {
        for (int i = threadIdx.y; i < 32; i += 8) {
            size_t o = (size_t)(x0 + i) * DM + y0 + threadIdx.x;
            wof[o] = __float2half_rn(t[threadIdx.x][i]);
        }
    }
}

// ---------------- fused QKV GEMM: KCH=16, 4-stage, occ 2 ----------------
#define KC2   16
#define NK2   (DM / KC2)
#define RW2   48
#define T2    (128 * 48)
#define QST2  (4 * T2)
#define QKV_SMEM (4 * QST2)

__global__ __launch_bounds__(256, 2) void gemm_qkv(
    const __nv_bfloat16* __restrict__ Ah, const __nv_bfloat16* __restrict__ Al,
    const __half* __restrict__ Af,
    const __nv_bfloat16* __restrict__ Wqk_h, const __nv_bfloat16* __restrict__ Wqk_l,
    const __half* __restrict__ Wv_h, const __half* __restrict__ Wv_l,
    __nv_bfloat16* __restrict__ qh, __nv_bfloat16* __restrict__ ql,
    __nv_bfloat16* __restrict__ kh, __nv_bfloat16* __restrict__ kl,
    __half* __restrict__ vf)
{
    extern __shared__ __align__(16) char dsm[];
    const uint32_t base = smem_u32(dsm);
    const int tid = threadIdx.x, lane = tid & 31, wid = tid >> 5;
    const int warpM = wid & 1, warpN = wid >> 1;
    const int m0 = blockIdx.y * 128, n0 = blockIdx.x * 128;
    const int which = n0 >> 10;
    const bool isV = (which == 2);

    const int lrow = tid >> 1;
    const int lu   = tid & 1;

    const __nv_bfloat16* Ahp = Ah + (size_t)m0 * DM;
    const __nv_bfloat16* Alp = Al + (size_t)m0 * DM;
    const __half*        Afp = Af + (size_t)m0 * DM;
    const __nv_bfloat16* Bhp = Wqk_h + (size_t)n0 * DM;
    const __nv_bfloat16* Blp = Wqk_l + (size_t)n0 * DM;
    const __half*        Vhp = Wv_h + (size_t)(n0 - 2048) * DM;
    const __half*        Vlp = Wv_l + (size_t)(n0 - 2048) * DM;

    auto issue = [&](int kc, int st) {
        uint32_t sb = base + st * QST2;
        uint32_t d  = sb + lrow * RW2 + lu * 16;
        size_t   go = (size_t)lrow * DM + kc + lu * 8;
        if (isV) {
            cp16(d,          Afp + go);
            cp16(d + 2 * T2, Vhp + go);
            cp16(d + 3 * T2, Vlp + go);
        } else {
            cp16(d,          Ahp + go);
            cp16(d + T2,     Alp + go);
            cp16(d + 2 * T2, Bhp + go);
            cp16(d + 3 * T2, Blp + go);
        }
        cp_commit();
    };

    float acc[4][4][4];
#pragma unroll
    for (int i = 0; i < 4; ++i)
#pragma unroll
        for (int j = 0; j < 4; ++j)
#pragma unroll
            for (int r = 0; r < 4; ++r) acc[i][j][r] = 0.f;

    issue(0, 0); issue(KC2, 1); issue(2 * KC2, 2);

    const uint32_t aRow = (uint32_t)(warpM * 64 + (lane & 15));
    const uint32_t aCol = (uint32_t)(((lane >> 4) & 1) * 16);
    const uint32_t bRow = (uint32_t)(warpN * 32 + (lane & 7));
    const uint32_t bCol = (uint32_t)(((lane >> 3) & 1) * 16);

    if (isV) {
        for (int kt = 0; kt < NK2; ++kt) {
            cp_wait<2>();
            __syncthreads();
            if (kt + 3 < NK2) issue((kt + 3) * KC2, (kt + 3) & 3);
            else cp_commit();

            uint32_t sb = base + (kt & 3) * QST2;
            uint32_t bh[4][2], bl[4][2];
#pragma unroll
            for (int j = 0; j < 4; ++j) {
                uint32_t b = sb + 2 * T2 + (bRow + j * 8) * RW2 + bCol;
                ldm_x2(b,      bh[j][0], bh[j][1]);
                ldm_x2(b + T2, bl[j][0], bl[j][1]);
            }
#pragma unroll
            for (int i = 0; i < 4; ++i) {
                uint32_t a = sb + (aRow + i * 16) * RW2 + aCol;
                uint32_t af[4];
                ldm_x4(a, af[0], af[1], af[2], af[3]);
#pragma unroll
                for (int j = 0; j < 4; ++j) {
                    mma16816h(acc[i][j], af, bh[j]);
                    mma16816h(acc[i][j], af, bl[j]);
                }
            }
        }
    } else {
        for (int kt = 0; kt < NK2; ++kt) {
            cp_wait<2>();
            __syncthreads();
            if (kt + 3 < NK2) issue((kt + 3) * KC2, (kt + 3) & 3);
            else cp_commit();

            uint32_t sb = base + (kt & 3) * QST2;
            uint32_t bh[4][2], bl[4][2];
#pragma unroll
            for (int j = 0; j < 4; ++j) {
                uint32_t b = sb + 2 * T2 + (bRow + j * 8) * RW2 + bCol;
                ldm_x2(b,      bh[j][0], bh[j][1]);
                ldm_x2(b + T2, bl[j][0], bl[j][1]);
            }
#pragma unroll
            for (int i = 0; i < 4; ++i) {
                uint32_t a = sb + (aRow + i * 16) * RW2 + aCol;
                uint32_t ah[4], al[4];
                ldm_x4(a,      ah[0], ah[1], ah[2], ah[3]);
                ldm_x4(a + T2, al[0], al[1], al[2], al[3]);
#pragma unroll
                for (int j = 0; j < 4; ++j) {
                    mma16816(acc[i][j], ah, bh[j]);
                    mma16816(acc[i][j], ah, bl[j]);
                    mma16816(acc[i][j], al, bh[j]);
                }
            }
        }
    }

    __nv_bfloat16* oH = (which == 0) ? qh : kh;
    __nv_bfloat16* oL = (which == 0) ? ql : kl;
    const float sc = (which == 1) ? LOG2E : 1.f;   // pre-scale K by log2(e)

#pragma unroll
    for (int i = 0; i < 4; ++i) {
        int mA = m0 + warpM * 64 + i * 16 + (lane >> 2);
        int mB = mA + 8;
#pragma unroll
        for (int j = 0; j < 4; ++j) {
            int n = n0 + warpN * 32 + j * 8 + ((lane & 3) << 1);
            int nn = n & 1023;
            int hh = nn >> 6, dd = nn & 63;
            int bA = mA >> 11, sA = mA & (S_LEN - 1);
            int bB = mB >> 11, sB = mB & (S_LEN - 1);
            size_t oA = ((size_t)(bA * NH + hh) * S_LEN + sA) * DK + dd;
            size_t oB = ((size_t)(bB * NH + hh) * S_LEN + sB) * DK + dd;
            if (isV) {
                __half2 v0 = __floats2half2_rn(acc[i][j][0], acc[i][j][1]);
                __half2 v1 = __floats2half2_rn(acc[i][j][2], acc[i][j][3]);
                *(uint32_t*)(vf + oA) = *(uint32_t*)&v0;
                *(uint32_t*)(vf + oB) = *(uint32_t*)&v1;
            } else {
                uint32_t h0, l0, h1, l1;
                pksplit(acc[i][j][0] * sc, acc[i][j][1] * sc, h0, l0);
                pksplit(acc[i][j][2] * sc, acc[i][j][3] * sc, h1, l1);
                *(uint32_t*)(oH + oA) = h0; *(uint32_t*)(oL + oA) = l0;
                *(uint32_t*)(oH + oB) = h1; *(uint32_t*)(oL + oB) = l1;
            }
        }
    }
}

// ---------------- out-projection GEMM: fp16 single x single ----------------
#define OST3 (2 * T2)
#define OUT_SMEM (4 * OST3)

__global__ __launch_bounds__(256, 2) void gemm_out(
    const __half* __restrict__ Af, const __half* __restrict__ Bf,
    float* __restrict__ outF)
{
    extern __shared__ __align__(16) char dsm[];
    const uint32_t base = smem_u32(dsm);
    const int tid = threadIdx.x, lane = tid & 31, wid = tid >> 5;
    const int warpM = wid & 1, warpN = wid >> 1;
    const int m0 = blockIdx.y * 128, n0 = blockIdx.x * 128;

    const __half* Ap = Af + (size_t)m0 * DM;
    const __half* Bp = Bf + (size_t)n0 * DM;

    const int lrow = tid >> 1;
    const int lu   = tid & 1;

    auto issue = [&](int kc, int st) {
        uint32_t sb = base + st * OST3;
        uint32_t d  = sb + lrow * RW2 + lu * 16;
        size_t   go = (size_t)lrow * DM + kc + lu * 8;
        cp16(d,      Ap + go);
        cp16(d + T2, Bp + go);
        cp_commit();
    };

    float acc[4][4][4];
#pragma unroll
    for (int i = 0; i < 4; ++i)
#pragma unroll
        for (int j = 0; j < 4; ++j)
#pragma unroll
            for (int r = 0; r < 4; ++r) acc[i][j][r] = 0.f;

    issue(0, 0); issue(KC2, 1); issue(2 * KC2, 2);

    const uint32_t aRow = (uint32_t)(warpM * 64 + (lane & 15));
    const uint32_t aCol = (uint32_t)(((lane >> 4) & 1) * 16);
    const uint32_t bRow = (uint32_t)(warpN * 32 + (lane & 7));
    const uint32_t bCol = (uint32_t)(((lane >> 3) & 1) * 16);

    for (int kt = 0; kt < NK2; ++kt) {
        cp_wait<2>();
        __syncthreads();
        if (kt + 3 < NK2) issue((kt + 3) * KC2, (kt + 3) & 3);
        else cp_commit();

        uint32_t sb = base + (kt & 3) * OST3;
        uint32_t bf[4][2];
#pragma unroll
        for (int j = 0; j < 4; ++j) {
            uint32_t b = sb + T2 + (bRow + j * 8) * RW2 + bCol;
            ldm_x2(b, bf[j][0], bf[j][1]);
        }
#pragma unroll
        for (int i = 0; i < 4; ++i) {
            uint32_t a = sb + (aRow + i * 16) * RW2 + aCol;
            uint32_t af[4];
            ldm_x4(a, af[0], af[1], af[2], af[3]);
#pragma unroll
            for (int j = 0; j < 4; ++j)
                mma16816h(acc[i][j], af, bf[j]);
        }
    }

#pragma unroll
    for (int i = 0; i < 4; ++i) {
        int mA = m0 + warpM * 64 + i * 16 + (lane >> 2);
        int mB = mA + 8;
#pragma unroll
        for (int j = 0; j < 4; ++j) {
            int n = n0 + warpN * 32 + j * 8 + ((lane & 3) << 1);
            *(float2*)(outF + (size_t)mA * DM + n) = make_float2(acc[i][j][0], acc[i][j][1]);
            *(float2*)(outF + (size_t)mB * DM + n) = make_float2(acc[i][j][2], acc[i][j][3]);
        }
    }
}

// ---------------- HMMA flash attention (log2-domain softmax, rescale skip) ----------------
__device__ __forceinline__ int t5_bucket(int delta)
{
    int base = (delta > 0) ? 16 : 0;
    int a = delta < 0 ? -delta : delta;
    int bucket;
    if (a < 8) bucket = a;
    else if (a >= 128) bucket = 15;
    else {
        int t = 31 - __clz(a);
        int f = (a * a >= (1 << (2 * t + 1))) ? 1 : 0;
        bucket = 2 + 2 * t + f;
        if (bucket > 15) bucket = 15;
    }
    return base + bucket;
}

#define PQ        144
#define A_QH      0
#define A_QL      18432
#define A_BUF     36864
#define A_BUFSZ   27648
#define A_KH      0
#define A_KL      9216
#define A_V       18432
#define A_BIAS    (A_BUF + 2*A_BUFSZ)
#define BIAS_N    4096
#define ATT_SMEM  (A_BIAS + BIAS_N*4)

__global__ __launch_bounds__(256, 2) void attn_mma(
    const __nv_bfloat16* __restrict__ qh, const __nv_bfloat16* __restrict__ ql,
    const __nv_bfloat16* __restrict__ kh, const __nv_bfloat16* __restrict__ kl,
    const __half* __restrict__ vf, const float* __restrict__ rel_bias,
    __half* __restrict__ cf)
{
    extern __shared__ __align__(16) char asmem[];
    const uint32_t base = smem_u32(asmem);
    float* bias = (float*)(asmem + A_BIAS);

    const int tid = threadIdx.x, lane = tid & 31, wid = tid >> 5;
    const int bh = blockIdx.y;
    const int hd = bh & (NH - 1);
    const int b  = bh >> 4;
    const int q0 = blockIdx.x * 128;
    const size_t bo = (size_t)bh * S_LEN * DK;

    for (int i = tid; i < BIAS_N; i += 256)
        bias[i] = rel_bias[t5_bucket(i - 2047) * NH + hd] * LOG2E;

#pragma unroll
    for (int it = 0; it < 8; ++it) {
        int idx = tid + it * 256;
        int sub = idx & 1023, row = sub >> 3, u = sub & 7;
        const __nv_bfloat16* src = (it < 4) ? qh : ql;
        cp16(base + (it < 4 ? A_QH : A_QL) + row * PQ + u * 16,
             src + bo + (size_t)(q0 + row) * DK + u * 8);
    }
    auto issue_kv = [&](int t, int buf) {
        uint32_t bb = base + A_BUF + buf * A_BUFSZ;
#pragma unroll
        for (int it = 0; it < 6; ++it) {
            int idx = tid + it * 256;
            int sub = idx & 511, row = sub >> 3, u = sub & 7;
            if (it < 4) {
                const __nv_bfloat16* src = (it < 2) ? kh : kl;
                uint32_t toff = (it < 2) ? A_KH : A_KL;
                cp16(bb + toff + row * PQ + u * 16,
                     src + bo + (size_t)(t * 64 + row) * DK + u * 8);
            } else {
                cp16(bb + A_V + row * PQ + u * 16,
                     vf + bo + (size_t)(t * 64 + row) * DK + u * 8);
            }
        }
        cp_commit();
    };
    issue_kv(0, 0);
    issue_kv(1, 1);

    const int g  = lane >> 2;
    const int tc = lane & 3;
    const int qg0 = q0 + wid * 16 + g;
    const int qg1 = qg0 + 8;

    float acc_o[8][4];
#pragma unroll
    for (int j = 0; j < 8; ++j)
#pragma unroll
        for (int r = 0; r < 4; ++r) acc_o[j][r] = 0.f;
    float m0 = -1e30f, m1 = -1e30f, l0 = 0.f, l1 = 0.f;

    const uint32_t aBase = base + (wid * 16 + (lane & 15)) * PQ + ((lane >> 4) & 1) * 16;
    const uint32_t bRowSel = ((lane >> 4) & 1) * 8 + (lane & 7);
    const uint32_t bColSel = ((lane >> 3) & 1) * 16;
    const uint32_t vRowSel = ((lane >> 3) & 1) * 8 + (lane & 7);
    const uint32_t vColSel = ((lane >> 4) & 1) * 16;

    for (int t = 0; t < 32; ++t) {
        if (t + 2 < 32) cp_wait<1>(); else cp_wait<0>();
        __syncthreads();
        uint32_t kb = base + A_BUF + (t & 1) * A_BUFSZ;

        // ---- S' = Q (K·log2e)^T (split-bf16, 3 mma) ----
        float s[8][4];
#pragma unroll
        for (int j = 0; j < 8; ++j)
#pragma unroll
            for (int r = 0; r < 4; ++r) s[j][r] = 0.f;

#pragma unroll
        for (int ks = 0; ks < 4; ++ks) {
            uint32_t ah[4], al[4];
            ldm_x4(aBase + ks * 32,        ah[0], ah[1], ah[2], ah[3]);
            ldm_x4(aBase + A_QL + ks * 32, al[0], al[1], al[2], al[3]);
#pragma unroll
            for (int nb2 = 0; nb2 < 4; ++nb2) {
                uint32_t bAddr = kb + A_KH + (nb2 * 16 + bRowSel) * PQ + bColSel + ks * 32;
                uint32_t h0, h1, h2, h3, u0, u1, u2, u3;
                ldm_x4(bAddr,                 h0, h1, h2, h3);
                ldm_x4(bAddr + (A_KL - A_KH), u0, u1, u2, u3);
                uint32_t bh0[2] = {h0, h1}, bh1[2] = {h2, h3};
                uint32_t bl0[2] = {u0, u1}, bl1[2] = {u2, u3};
                mma16816(s[2*nb2],   ah, bh0); mma16816(s[2*nb2],   ah, bl0);
                mma16816(s[2*nb2],   al, bh0);
                mma16816(s[2*nb2+1], ah, bh1); mma16816(s[2*nb2+1], ah, bl1);
                mma16816(s[2*nb2+1], al, bh1);
            }
        }

        // ---- bias + online softmax (log2 domain) ----
        int ktb = t * 64;
        float rm0 = -1e30f, rm1 = -1e30f;
        int i0base = ktb + tc * 2 - qg0 + 2047;
        int i1base = ktb + tc * 2 - qg1 + 2047;
#pragma unroll
        for (int nb = 0; nb < 8; ++nb) {
            int i00 = i0base + nb * 8;
            int i10 = i1base + nb * 8;
            s[nb][0] += bias[i00]; s[nb][1] += bias[i00 + 1];
            s[nb][2] += bias[i10]; s[nb][3] += bias[i10 + 1];
            rm0 = fmaxf(rm0, fmaxf(s[nb][0], s[nb][1]));
            rm1 = fmaxf(rm1, fmaxf(s[nb][2], s[nb][3]));
        }
        rm0 = fmaxf(rm0, __shfl_xor_sync(0xffffffffu, rm0, 1));
        rm0 = fmaxf(rm0, __shfl_xor_sync(0xffffffffu, rm0, 2));
        rm1 = fmaxf(rm1, __shfl_xor_sync(0xffffffffu, rm1, 1));
        rm1 = fmaxf(rm1, __shfl_xor_sync(0xffffffffu, rm1, 2));

        bool upd = __any_sync(0xffffffffu, (rm0 > m0) | (rm1 > m1));
        if (upd) {
            float mn0 = fmaxf(m0, rm0), mn1 = fmaxf(m1, rm1);
            float c0 = ex2f(m0 - mn0), c1 = ex2f(m1 - mn1);
            m0 = mn0; m1 = mn1;
            l0 *= c0; l1 *= c1;
#pragma unroll
            for (int j = 0; j < 8; ++j) {
                acc_o[j][0] *= c0; acc_o[j][1] *= c0;
                acc_o[j][2] *= c1; acc_o[j][3] *= c1;
            }
        }

        float ps0 = 0.f, ps1 = 0.f;
#pragma unroll
        for (int nb = 0; nb < 8; ++nb) {
            s[nb][0] = ex2f(s[nb][0] - m0); s[nb][1] = ex2f(s[nb][1] - m0);
            s[nb][2] = ex2f(s[nb][2] - m1); s[nb][3] = ex2f(s[nb][3] - m1);
            ps0 += s[nb][0] + s[nb][1];
            ps1 += s[nb][2] + s[nb][3];
        }
        ps0 += __shfl_xor_sync(0xffffffffu, ps0, 1);
        ps0 += __shfl_xor_sync(0xffffffffu, ps0, 2);
        ps1 += __shfl_xor_sync(0xffffffffu, ps1, 1);
        ps1 += __shfl_xor_sync(0xffffffffu, ps1, 2);
        l0 += ps0; l1 += ps1;

        // ---- O += P V (fp16 mma) ----
#pragma unroll
        for (int ks = 0; ks < 4; ++ks) {
            uint32_t ap[4];
            __half2 p0 = __floats2half2_rn(s[2*ks][0],   s[2*ks][1]);
            __half2 p1 = __floats2half2_rn(s[2*ks][2],   s[2*ks][3]);
            __half2 p2 = __floats2half2_rn(s[2*ks+1][0], s[2*ks+1][1]);
            __half2 p3 = __floats2half2_rn(s[2*ks+1][2], s[2*ks+1][3]);
            ap[0] = *(uint32_t*)&p0; ap[1] = *(uint32_t*)&p1;
            ap[2] = *(uint32_t*)&p2; ap[3] = *(uint32_t*)&p3;
#pragma unroll
            for (int db2 = 0; db2 < 4; ++db2) {
                uint32_t vAddr = kb + A_V + (ks * 16 + vRowSel) * PQ + db2 * 32 + vColSel;
                uint32_t h0, h1, h2, h3;
                ldm_x4t(vAddr, h0, h1, h2, h3);
                uint32_t v0[2] = {h0, h1}, v1[2] = {h2, h3};
                mma16816h(acc_o[2*db2],   ap, v0);
                mma16816h(acc_o[2*db2+1], ap, v1);
            }
        }
        __syncthreads();
        if (t + 2 < 32) issue_kv(t + 2, t & 1);
    }

    float inv0 = 1.f / l0, inv1 = 1.f / l1;
#pragma unroll
    for (int db = 0; db < 8; ++db) {
        int dcol = hd * DK + db * 8 + tc * 2;
        size_t o0 = ((size_t)b * S_LEN + qg0) * DM + dcol;
        size_t o1 = ((size_t)b * S_LEN + qg1) * DM + dcol;
        __half2 w0 = __floats2half2_rn(acc_o[db][0] * inv0, acc_o[db][1] * inv0);
        __half2 w1 = __floats2half2_rn(acc_o[db][2] * inv1, acc_o[db][3] * inv1);
        *(uint32_t*)(cf + o0) = *(uint32_t*)&w0;
        *(uint32_t*)(cf + o1) = *(uint32_t*)&w1;
    }
}

// ---------------------------------------------------------------------------
extern "C" void kernel_launch(void* const* d_in, const int* in_sizes, int n_in,
                              void* d_out, int out_size)
{
    const float* hidden  = (const float*)d_in[0];
    const float* wq      = (const float*)d_in[1];
    const float* wk      = (const float*)d_in[2];
    const float* wv      = (const float*)d_in[3];
    const float* wo      = (const float*)d_in[4];
    const float* relbias = (const float*)d_in[5];
    float* out = (float*)d_out;

    __nv_bfloat16 *hhi, *hlo, *whi, *wlo, *qh, *ql, *kh, *kl;
    __half *hf, *wvh, *wvl, *wof, *vf, *cf;
    cudaGetSymbolAddress((void**)&hhi, g_h_hi);
    cudaGetSymbolAddress((void**)&hlo, g_h_lo);
    cudaGetSymbolAddress((void**)&hf,  g_h_f);
    cudaGetSymbolAddress((void**)&whi, g_wt_hi);
    cudaGetSymbolAddress((void**)&wlo, g_wt_lo);
    cudaGetSymbolAddress((void**)&wvh, g_wv_hi);
    cudaGetSymbolAddress((void**)&wvl, g_wv_lo);
    cudaGetSymbolAddress((void**)&wof, g_wo_f);
    cudaGetSymbolAddress((void**)&qh,  g_qh);
    cudaGetSymbolAddress((void**)&ql,  g_ql);
    cudaGetSymbolAddress((void**)&kh,  g_kh);
    cudaGetSymbolAddress((void**)&kl,  g_kl);
    cudaGetSymbolAddress((void**)&vf,  g_vf);
    cudaGetSymbolAddress((void**)&cf,  g_ctx);

    cudaFuncSetAttribute(gemm_qkv, cudaFuncAttributeMaxDynamicSharedMemorySize, QKV_SMEM);
    cudaFuncSetAttribute(gemm_out, cudaFuncAttributeMaxDynamicSharedMemorySize, OUT_SMEM);
    cudaFuncSetAttribute(attn_mma, cudaFuncAttributeMaxDynamicSharedMemorySize, ATT_SMEM);

    split_hidden<<<MT * DM / 1024, 256>>>((const float4*)hidden, hhi, hlo, hf);
    transpose_split<<<dim3(32, 32, 4), dim3(32, 8)>>>(wq, wk, wv, wo, whi, wlo, wvh, wvl, wof);

    gemm_qkv<<<dim3(24, 64), 256, QKV_SMEM>>>(hhi, hlo, hf, whi, wlo, wvh, wvl,
                                              qh, ql, kh, kl, vf);

    attn_mma<<<dim3(16, 64), 256, ATT_SMEM>>>(qh, ql, kh, kl, vf, relbias, cf);

    gemm_out<<<dim3(8, 64), 256, OUT_SMEM>>>(cf, wof, out);
}

// round 14
// speedup vs baseline: 4.4815x; 1.0099x over previous
#include <cuda_runtime.h>
#include <cuda_bf16.h>
#include <cuda_fp16.h>
#include <cstdint>

#define BATCH 4
#define S_LEN 2048
#define NH    16
#define DK    64
#define DM    1024
#define MT    (BATCH*S_LEN)
#define BHSZ  ((size_t)BATCH * NH * S_LEN * DK)
#define LOG2E 1.4426950408889634f

__device__ __nv_bfloat16 g_h_hi[MT * DM];
__device__ __nv_bfloat16 g_h_lo[MT * DM];
__device__ __half        g_h_f[MT * DM];
__device__ __nv_bfloat16 g_wt_hi[2 * DM * DM];
__device__ __nv_bfloat16 g_wt_lo[2 * DM * DM];
__device__ __half        g_wv_hi[DM * DM];
__device__ __half        g_wv_lo[DM * DM];
__device__ __half        g_wo_f[DM * DM];
__device__ __nv_bfloat16 g_qh[BHSZ], g_ql[BHSZ];
__device__ __nv_bfloat16 g_kh[BHSZ], g_kl[BHSZ];   // K pre-scaled by log2(e)
__device__ __half        g_vf[BHSZ];
__device__ __half        g_ctx[MT * DM];

// ---------------- helpers ----------------
__device__ __forceinline__ uint32_t smem_u32(const void* p) {
    uint32_t a;
    asm("{ .reg .u64 t; cvta.to.shared.u64 t, %1; cvt.u32.u64 %0, t; }" : "=r"(a) : "l"(p));
    return a;
}
__device__ __forceinline__ float ex2f(float x) {
    float y;
    asm("ex2.approx.f32 %0, %1;" : "=f"(y) : "f"(x));
    return y;
}
__device__ __forceinline__ void cp16(uint32_t dst, const void* src) {
    asm volatile("cp.async.cg.shared.global [%0], [%1], 16;" :: "r"(dst), "l"(src));
}
__device__ __forceinline__ void cp_commit() { asm volatile("cp.async.commit_group;" ::: "memory"); }
template<int N> __device__ __forceinline__ void cp_wait() {
    asm volatile("cp.async.wait_group %0;" :: "n"(N) : "memory");
}
__device__ __forceinline__ void ldm_x4(uint32_t a, uint32_t& r0, uint32_t& r1,
                                       uint32_t& r2, uint32_t& r3) {
    asm volatile("ldmatrix.sync.aligned.m8n8.x4.shared.b16 {%0,%1,%2,%3}, [%4];"
                 : "=r"(r0), "=r"(r1), "=r"(r2), "=r"(r3) : "r"(a));
}
__device__ __forceinline__ void ldm_x4t(uint32_t a, uint32_t& r0, uint32_t& r1,
                                        uint32_t& r2, uint32_t& r3) {
    asm volatile("ldmatrix.sync.aligned.m8n8.x4.trans.shared.b16 {%0,%1,%2,%3}, [%4];"
                 : "=r"(r0), "=r"(r1), "=r"(r2), "=r"(r3) : "r"(a));
}
__device__ __forceinline__ void mma16816(float* c, const uint32_t* a, const uint32_t* b) {
    asm volatile("mma.sync.aligned.m16n8k16.row.col.f32.bf16.bf16.f32 "
                 "{%0,%1,%2,%3},{%4,%5,%6,%7},{%8,%9},{%0,%1,%2,%3};"
                 : "+f"(c[0]), "+f"(c[1]), "+f"(c[2]), "+f"(c[3])
                 : "r"(a[0]), "r"(a[1]), "r"(a[2]), "r"(a[3]), "r"(b[0]), "r"(b[1]));
}
__device__ __forceinline__ void mma16816h(float* c, const uint32_t* a, const uint32_t* b) {
    asm volatile("mma.sync.aligned.m16n8k16.row.col.f32.f16.f16.f32 "
                 "{%0,%1,%2,%3},{%4,%5,%6,%7},{%8,%9},{%0,%1,%2,%3};"
                 : "+f"(c[0]), "+f"(c[1]), "+f"(c[2]), "+f"(c[3])
                 : "r"(a[0]), "r"(a[1]), "r"(a[2]), "r"(a[3]), "r"(b[0]), "r"(b[1]));
}
__device__ __forceinline__ void pksplit(float x, float y, uint32_t& hi, uint32_t& lo) {
    __nv_bfloat162 h = __floats2bfloat162_rn(x, y);
    __nv_bfloat162 l = __floats2bfloat162_rn(x - __bfloat162float(h.x),
                                             y - __bfloat162float(h.y));
    hi = *(uint32_t*)&h; lo = *(uint32_t*)&l;
}

// ---------------- fused prep: split_hidden + transpose_split in ONE launch ----------------
#define SPLIT_BLOCKS (MT * DM / 1024)    // 8192
#define PREP_BLOCKS  (SPLIT_BLOCKS + 4096)

__global__ void prep_all(const float4* __restrict__ in,
                         __nv_bfloat16* __restrict__ hi, __nv_bfloat16* __restrict__ lo,
                         __half* __restrict__ hf,
                         const float* __restrict__ w0, const float* __restrict__ w1,
                         const float* __restrict__ w2, const float* __restrict__ w3,
                         __nv_bfloat16* __restrict__ ohi, __nv_bfloat16* __restrict__ olo,
                         __half* __restrict__ wvh, __half* __restrict__ wvl,
                         __half* __restrict__ wof)
{
    __shared__ float t[32][33];
    const int tid = threadIdx.x;
    if (blockIdx.x < SPLIT_BLOCKS) {
        int i = blockIdx.x * 256 + tid;
        float4 v = in[i];
        float f[4] = {v.x, v.y, v.z, v.w};
        __nv_bfloat16 h4[4], l4[4];
        __half f4[4];
#pragma unroll
        for (int j = 0; j < 4; ++j) {
            h4[j] = __float2bfloat16(f[j]);
            l4[j] = __float2bfloat16(f[j] - __bfloat162float(h4[j]));
            f4[j] = __float2half_rn(f[j]);
        }
        *(uint2*)(hi + (size_t)i * 4) = *(uint2*)h4;
        *(uint2*)(lo + (size_t)i * 4) = *(uint2*)l4;
        *(uint2*)(hf + (size_t)i * 4) = *(uint2*)f4;
        return;
    }
    int tb = blockIdx.x - SPLIT_BLOCKS;      // 0..4095
    int z  = tb >> 10;                       // 0..3
    int bx = tb & 31, by = (tb >> 5) & 31;
    int tx = tid & 31, ty = tid >> 5;        // 32 x 8
    const float* w = z == 0 ? w0 : z == 1 ? w1 : z == 2 ? w2 : w3;
    int x0 = bx * 32, y0 = by * 32;
    for (int i = ty; i < 32; i += 8)
        t[i][tx] = w[(size_t)(y0 + i) * DM + x0 + tx];
    __syncthreads();
    if (z < 2) {
        size_t zoff = (size_t)z * DM * DM;
        for (int i = ty; i < 32; i += 8) {
            float v = t[tx][i];
            __nv_bfloat16 hb = __float2bfloat16(v);
            __nv_bfloat16 lb = __float2bfloat16(v - __bfloat162float(hb));
            size_t o = zoff + (size_t)(x0 + i) * DM + y0 + tx;
            ohi[o] = hb; olo[o] = lb;
        }
    } else if (z == 2) {
        for (int i = ty; i < 32; i += 8) {
            float v = t[tx][i];
            __half hh = __float2half_rn(v);
            __half hl = __float2half_rn(v - __half2float(hh));
            size_t o = (size_t)(x0 + i) * DM + y0 + tx;
            wvh[o] = hh; wvl[o] = hl;
        }
    } else {
        for (int i = ty; i < 32; i += 8) {
            size_t o = (size_t)(x0 + i) * DM + y0 + tx;
            wof[o] = __float2half_rn(t[tx][i]);
        }
    }
}

// ---------------- fused QKV GEMM: KCH=16, 4-stage, occ 2, x4 B-pair loads ----------------
#define KC2   16
#define NK2   (DM / KC2)
#define RW2   48
#define T2    (128 * 48)
#define QST2  (4 * T2)
#define QKV_SMEM (4 * QST2)

__global__ __launch_bounds__(256, 2) void gemm_qkv(
    const __nv_bfloat16* __restrict__ Ah, const __nv_bfloat16* __restrict__ Al,
    const __half* __restrict__ Af,
    const __nv_bfloat16* __restrict__ Wqk_h, const __nv_bfloat16* __restrict__ Wqk_l,
    const __half* __restrict__ Wv_h, const __half* __restrict__ Wv_l,
    __nv_bfloat16* __restrict__ qh, __nv_bfloat16* __restrict__ ql,
    __nv_bfloat16* __restrict__ kh, __nv_bfloat16* __restrict__ kl,
    __half* __restrict__ vf)
{
    extern __shared__ __align__(16) char dsm[];
    const uint32_t base = smem_u32(dsm);
    const int tid = threadIdx.x, lane = tid & 31, wid = tid >> 5;
    const int warpM = wid & 1, warpN = wid >> 1;
    const int m0 = blockIdx.y * 128, n0 = blockIdx.x * 128;
    const int which = n0 >> 10;
    const bool isV = (which == 2);

    const int lrow = tid >> 1;
    const int lu   = tid & 1;

    const __nv_bfloat16* Ahp = Ah + (size_t)m0 * DM;
    const __nv_bfloat16* Alp = Al + (size_t)m0 * DM;
    const __half*        Afp = Af + (size_t)m0 * DM;
    const __nv_bfloat16* Bhp = Wqk_h + (size_t)n0 * DM;
    const __nv_bfloat16* Blp = Wqk_l + (size_t)n0 * DM;
    const __half*        Vhp = Wv_h + (size_t)(n0 - 2048) * DM;
    const __half*        Vlp = Wv_l + (size_t)(n0 - 2048) * DM;

    auto issue = [&](int kc, int st) {
        uint32_t sb = base + st * QST2;
        uint32_t d  = sb + lrow * RW2 + lu * 16;
        size_t   go = (size_t)lrow * DM + kc + lu * 8;
        if (isV) {
            cp16(d,          Afp + go);
            cp16(d + 2 * T2, Vhp + go);
            cp16(d + 3 * T2, Vlp + go);
        } else {
            cp16(d,          Ahp + go);
            cp16(d + T2,     Alp + go);
            cp16(d + 2 * T2, Bhp + go);
            cp16(d + 3 * T2, Blp + go);
        }
        cp_commit();
    };

    float acc[4][4][4];
#pragma unroll
    for (int i = 0; i < 4; ++i)
#pragma unroll
        for (int j = 0; j < 4; ++j)
#pragma unroll
            for (int r = 0; r < 4; ++r) acc[i][j][r] = 0.f;

    issue(0, 0); issue(KC2, 1); issue(2 * KC2, 2);

    const uint32_t aRow  = (uint32_t)(warpM * 64 + (lane & 15));
    const uint32_t aCol  = (uint32_t)(((lane >> 4) & 1) * 16);
    // x4 B-pair addressing (two n8 blocks per ldmatrix, attention-verified)
    const uint32_t bRowX = (uint32_t)(warpN * 32 + ((lane >> 4) & 1) * 8 + (lane & 7));
    const uint32_t bColX = (uint32_t)(((lane >> 3) & 1) * 16);

    if (isV) {
        for (int kt = 0; kt < NK2; ++kt) {
            cp_wait<2>();
            __syncthreads();
            if (kt + 3 < NK2) issue((kt + 3) * KC2, (kt + 3) & 3);
            else cp_commit();

            uint32_t sb = base + (kt & 3) * QST2;
            uint32_t bh[4][2], bl[4][2];
#pragma unroll
            for (int jp = 0; jp < 2; ++jp) {
                uint32_t b = sb + 2 * T2 + (bRowX + jp * 16) * RW2 + bColX;
                ldm_x4(b,      bh[2*jp][0], bh[2*jp][1], bh[2*jp+1][0], bh[2*jp+1][1]);
                ldm_x4(b + T2, bl[2*jp][0], bl[2*jp][1], bl[2*jp+1][0], bl[2*jp+1][1]);
            }
#pragma unroll
            for (int i = 0; i < 4; ++i) {
                uint32_t a = sb + (aRow + i * 16) * RW2 + aCol;
                uint32_t af[4];
                ldm_x4(a, af[0], af[1], af[2], af[3]);
#pragma unroll
                for (int j = 0; j < 4; ++j) {
                    mma16816h(acc[i][j], af, bh[j]);
                    mma16816h(acc[i][j], af, bl[j]);
                }
            }
        }
    } else {
        for (int kt = 0; kt < NK2; ++kt) {
            cp_wait<2>();
            __syncthreads();
            if (kt + 3 < NK2) issue((kt + 3) * KC2, (kt + 3) & 3);
            else cp_commit();

            uint32_t sb = base + (kt & 3) * QST2;
            uint32_t bh[4][2], bl[4][2];
#pragma unroll
            for (int jp = 0; jp < 2; ++jp) {
                uint32_t b = sb + 2 * T2 + (bRowX + jp * 16) * RW2 + bColX;
                ldm_x4(b,      bh[2*jp][0], bh[2*jp][1], bh[2*jp+1][0], bh[2*jp+1][1]);
                ldm_x4(b + T2, bl[2*jp][0], bl[2*jp][1], bl[2*jp+1][0], bl[2*jp+1][1]);
            }
#pragma unroll
            for (int i = 0; i < 4; ++i) {
                uint32_t a = sb + (aRow + i * 16) * RW2 + aCol;
                uint32_t ah[4], al[4];
                ldm_x4(a,      ah[0], ah[1], ah[2], ah[3]);
                ldm_x4(a + T2, al[0], al[1], al[2], al[3]);
#pragma unroll
                for (int j = 0; j < 4; ++j) {
                    mma16816(acc[i][j], ah, bh[j]);
                    mma16816(acc[i][j], ah, bl[j]);
                    mma16816(acc[i][j], al, bh[j]);
                }
            }
        }
    }

    __nv_bfloat16* oH = (which == 0) ? qh : kh;
    __nv_bfloat16* oL = (which == 0) ? ql : kl;
    const float sc = (which == 1) ? LOG2E : 1.f;

#pragma unroll
    for (int i = 0; i < 4; ++i) {
        int mA = m0 + warpM * 64 + i * 16 + (lane >> 2);
        int mB = mA + 8;
#pragma unroll
        for (int j = 0; j < 4; ++j) {
            int n = n0 + warpN * 32 + j * 8 + ((lane & 3) << 1);
            int nn = n & 1023;
            int hh = nn >> 6, dd = nn & 63;
            int bA = mA >> 11, sA = mA & (S_LEN - 1);
            int bB = mB >> 11, sB = mB & (S_LEN - 1);
            size_t oA = ((size_t)(bA * NH + hh) * S_LEN + sA) * DK + dd;
            size_t oB = ((size_t)(bB * NH + hh) * S_LEN + sB) * DK + dd;
            if (isV) {
                __half2 v0 = __floats2half2_rn(acc[i][j][0], acc[i][j][1]);
                __half2 v1 = __floats2half2_rn(acc[i][j][2], acc[i][j][3]);
                *(uint32_t*)(vf + oA) = *(uint32_t*)&v0;
                *(uint32_t*)(vf + oB) = *(uint32_t*)&v1;
            } else {
                uint32_t h0, l0, h1, l1;
                pksplit(acc[i][j][0] * sc, acc[i][j][1] * sc, h0, l0);
                pksplit(acc[i][j][2] * sc, acc[i][j][3] * sc, h1, l1);
                *(uint32_t*)(oH + oA) = h0; *(uint32_t*)(oL + oA) = l0;
                *(uint32_t*)(oH + oB) = h1; *(uint32_t*)(oL + oB) = l1;
            }
        }
    }
}

// ---------------- out-projection GEMM: fp16 single x single, x4 B-pairs ----------------
#define OST3 (2 * T2)
#define OUT_SMEM (4 * OST3)

__global__ __launch_bounds__(256, 2) void gemm_out(
    const __half* __restrict__ Af, const __half* __restrict__ Bf,
    float* __restrict__ outF)
{
    extern __shared__ __align__(16) char dsm[];
    const uint32_t base = smem_u32(dsm);
    const int tid = threadIdx.x, lane = tid & 31, wid = tid >> 5;
    const int warpM = wid & 1, warpN = wid >> 1;
    const int m0 = blockIdx.y * 128, n0 = blockIdx.x * 128;

    const __half* Ap = Af + (size_t)m0 * DM;
    const __half* Bp = Bf + (size_t)n0 * DM;

    const int lrow = tid >> 1;
    const int lu   = tid & 1;

    auto issue = [&](int kc, int st) {
        uint32_t sb = base + st * OST3;
        uint32_t d  = sb + lrow * RW2 + lu * 16;
        size_t   go = (size_t)lrow * DM + kc + lu * 8;
        cp16(d,      Ap + go);
        cp16(d + T2, Bp + go);
        cp_commit();
    };

    float acc[4][4][4];
#pragma unroll
    for (int i = 0; i < 4; ++i)
#pragma unroll
        for (int j = 0; j < 4; ++j)
#pragma unroll
            for (int r = 0; r < 4; ++r) acc[i][j][r] = 0.f;

    issue(0, 0); issue(KC2, 1); issue(2 * KC2, 2);

    const uint32_t aRow  = (uint32_t)(warpM * 64 + (lane & 15));
    const uint32_t aCol  = (uint32_t)(((lane >> 4) & 1) * 16);
    const uint32_t bRowX = (uint32_t)(warpN * 32 + ((lane >> 4) & 1) * 8 + (lane & 7));
    const uint32_t bColX = (uint32_t)(((lane >> 3) & 1) * 16);

    for (int kt = 0; kt < NK2; ++kt) {
        cp_wait<2>();
        __syncthreads();
        if (kt + 3 < NK2) issue((kt + 3) * KC2, (kt + 3) & 3);
        else cp_commit();

        uint32_t sb = base + (kt & 3) * OST3;
        uint32_t bf[4][2];
#pragma unroll
        for (int jp = 0; jp < 2; ++jp) {
            uint32_t b = sb + T2 + (bRowX + jp * 16) * RW2 + bColX;
            ldm_x4(b, bf[2*jp][0], bf[2*jp][1], bf[2*jp+1][0], bf[2*jp+1][1]);
        }
#pragma unroll
        for (int i = 0; i < 4; ++i) {
            uint32_t a = sb + (aRow + i * 16) * RW2 + aCol;
            uint32_t af[4];
            ldm_x4(a, af[0], af[1], af[2], af[3]);
#pragma unroll
            for (int j = 0; j < 4; ++j)
                mma16816h(acc[i][j], af, bf[j]);
        }
    }

#pragma unroll
    for (int i = 0; i < 4; ++i) {
        int mA = m0 + warpM * 64 + i * 16 + (lane >> 2);
        int mB = mA + 8;
#pragma unroll
        for (int j = 0; j < 4; ++j) {
            int n = n0 + warpN * 32 + j * 8 + ((lane & 3) << 1);
            *(float2*)(outF + (size_t)mA * DM + n) = make_float2(acc[i][j][0], acc[i][j][1]);
            *(float2*)(outF + (size_t)mB * DM + n) = make_float2(acc[i][j][2], acc[i][j][3]);
        }
    }
}

// ---------------- HMMA flash attention (unchanged from R13) ----------------
__device__ __forceinline__ int t5_bucket(int delta)
{
    int base = (delta > 0) ? 16 : 0;
    int a = delta < 0 ? -delta : delta;
    int bucket;
    if (a < 8) bucket = a;
    else if (a >= 128) bucket = 15;
    else {
        int t = 31 - __clz(a);
        int f = (a * a >= (1 << (2 * t + 1))) ? 1 : 0;
        bucket = 2 + 2 * t + f;
        if (bucket > 15) bucket = 15;
    }
    return base + bucket;
}

#define PQ        144
#define A_QH      0
#define A_QL      18432
#define A_BUF     36864
#define A_BUFSZ   27648
#define A_KH      0
#define A_KL      9216
#define A_V       18432
#define A_BIAS    (A_BUF + 2*A_BUFSZ)
#define BIAS_N    4096
#define ATT_SMEM  (A_BIAS + BIAS_N*4)

__global__ __launch_bounds__(256, 2) void attn_mma(
    const __nv_bfloat16* __restrict__ qh, const __nv_bfloat16* __restrict__ ql,
    const __nv_bfloat16* __restrict__ kh, const __nv_bfloat16* __restrict__ kl,
    const __half* __restrict__ vf, const float* __restrict__ rel_bias,
    __half* __restrict__ cf)
{
    extern __shared__ __align__(16) char asmem[];
    const uint32_t base = smem_u32(asmem);
    float* bias = (float*)(asmem + A_BIAS);

    const int tid = threadIdx.x, lane = tid & 31, wid = tid >> 5;
    const int bh = blockIdx.y;
    const int hd = bh & (NH - 1);
    const int b  = bh >> 4;
    const int q0 = blockIdx.x * 128;
    const size_t bo = (size_t)bh * S_LEN * DK;

    for (int i = tid; i < BIAS_N; i += 256)
        bias[i] = rel_bias[t5_bucket(i - 2047) * NH + hd] * LOG2E;

#pragma unroll
    for (int it = 0; it < 8; ++it) {
        int idx = tid + it * 256;
        int sub = idx & 1023, row = sub >> 3, u = sub & 7;
        const __nv_bfloat16* src = (it < 4) ? qh : ql;
        cp16(base + (it < 4 ? A_QH : A_QL) + row * PQ + u * 16,
             src + bo + (size_t)(q0 + row) * DK + u * 8);
    }
    auto issue_kv = [&](int t, int buf) {
        uint32_t bb = base + A_BUF + buf * A_BUFSZ;
#pragma unroll
        for (int it = 0; it < 6; ++it) {
            int idx = tid + it * 256;
            int sub = idx & 511, row = sub >> 3, u = sub & 7;
            if (it < 4) {
                const __nv_bfloat16* src = (it < 2) ? kh : kl;
                uint32_t toff = (it < 2) ? A_KH : A_KL;
                cp16(bb + toff + row * PQ + u * 16,
                     src + bo + (size_t)(t * 64 + row) * DK + u * 8);
            } else {
                cp16(bb + A_V + row * PQ + u * 16,
                     vf + bo + (size_t)(t * 64 + row) * DK + u * 8);
            }
        }
        cp_commit();
    };
    issue_kv(0, 0);
    issue_kv(1, 1);

    const int g  = lane >> 2;
    const int tc = lane & 3;
    const int qg0 = q0 + wid * 16 + g;
    const int qg1 = qg0 + 8;

    float acc_o[8][4];
#pragma unroll
    for (int j = 0; j < 8; ++j)
#pragma unroll
        for (int r = 0; r < 4; ++r) acc_o[j][r] = 0.f;
    float m0 = -1e30f, m1 = -1e30f, l0 = 0.f, l1 = 0.f;

    const uint32_t aBase = base + (wid * 16 + (lane & 15)) * PQ + ((lane >> 4) & 1) * 16;
    const uint32_t bRowSel = ((lane >> 4) & 1) * 8 + (lane & 7);
    const uint32_t bColSel = ((lane >> 3) & 1) * 16;
    const uint32_t vRowSel = ((lane >> 3) & 1) * 8 + (lane & 7);
    const uint32_t vColSel = ((lane >> 4) & 1) * 16;

    for (int t = 0; t < 32; ++t) {
        if (t + 2 < 32) cp_wait<1>(); else cp_wait<0>();
        __syncthreads();
        uint32_t kb = base + A_BUF + (t & 1) * A_BUFSZ;

        float s[8][4];
#pragma unroll
        for (int j = 0; j < 8; ++j)
#pragma unroll
            for (int r = 0; r < 4; ++r) s[j][r] = 0.f;

#pragma unroll
        for (int ks = 0; ks < 4; ++ks) {
            uint32_t ah[4], al[4];
            ldm_x4(aBase + ks * 32,        ah[0], ah[1], ah[2], ah[3]);
            ldm_x4(aBase + A_QL + ks * 32, al[0], al[1], al[2], al[3]);
#pragma unroll
            for (int nb2 = 0; nb2 < 4; ++nb2) {
                uint32_t bAddr = kb + A_KH + (nb2 * 16 + bRowSel) * PQ + bColSel + ks * 32;
                uint32_t h0, h1, h2, h3, u0, u1, u2, u3;
                ldm_x4(bAddr,                 h0, h1, h2, h3);
                ldm_x4(bAddr + (A_KL - A_KH), u0, u1, u2, u3);
                uint32_t bh0[2] = {h0, h1}, bh1[2] = {h2, h3};
                uint32_t bl0[2] = {u0, u1}, bl1[2] = {u2, u3};
                mma16816(s[2*nb2],   ah, bh0); mma16816(s[2*nb2],   ah, bl0);
                mma16816(s[2*nb2],   al, bh0);
                mma16816(s[2*nb2+1], ah, bh1); mma16816(s[2*nb2+1], ah, bl1);
                mma16816(s[2*nb2+1], al, bh1);
            }
        }

        int ktb = t * 64;
        float rm0 = -1e30f, rm1 = -1e30f;
        int i0base = ktb + tc * 2 - qg0 + 2047;
        int i1base = ktb + tc * 2 - qg1 + 2047;
#pragma unroll
        for (int nb = 0; nb < 8; ++nb) {
            int i00 = i0base + nb * 8;
            int i10 = i1base + nb * 8;
            s[nb][0] += bias[i00]; s[nb][1] += bias[i00 + 1];
            s[nb][2] += bias[i10]; s[nb][3] += bias[i10 + 1];
            rm0 = fmaxf(rm0, fmaxf(s[nb][0], s[nb][1]));
            rm1 = fmaxf(rm1, fmaxf(s[nb][2], s[nb][3]));
        }
        rm0 = fmaxf(rm0, __shfl_xor_sync(0xffffffffu, rm0, 1));
        rm0 = fmaxf(rm0, __shfl_xor_sync(0xffffffffu, rm0, 2));
        rm1 = fmaxf(rm1, __shfl_xor_sync(0xffffffffu, rm1, 1));
        rm1 = fmaxf(rm1, __shfl_xor_sync(0xffffffffu, rm1, 2));

        bool upd = __any_sync(0xffffffffu, (rm0 > m0) | (rm1 > m1));
        if (upd) {
            float mn0 = fmaxf(m0, rm0), mn1 = fmaxf(m1, rm1);
            float c0 = ex2f(m0 - mn0), c1 = ex2f(m1 - mn1);
            m0 = mn0; m1 = mn1;
            l0 *= c0; l1 *= c1;
#pragma unroll
            for (int j = 0; j < 8; ++j) {
                acc_o[j][0] *= c0; acc_o[j][1] *= c0;
                acc_o[j][2] *= c1; acc_o[j][3] *= c1;
            }
        }

        float ps0 = 0.f, ps1 = 0.f;
#pragma unroll
        for (int nb = 0; nb < 8; ++nb) {
            s[nb][0] = ex2f(s[nb][0] - m0); s[nb][1] = ex2f(s[nb][1] - m0);
            s[nb][2] = ex2f(s[nb][2] - m1); s[nb][3] = ex2f(s[nb][3] - m1);
            ps0 += s[nb][0] + s[nb][1];
            ps1 += s[nb][2] + s[nb][3];
        }
        ps0 += __shfl_xor_sync(0xffffffffu, ps0, 1);
        ps0 += __shfl_xor_sync(0xffffffffu, ps0, 2);
        ps1 += __shfl_xor_sync(0xffffffffu, ps1, 1);
        ps1 += __shfl_xor_sync(0xffffffffu, ps1, 2);
        l0 += ps0; l1 += ps1;

#pragma unroll
        for (int ks = 0; ks < 4; ++ks) {
            uint32_t ap[4];
            __half2 p0 = __floats2half2_rn(s[2*ks][0],   s[2*ks][1]);
            __half2 p1 = __floats2half2_rn(s[2*ks][2],   s[2*ks][3]);
            __half2 p2 = __floats2half2_rn(s[2*ks+1][0], s[2*ks+1][1]);
            __half2 p3 = __floats2half2_rn(s[2*ks+1][2], s[2*ks+1][3]);
            ap[0] = *(uint32_t*)&p0; ap[1] = *(uint32_t*)&p1;
            ap[2] = *(uint32_t*)&p2; ap[3] = *(uint32_t*)&p3;
#pragma unroll
            for (int db2 = 0; db2 < 4; ++db2) {
                uint32_t vAddr = kb + A_V + (ks * 16 + vRowSel) * PQ + db2 * 32 + vColSel;
                uint32_t h0, h1, h2, h3;
                ldm_x4t(vAddr, h0, h1, h2, h3);
                uint32_t v0[2] = {h0, h1}, v1[2] = {h2, h3};
                mma16816h(acc_o[2*db2],   ap, v0);
                mma16816h(acc_o[2*db2+1], ap, v1);
            }
        }
        __syncthreads();
        if (t + 2 < 32) issue_kv(t + 2, t & 1);
    }

    float inv0 = 1.f / l0, inv1 = 1.f / l1;
#pragma unroll
    for (int db = 0; db < 8; ++db) {
        int dcol = hd * DK + db * 8 + tc * 2;
        size_t o0 = ((size_t)b * S_LEN + qg0) * DM + dcol;
        size_t o1 = ((size_t)b * S_LEN + qg1) * DM + dcol;
        __half2 w0 = __floats2half2_rn(acc_o[db][0] * inv0, acc_o[db][1] * inv0);
        __half2 w1 = __floats2half2_rn(acc_o[db][2] * inv1, acc_o[db][3] * inv1);
        *(uint32_t*)(cf + o0) = *(uint32_t*)&w0;
        *(uint32_t*)(cf + o1) = *(uint32_t*)&w1;
    }
}

// ---------------------------------------------------------------------------
extern "C" void kernel_launch(void* const* d_in, const int* in_sizes, int n_in,
                              void* d_out, int out_size)
{
    const float* hidden  = (const float*)d_in[0];
    const float* wq      = (const float*)d_in[1];
    const float* wk      = (const float*)d_in[2];
    const float* wv      = (const float*)d_in[3];
    const float* wo      = (const float*)d_in[4];
    const float* relbias = (const float*)d_in[5];
    float* out = (float*)d_out;

    __nv_bfloat16 *hhi, *hlo, *whi, *wlo, *qh, *ql, *kh, *kl;
    __half *hf, *wvh, *wvl, *wof, *vf, *cf;
    cudaGetSymbolAddress((void**)&hhi, g_h_hi);
    cudaGetSymbolAddress((void**)&hlo, g_h_lo);
    cudaGetSymbolAddress((void**)&hf,  g_h_f);
    cudaGetSymbolAddress((void**)&whi, g_wt_hi);
    cudaGetSymbolAddress((void**)&wlo, g_wt_lo);
    cudaGetSymbolAddress((void**)&wvh, g_wv_hi);
    cudaGetSymbolAddress((void**)&wvl, g_wv_lo);
    cudaGetSymbolAddress((void**)&wof, g_wo_f);
    cudaGetSymbolAddress((void**)&qh,  g_qh);
    cudaGetSymbolAddress((void**)&ql,  g_ql);
    cudaGetSymbolAddress((void**)&kh,  g_kh);
    cudaGetSymbolAddress((void**)&kl,  g_kl);
    cudaGetSymbolAddress((void**)&vf,  g_vf);
    cudaGetSymbolAddress((void**)&cf,  g_ctx);

    cudaFuncSetAttribute(gemm_qkv, cudaFuncAttributeMaxDynamicSharedMemorySize, QKV_SMEM);
    cudaFuncSetAttribute(gemm_out, cudaFuncAttributeMaxDynamicSharedMemorySize, OUT_SMEM);
    cudaFuncSetAttribute(attn_mma, cudaFuncAttributeMaxDynamicSharedMemorySize, ATT_SMEM);

    prep_all<<<PREP_BLOCKS, 256>>>((const float4*)hidden, hhi, hlo, hf,
                                   wq, wk, wv, wo, whi, wlo, wvh, wvl, wof);

    gemm_qkv<<<dim3(24, 64), 256, QKV_SMEM>>>(hhi, hlo, hf, whi, wlo, wvh, wvl,
                                              qh, ql, kh, kl, vf);

    attn_mma<<<dim3(16, 64), 256, ATT_SMEM>>>(qh, ql, kh, kl, vf, relbias, cf);

    gemm_out<<<dim3(8, 64), 256, OUT_SMEM>>>(cf, wof, out);
}

// round 15
// speedup vs baseline: 4.4934x; 1.0027x over previous
#include <cuda_runtime.h>
#include <cuda_bf16.h>
#include <cuda_fp16.h>
#include <cstdint>

#define BATCH 4
#define S_LEN 2048
#define NH    16
#define DK    64
#define DM    1024
#define MT    (BATCH*S_LEN)
#define BHSZ  ((size_t)BATCH * NH * S_LEN * DK)
#define LOG2E 1.4426950408889634f

__device__ __nv_bfloat16 g_h_hi[MT * DM];
__device__ __nv_bfloat16 g_h_lo[MT * DM];
__device__ __half        g_h_f[MT * DM];
__device__ __nv_bfloat16 g_wt_hi[2 * DM * DM];
__device__ __nv_bfloat16 g_wt_lo[2 * DM * DM];
__device__ __half        g_wv_hi[DM * DM];
__device__ __half        g_wv_lo[DM * DM];
__device__ __half        g_wo_f[DM * DM];
__device__ __nv_bfloat16 g_qh[BHSZ], g_ql[BHSZ];
__device__ __nv_bfloat16 g_kh[BHSZ], g_kl[BHSZ];   // K pre-scaled by log2(e)
__device__ __half        g_vf[BHSZ];
__device__ __half        g_ctx[MT * DM];

// ---------------- helpers ----------------
__device__ __forceinline__ uint32_t smem_u32(const void* p) {
    uint32_t a;
    asm("{ .reg .u64 t; cvta.to.shared.u64 t, %1; cvt.u32.u64 %0, t; }" : "=r"(a) : "l"(p));
    return a;
}
__device__ __forceinline__ float ex2f(float x) {
    float y;
    asm("ex2.approx.f32 %0, %1;" : "=f"(y) : "f"(x));
    return y;
}
__device__ __forceinline__ void cp16(uint32_t dst, const void* src) {
    asm volatile("cp.async.cg.shared.global [%0], [%1], 16;" :: "r"(dst), "l"(src));
}
__device__ __forceinline__ void cp_commit() { asm volatile("cp.async.commit_group;" ::: "memory"); }
template<int N> __device__ __forceinline__ void cp_wait() {
    asm volatile("cp.async.wait_group %0;" :: "n"(N) : "memory");
}
__device__ __forceinline__ void ldm_x4(uint32_t a, uint32_t& r0, uint32_t& r1,
                                       uint32_t& r2, uint32_t& r3) {
    asm volatile("ldmatrix.sync.aligned.m8n8.x4.shared.b16 {%0,%1,%2,%3}, [%4];"
                 : "=r"(r0), "=r"(r1), "=r"(r2), "=r"(r3) : "r"(a));
}
__device__ __forceinline__ void ldm_x4t(uint32_t a, uint32_t& r0, uint32_t& r1,
                                        uint32_t& r2, uint32_t& r3) {
    asm volatile("ldmatrix.sync.aligned.m8n8.x4.trans.shared.b16 {%0,%1,%2,%3}, [%4];"
                 : "=r"(r0), "=r"(r1), "=r"(r2), "=r"(r3) : "r"(a));
}
__device__ __forceinline__ void mma16816(float* c, const uint32_t* a, const uint32_t* b) {
    asm volatile("mma.sync.aligned.m16n8k16.row.col.f32.bf16.bf16.f32 "
                 "{%0,%1,%2,%3},{%4,%5,%6,%7},{%8,%9},{%0,%1,%2,%3};"
                 : "+f"(c[0]), "+f"(c[1]), "+f"(c[2]), "+f"(c[3])
                 : "r"(a[0]), "r"(a[1]), "r"(a[2]), "r"(a[3]), "r"(b[0]), "r"(b[1]));
}
__device__ __forceinline__ void mma16816h(float* c, const uint32_t* a, const uint32_t* b) {
    asm volatile("mma.sync.aligned.m16n8k16.row.col.f32.f16.f16.f32 "
                 "{%0,%1,%2,%3},{%4,%5,%6,%7},{%8,%9},{%0,%1,%2,%3};"
                 : "+f"(c[0]), "+f"(c[1]), "+f"(c[2]), "+f"(c[3])
                 : "r"(a[0]), "r"(a[1]), "r"(a[2]), "r"(a[3]), "r"(b[0]), "r"(b[1]));
}
__device__ __forceinline__ void pksplit(float x, float y, uint32_t& hi, uint32_t& lo) {
    __nv_bfloat162 h = __floats2bfloat162_rn(x, y);
    __nv_bfloat162 l = __floats2bfloat162_rn(x - __bfloat162float(h.x),
                                             y - __bfloat162float(h.y));
    hi = *(uint32_t*)&h; lo = *(uint32_t*)&l;
}

// ---------------- fused prep ----------------
#define SPLIT_BLOCKS (MT * DM / 1024)
#define PREP_BLOCKS  (SPLIT_BLOCKS + 4096)

__global__ void prep_all(const float4* __restrict__ in,
                         __nv_bfloat16* __restrict__ hi, __nv_bfloat16* __restrict__ lo,
                         __half* __restrict__ hf,
                         const float* __restrict__ w0, const float* __restrict__ w1,
                         const float* __restrict__ w2, const float* __restrict__ w3,
                         __nv_bfloat16* __restrict__ ohi, __nv_bfloat16* __restrict__ olo,
                         __half* __restrict__ wvh, __half* __restrict__ wvl,
                         __half* __restrict__ wof)
{
    __shared__ float t[32][33];
    const int tid = threadIdx.x;
    if (blockIdx.x < SPLIT_BLOCKS) {
        int i = blockIdx.x * 256 + tid;
        float4 v = in[i];
        float f[4] = {v.x, v.y, v.z, v.w};
        __nv_bfloat16 h4[4], l4[4];
        __half f4[4];
#pragma unroll
        for (int j = 0; j < 4; ++j) {
            h4[j] = __float2bfloat16(f[j]);
            l4[j] = __float2bfloat16(f[j] - __bfloat162float(h4[j]));
            f4[j] = __float2half_rn(f[j]);
        }
        *(uint2*)(hi + (size_t)i * 4) = *(uint2*)h4;
        *(uint2*)(lo + (size_t)i * 4) = *(uint2*)l4;
        *(uint2*)(hf + (size_t)i * 4) = *(uint2*)f4;
        return;
    }
    int tb = blockIdx.x - SPLIT_BLOCKS;
    int z  = tb >> 10;
    int bx = tb & 31, by = (tb >> 5) & 31;
    int tx = tid & 31, ty = tid >> 5;
    const float* w = z == 0 ? w0 : z == 1 ? w1 : z == 2 ? w2 : w3;
    int x0 = bx * 32, y0 = by * 32;
    for (int i = ty; i < 32; i += 8)
        t[i][tx] = w[(size_t)(y0 + i) * DM + x0 + tx];
    __syncthreads();
    if (z < 2) {
        size_t zoff = (size_t)z * DM * DM;
        for (int i = ty; i < 32; i += 8) {
            float v = t[tx][i];
            __nv_bfloat16 hb = __float2bfloat16(v);
            __nv_bfloat16 lb = __float2bfloat16(v - __bfloat162float(hb));
            size_t o = zoff + (size_t)(x0 + i) * DM + y0 + tx;
            ohi[o] = hb; olo[o] = lb;
        }
    } else if (z == 2) {
        for (int i = ty; i < 32; i += 8) {
            float v = t[tx][i];
            __half hh = __float2half_rn(v);
            __half hl = __float2half_rn(v - __half2float(hh));
            size_t o = (size_t)(x0 + i) * DM + y0 + tx;
            wvh[o] = hh; wvl[o] = hl;
        }
    } else {
        for (int i = ty; i < 32; i += 8) {
            size_t o = (size_t)(x0 + i) * DM + y0 + tx;
            wof[o] = __float2half_rn(t[tx][i]);
        }
    }
}

// ---------------- fused QKV GEMM: KCH=16, 4-stage, occ 2, x4 B-pairs ----------------
#define KC2   16
#define NK2   (DM / KC2)
#define RW2   48
#define T2    (128 * 48)
#define QST2  (4 * T2)
#define QKV_SMEM (4 * QST2)

__global__ __launch_bounds__(256, 2) void gemm_qkv(
    const __nv_bfloat16* __restrict__ Ah, const __nv_bfloat16* __restrict__ Al,
    const __half* __restrict__ Af,
    const __nv_bfloat16* __restrict__ Wqk_h, const __nv_bfloat16* __restrict__ Wqk_l,
    const __half* __restrict__ Wv_h, const __half* __restrict__ Wv_l,
    __nv_bfloat16* __restrict__ qh, __nv_bfloat16* __restrict__ ql,
    __nv_bfloat16* __restrict__ kh, __nv_bfloat16* __restrict__ kl,
    __half* __restrict__ vf)
{
    extern __shared__ __align__(16) char dsm[];
    const uint32_t base = smem_u32(dsm);
    const int tid = threadIdx.x, lane = tid & 31, wid = tid >> 5;
    const int warpM = wid & 1, warpN = wid >> 1;
    const int m0 = blockIdx.y * 128, n0 = blockIdx.x * 128;
    const int which = n0 >> 10;
    const bool isV = (which == 2);

    const int lrow = tid >> 1;
    const int lu   = tid & 1;

    const __nv_bfloat16* Ahp = Ah + (size_t)m0 * DM;
    const __nv_bfloat16* Alp = Al + (size_t)m0 * DM;
    const __half*        Afp = Af + (size_t)m0 * DM;
    const __nv_bfloat16* Bhp = Wqk_h + (size_t)n0 * DM;
    const __nv_bfloat16* Blp = Wqk_l + (size_t)n0 * DM;
    const __half*        Vhp = Wv_h + (size_t)(n0 - 2048) * DM;
    const __half*        Vlp = Wv_l + (size_t)(n0 - 2048) * DM;

    auto issue = [&](int kc, int st) {
        uint32_t sb = base + st * QST2;
        uint32_t d  = sb + lrow * RW2 + lu * 16;
        size_t   go = (size_t)lrow * DM + kc + lu * 8;
        if (isV) {
            cp16(d,          Afp + go);
            cp16(d + 2 * T2, Vhp + go);
            cp16(d + 3 * T2, Vlp + go);
        } else {
            cp16(d,          Ahp + go);
            cp16(d + T2,     Alp + go);
            cp16(d + 2 * T2, Bhp + go);
            cp16(d + 3 * T2, Blp + go);
        }
        cp_commit();
    };

    float acc[4][4][4];
#pragma unroll
    for (int i = 0; i < 4; ++i)
#pragma unroll
        for (int j = 0; j < 4; ++j)
#pragma unroll
            for (int r = 0; r < 4; ++r) acc[i][j][r] = 0.f;

    issue(0, 0); issue(KC2, 1); issue(2 * KC2, 2);

    const uint32_t aRow  = (uint32_t)(warpM * 64 + (lane & 15));
    const uint32_t aCol  = (uint32_t)(((lane >> 4) & 1) * 16);
    const uint32_t bRowX = (uint32_t)(warpN * 32 + ((lane >> 4) & 1) * 8 + (lane & 7));
    const uint32_t bColX = (uint32_t)(((lane >> 3) & 1) * 16);

    if (isV) {
        for (int kt = 0; kt < NK2; ++kt) {
            cp_wait<2>();
            __syncthreads();
            if (kt + 3 < NK2) issue((kt + 3) * KC2, (kt + 3) & 3);
            else cp_commit();

            uint32_t sb = base + (kt & 3) * QST2;
            uint32_t bh[4][2], bl[4][2];
#pragma unroll
            for (int jp = 0; jp < 2; ++jp) {
                uint32_t b = sb + 2 * T2 + (bRowX + jp * 16) * RW2 + bColX;
                ldm_x4(b,      bh[2*jp][0], bh[2*jp][1], bh[2*jp+1][0], bh[2*jp+1][1]);
                ldm_x4(b + T2, bl[2*jp][0], bl[2*jp][1], bl[2*jp+1][0], bl[2*jp+1][1]);
            }
#pragma unroll
            for (int i = 0; i < 4; ++i) {
                uint32_t a = sb + (aRow + i * 16) * RW2 + aCol;
                uint32_t af[4];
                ldm_x4(a, af[0], af[1], af[2], af[3]);
#pragma unroll
                for (int j = 0; j < 4; ++j) {
                    mma16816h(acc[i][j], af, bh[j]);
                    mma16816h(acc[i][j], af, bl[j]);
                }
            }
        }
    } else {
        for (int kt = 0; kt < NK2; ++kt) {
            cp_wait<2>();
            __syncthreads();
            if (kt + 3 < NK2) issue((kt + 3) * KC2, (kt + 3) & 3);
            else cp_commit();

            uint32_t sb = base + (kt & 3) * QST2;
            uint32_t bh[4][2], bl[4][2];
#pragma unroll
            for (int jp = 0; jp < 2; ++jp) {
                uint32_t b = sb + 2 * T2 + (bRowX + jp * 16) * RW2 + bColX;
                ldm_x4(b,      bh[2*jp][0], bh[2*jp][1], bh[2*jp+1][0], bh[2*jp+1][1]);
                ldm_x4(b + T2, bl[2*jp][0], bl[2*jp][1], bl[2*jp+1][0], bl[2*jp+1][1]);
            }
#pragma unroll
            for (int i = 0; i < 4; ++i) {
                uint32_t a = sb + (aRow + i * 16) * RW2 + aCol;
                uint32_t ah[4], al[4];
                ldm_x4(a,      ah[0], ah[1], ah[2], ah[3]);
                ldm_x4(a + T2, al[0], al[1], al[2], al[3]);
#pragma unroll
                for (int j = 0; j < 4; ++j) {
                    mma16816(acc[i][j], ah, bh[j]);
                    mma16816(acc[i][j], ah, bl[j]);
                    mma16816(acc[i][j], al, bh[j]);
                }
            }
        }
    }

    __nv_bfloat16* oH = (which == 0) ? qh : kh;
    __nv_bfloat16* oL = (which == 0) ? ql : kl;
    const float sc = (which == 1) ? LOG2E : 1.f;

#pragma unroll
    for (int i = 0; i < 4; ++i) {
        int mA = m0 + warpM * 64 + i * 16 + (lane >> 2);
        int mB = mA + 8;
#pragma unroll
        for (int j = 0; j < 4; ++j) {
            int n = n0 + warpN * 32 + j * 8 + ((lane & 3) << 1);
            int nn = n & 1023;
            int hh = nn >> 6, dd = nn & 63;
            int bA = mA >> 11, sA = mA & (S_LEN - 1);
            int bB = mB >> 11, sB = mB & (S_LEN - 1);
            size_t oA = ((size_t)(bA * NH + hh) * S_LEN + sA) * DK + dd;
            size_t oB = ((size_t)(bB * NH + hh) * S_LEN + sB) * DK + dd;
            if (isV) {
                __half2 v0 = __floats2half2_rn(acc[i][j][0], acc[i][j][1]);
                __half2 v1 = __floats2half2_rn(acc[i][j][2], acc[i][j][3]);
                *(uint32_t*)(vf + oA) = *(uint32_t*)&v0;
                *(uint32_t*)(vf + oB) = *(uint32_t*)&v1;
            } else {
                uint32_t h0, l0, h1, l1;
                pksplit(acc[i][j][0] * sc, acc[i][j][1] * sc, h0, l0);
                pksplit(acc[i][j][2] * sc, acc[i][j][3] * sc, h1, l1);
                *(uint32_t*)(oH + oA) = h0; *(uint32_t*)(oL + oA) = l0;
                *(uint32_t*)(oH + oB) = h1; *(uint32_t*)(oL + oB) = l1;
            }
        }
    }
}

// ---------------- out-projection GEMM: KCH=32, 80B rows, 4-stage, occ 2 ----------------
#define KC3   32
#define NK3   (DM / KC3)               // 32
#define RW3   80
#define T3    (128 * 80)               // 10240 bytes per tile
#define OST4  (2 * T3)                 // 20480 per stage (A + B)
#define OUT_SMEM (4 * OST4)            // 81920

__global__ __launch_bounds__(256, 2) void gemm_out(
    const __half* __restrict__ Af, const __half* __restrict__ Bf,
    float* __restrict__ outF)
{
    extern __shared__ __align__(16) char dsm[];
    const uint32_t base = smem_u32(dsm);
    const int tid = threadIdx.x, lane = tid & 31, wid = tid >> 5;
    const int warpM = wid & 1, warpN = wid >> 1;
    const int m0 = blockIdx.y * 128, n0 = blockIdx.x * 128;

    const __half* Ap = Af + (size_t)m0 * DM;
    const __half* Bp = Bf + (size_t)n0 * DM;

    const int lrow = tid >> 2;          // 0..63 (2 row-iters -> 128)
    const int lu   = tid & 3;           // 16B unit within 64B row

    auto issue = [&](int kc, int st) {
        uint32_t sb = base + st * OST4;
#pragma unroll
        for (int t = 0; t < 2; ++t) {
            int row = lrow + t * 64;
            uint32_t d = sb + row * RW3 + lu * 16;
            size_t  go = (size_t)row * DM + kc + lu * 8;
            cp16(d,      Ap + go);
            cp16(d + T3, Bp + go);
        }
        cp_commit();
    };

    float acc[4][4][4];
#pragma unroll
    for (int i = 0; i < 4; ++i)
#pragma unroll
        for (int j = 0; j < 4; ++j)
#pragma unroll
            for (int r = 0; r < 4; ++r) acc[i][j][r] = 0.f;

    issue(0, 0); issue(KC3, 1); issue(2 * KC3, 2);

    const uint32_t aRow  = (uint32_t)(warpM * 64 + (lane & 15));
    const uint32_t aCol  = (uint32_t)(((lane >> 4) & 1) * 16);
    const uint32_t bRowX = (uint32_t)(warpN * 32 + ((lane >> 4) & 1) * 8 + (lane & 7));
    const uint32_t bColX = (uint32_t)(((lane >> 3) & 1) * 16);

    for (int kt = 0; kt < NK3; ++kt) {
        cp_wait<2>();
        __syncthreads();
        if (kt + 3 < NK3) issue((kt + 3) * KC3, (kt + 3) & 3);
        else cp_commit();

        uint32_t sb = base + (kt & 3) * OST4;
#pragma unroll
        for (int s = 0; s < 2; ++s) {    // two k16 steps per stage
            uint32_t bf[4][2];
#pragma unroll
            for (int jp = 0; jp < 2; ++jp) {
                uint32_t b = sb + T3 + (bRowX + jp * 16) * RW3 + s * 32 + bColX;
                ldm_x4(b, bf[2*jp][0], bf[2*jp][1], bf[2*jp+1][0], bf[2*jp+1][1]);
            }
#pragma unroll
            for (int i = 0; i < 4; ++i) {
                uint32_t a = sb + (aRow + i * 16) * RW3 + s * 32 + aCol;
                uint32_t af[4];
                ldm_x4(a, af[0], af[1], af[2], af[3]);
#pragma unroll
                for (int j = 0; j < 4; ++j)
                    mma16816h(acc[i][j], af, bf[j]);
            }
        }
    }

#pragma unroll
    for (int i = 0; i < 4; ++i) {
        int mA = m0 + warpM * 64 + i * 16 + (lane >> 2);
        int mB = mA + 8;
#pragma unroll
        for (int j = 0; j < 4; ++j) {
            int n = n0 + warpN * 32 + j * 8 + ((lane & 3) << 1);
            *(float2*)(outF + (size_t)mA * DM + n) = make_float2(acc[i][j][0], acc[i][j][1]);
            *(float2*)(outF + (size_t)mB * DM + n) = make_float2(acc[i][j][2], acc[i][j][3]);
        }
    }
}

// ---------------- HMMA flash attention (unchanged) ----------------
__device__ __forceinline__ int t5_bucket(int delta)
{
    int base = (delta > 0) ? 16 : 0;
    int a = delta < 0 ? -delta : delta;
    int bucket;
    if (a < 8) bucket = a;
    else if (a >= 128) bucket = 15;
    else {
        int t = 31 - __clz(a);
        int f = (a * a >= (1 << (2 * t + 1))) ? 1 : 0;
        bucket = 2 + 2 * t + f;
        if (bucket > 15) bucket = 15;
    }
    return base + bucket;
}

#define PQ        144
#define A_QH      0
#define A_QL      18432
#define A_BUF     36864
#define A_BUFSZ   27648
#define A_KH      0
#define A_KL      9216
#define A_V       18432
#define A_BIAS    (A_BUF + 2*A_BUFSZ)
#define BIAS_N    4096
#define ATT_SMEM  (A_BIAS + BIAS_N*4)

__global__ __launch_bounds__(256, 2) void attn_mma(
    const __nv_bfloat16* __restrict__ qh, const __nv_bfloat16* __restrict__ ql,
    const __nv_bfloat16* __restrict__ kh, const __nv_bfloat16* __restrict__ kl,
    const __half* __restrict__ vf, const float* __restrict__ rel_bias,
    __half* __restrict__ cf)
{
    extern __shared__ __align__(16) char asmem[];
    const uint32_t base = smem_u32(asmem);
    float* bias = (float*)(asmem + A_BIAS);

    const int tid = threadIdx.x, lane = tid & 31, wid = tid >> 5;
    const int bh = blockIdx.y;
    const int hd = bh & (NH - 1);
    const int b  = bh >> 4;
    const int q0 = blockIdx.x * 128;
    const size_t bo = (size_t)bh * S_LEN * DK;

    for (int i = tid; i < BIAS_N; i += 256)
        bias[i] = rel_bias[t5_bucket(i - 2047) * NH + hd] * LOG2E;

#pragma unroll
    for (int it = 0; it < 8; ++it) {
        int idx = tid + it * 256;
        int sub = idx & 1023, row = sub >> 3, u = sub & 7;
        const __nv_bfloat16* src = (it < 4) ? qh : ql;
        cp16(base + (it < 4 ? A_QH : A_QL) + row * PQ + u * 16,
             src + bo + (size_t)(q0 + row) * DK + u * 8);
    }
    auto issue_kv = [&](int t, int buf) {
        uint32_t bb = base + A_BUF + buf * A_BUFSZ;
#pragma unroll
        for (int it = 0; it < 6; ++it) {
            int idx = tid + it * 256;
            int sub = idx & 511, row = sub >> 3, u = sub & 7;
            if (it < 4) {
                const __nv_bfloat16* src = (it < 2) ? kh : kl;
                uint32_t toff = (it < 2) ? A_KH : A_KL;
                cp16(bb + toff + row * PQ + u * 16,
                     src + bo + (size_t)(t * 64 + row) * DK + u * 8);
            } else {
                cp16(bb + A_V + row * PQ + u * 16,
                     vf + bo + (size_t)(t * 64 + row) * DK + u * 8);
            }
        }
        cp_commit();
    };
    issue_kv(0, 0);
    issue_kv(1, 1);

    const int g  = lane >> 2;
    const int tc = lane & 3;
    const int qg0 = q0 + wid * 16 + g;
    const int qg1 = qg0 + 8;

    float acc_o[8][4];
#pragma unroll
    for (int j = 0; j < 8; ++j)
#pragma unroll
        for (int r = 0; r < 4; ++r) acc_o[j][r] = 0.f;
    float m0 = -1e30f, m1 = -1e30f, l0 = 0.f, l1 = 0.f;

    const uint32_t aBase = base + (wid * 16 + (lane & 15)) * PQ + ((lane >> 4) & 1) * 16;
    const uint32_t bRowSel = ((lane >> 4) & 1) * 8 + (lane & 7);
    const uint32_t bColSel = ((lane >> 3) & 1) * 16;
    const uint32_t vRowSel = ((lane >> 3) & 1) * 8 + (lane & 7);
    const uint32_t vColSel = ((lane >> 4) & 1) * 16;

    for (int t = 0; t < 32; ++t) {
        if (t + 2 < 32) cp_wait<1>(); else cp_wait<0>();
        __syncthreads();
        uint32_t kb = base + A_BUF + (t & 1) * A_BUFSZ;

        float s[8][4];
#pragma unroll
        for (int j = 0; j < 8; ++j)
#pragma unroll
            for (int r = 0; r < 4; ++r) s[j][r] = 0.f;

#pragma unroll
        for (int ks = 0; ks < 4; ++ks) {
            uint32_t ah[4], al[4];
            ldm_x4(aBase + ks * 32,        ah[0], ah[1], ah[2], ah[3]);
            ldm_x4(aBase + A_QL + ks * 32, al[0], al[1], al[2], al[3]);
#pragma unroll
            for (int nb2 = 0; nb2 < 4; ++nb2) {
                uint32_t bAddr = kb + A_KH + (nb2 * 16 + bRowSel) * PQ + bColSel + ks * 32;
                uint32_t h0, h1, h2, h3, u0, u1, u2, u3;
                ldm_x4(bAddr,                 h0, h1, h2, h3);
                ldm_x4(bAddr + (A_KL - A_KH), u0, u1, u2, u3);
                uint32_t bh0[2] = {h0, h1}, bh1[2] = {h2, h3};
                uint32_t bl0[2] = {u0, u1}, bl1[2] = {u2, u3};
                mma16816(s[2*nb2],   ah, bh0); mma16816(s[2*nb2],   ah, bl0);
                mma16816(s[2*nb2],   al, bh0);
                mma16816(s[2*nb2+1], ah, bh1); mma16816(s[2*nb2+1], ah, bl1);
                mma16816(s[2*nb2+1], al, bh1);
            }
        }

        int ktb = t * 64;
        float rm0 = -1e30f, rm1 = -1e30f;
        int i0base = ktb + tc * 2 - qg0 + 2047;
        int i1base = ktb + tc * 2 - qg1 + 2047;
#pragma unroll
        for (int nb = 0; nb < 8; ++nb) {
            int i00 = i0base + nb * 8;
            int i10 = i1base + nb * 8;
            s[nb][0] += bias[i00]; s[nb][1] += bias[i00 + 1];
            s[nb][2] += bias[i10]; s[nb][3] += bias[i10 + 1];
            rm0 = fmaxf(rm0, fmaxf(s[nb][0], s[nb][1]));
            rm1 = fmaxf(rm1, fmaxf(s[nb][2], s[nb][3]));
        }
        rm0 = fmaxf(rm0, __shfl_xor_sync(0xffffffffu, rm0, 1));
        rm0 = fmaxf(rm0, __shfl_xor_sync(0xffffffffu, rm0, 2));
        rm1 = fmaxf(rm1, __shfl_xor_sync(0xffffffffu, rm1, 1));
        rm1 = fmaxf(rm1, __shfl_xor_sync(0xffffffffu, rm1, 2));

        bool upd = __any_sync(0xffffffffu, (rm0 > m0) | (rm1 > m1));
        if (upd) {
            float mn0 = fmaxf(m0, rm0), mn1 = fmaxf(m1, rm1);
            float c0 = ex2f(m0 - mn0), c1 = ex2f(m1 - mn1);
            m0 = mn0; m1 = mn1;
            l0 *= c0; l1 *= c1;
#pragma unroll
            for (int j = 0; j < 8; ++j) {
                acc_o[j][0] *= c0; acc_o[j][1] *= c0;
                acc_o[j][2] *= c1; acc_o[j][3] *= c1;
            }
        }

        float ps0 = 0.f, ps1 = 0.f;
#pragma unroll
        for (int nb = 0; nb < 8; ++nb) {
            s[nb][0] = ex2f(s[nb][0] - m0); s[nb][1] = ex2f(s[nb][1] - m0);
            s[nb][2] = ex2f(s[nb][2] - m1); s[nb][3] = ex2f(s[nb][3] - m1);
            ps0 += s[nb][0] + s[nb][1];
            ps1 += s[nb][2] + s[nb][3];
        }
        ps0 += __shfl_xor_sync(0xffffffffu, ps0, 1);
        ps0 += __shfl_xor_sync(0xffffffffu, ps0, 2);
        ps1 += __shfl_xor_sync(0xffffffffu, ps1, 1);
        ps1 += __shfl_xor_sync(0xffffffffu, ps1, 2);
        l0 += ps0; l1 += ps1;

#pragma unroll
        for (int ks = 0; ks < 4; ++ks) {
            uint32_t ap[4];
            __half2 p0 = __floats2half2_rn(s[2*ks][0],   s[2*ks][1]);
            __half2 p1 = __floats2half2_rn(s[2*ks][2],   s[2*ks][3]);
            __half2 p2 = __floats2half2_rn(s[2*ks+1][0], s[2*ks+1][1]);
            __half2 p3 = __floats2half2_rn(s[2*ks+1][2], s[2*ks+1][3]);
            ap[0] = *(uint32_t*)&p0; ap[1] = *(uint32_t*)&p1;
            ap[2] = *(uint32_t*)&p2; ap[3] = *(uint32_t*)&p3;
#pragma unroll
            for (int db2 = 0; db2 < 4; ++db2) {
                uint32_t vAddr = kb + A_V + (ks * 16 + vRowSel) * PQ + db2 * 32 + vColSel;
                uint32_t h0, h1, h2, h3;
                ldm_x4t(vAddr, h0, h1, h2, h3);
                uint32_t v0[2] = {h0, h1}, v1[2] = {h2, h3};
                mma16816h(acc_o[2*db2],   ap, v0);
                mma16816h(acc_o[2*db2+1], ap, v1);
            }
        }
        __syncthreads();
        if (t + 2 < 32) issue_kv(t + 2, t & 1);
    }

    float inv0 = 1.f / l0, inv1 = 1.f / l1;
#pragma unroll
    for (int db = 0; db < 8; ++db) {
        int dcol = hd * DK + db * 8 + tc * 2;
        size_t o0 = ((size_t)b * S_LEN + qg0) * DM + dcol;
        size_t o1 = ((size_t)b * S_LEN + qg1) * DM + dcol;
        __half2 w0 = __floats2half2_rn(acc_o[db][0] * inv0, acc_o[db][1] * inv0);
        __half2 w1 = __floats2half2_rn(acc_o[db][2] * inv1, acc_o[db][3] * inv1);
        *(uint32_t*)(cf + o0) = *(uint32_t*)&w0;
        *(uint32_t*)(cf + o1) = *(uint32_t*)&w1;
    }
}

// ---------------------------------------------------------------------------
extern "C" void kernel_launch(void* const* d_in, const int* in_sizes, int n_in,
                              void* d_out, int out_size)
{
    const float* hidden  = (const float*)d_in[0];
    const float* wq      = (const float*)d_in[1];
    const float* wk      = (const float*)d_in[2];
    const float* wv      = (const float*)d_in[3];
    const float* wo      = (const float*)d_in[4];
    const float* relbias = (const float*)d_in[5];
    float* out = (float*)d_out;

    __nv_bfloat16 *hhi, *hlo, *whi, *wlo, *qh, *ql, *kh, *kl;
    __half *hf, *wvh, *wvl, *wof, *vf, *cf;
    cudaGetSymbolAddress((void**)&hhi, g_h_hi);
    cudaGetSymbolAddress((void**)&hlo, g_h_lo);
    cudaGetSymbolAddress((void**)&hf,  g_h_f);
    cudaGetSymbolAddress((void**)&whi, g_wt_hi);
    cudaGetSymbolAddress((void**)&wlo, g_wt_lo);
    cudaGetSymbolAddress((void**)&wvh, g_wv_hi);
    cudaGetSymbolAddress((void**)&wvl, g_wv_lo);
    cudaGetSymbolAddress((void**)&wof, g_wo_f);
    cudaGetSymbolAddress((void**)&qh,  g_qh);
    cudaGetSymbolAddress((void**)&ql,  g_ql);
    cudaGetSymbolAddress((void**)&kh,  g_kh);
    cudaGetSymbolAddress((void**)&kl,  g_kl);
    cudaGetSymbolAddress((void**)&vf,  g_vf);
    cudaGetSymbolAddress((void**)&cf,  g_ctx);

    cudaFuncSetAttribute(gemm_qkv, cudaFuncAttributeMaxDynamicSharedMemorySize, QKV_SMEM);
    cudaFuncSetAttribute(gemm_out, cudaFuncAttributeMaxDynamicSharedMemorySize, OUT_SMEM);
    cudaFuncSetAttribute(attn_mma, cudaFuncAttributeMaxDynamicSharedMemorySize, ATT_SMEM);

    prep_all<<<PREP_BLOCKS, 256>>>((const float4*)hidden, hhi, hlo, hf,
                                   wq, wk, wv, wo, whi, wlo, wvh, wvl, wof);

    gemm_qkv<<<dim3(24, 64), 256, QKV_SMEM>>>(hhi, hlo, hf, whi, wlo, wvh, wvl,
                                              qh, ql, kh, kl, vf);

    attn_mma<<<dim3(16, 64), 256, ATT_SMEM>>>(qh, ql, kh, kl, vf, relbias, cf);

    gemm_out<<<dim3(8, 64), 256, OUT_SMEM>>>(cf, wof, out);
}